// round 2
// baseline (speedup 1.0000x reference)
#include <cuda_runtime.h>
#include <math.h>

#define B_  4
#define T_  1024
#define C_  1024
#define H_  16
#define DH_ 64
#define BH_ 64            // B_*H_
#define M_  4096          // B_*T_

// ---------------- scratch (device globals: allocation-free) ----------------
__device__ float g_q[BH_ * T_ * DH_];       // 16 MB  (bh, t, d)
__device__ float g_k[BH_ * T_ * DH_];       // 16 MB
__device__ float g_v[BH_ * T_ * DH_];       // 16 MB
__device__ float g_attn[(size_t)BH_ * T_ * T_];  // 256 MB (bh, t, j)
__device__ float g_epart[BH_ * 16];         // per (bh, qtile) energy partials
__device__ float g_mask[BH_];               // head mask 0/1
__device__ float g_ao[M_ * C_];             // 16 MB  attention output (b*t, h*Dh+d)

// keep counts: trunc(linspace(0.35,0.15,16)*64), min 1
__constant__ int KEEPC[16] = {22,21,20,19,18,18,17,16,15,14,13,13,12,11,10,9};

// ---------------- high-accuracy q projection: q = x @ sign(W)^T + b ----------------
// 64x64 block tile, 256 threads, 4x4 per thread, K-slab 16.
// Each slab accumulated plainly (FMA), then TwoSum-flushed into (s, c).
// Result is ~1-ulp accurate -> stable top-k ordering.
__global__ __launch_bounds__(256) void qgemm(
    const float* __restrict__ A, const float* __restrict__ W,
    const float* __restrict__ bias, float* __restrict__ Q)
{
    __shared__ float As[16][64];
    __shared__ float Ws[16][64];
    const int tid = threadIdx.x;
    const int tx = tid & 15, ty = tid >> 4;
    const int m0 = blockIdx.y * 64, n0 = blockIdx.x * 64;
    const int lr = tid >> 2, lc = (tid & 3) * 4;

    float s[4][4], c[4][4];
#pragma unroll
    for (int i = 0; i < 4; i++)
#pragma unroll
        for (int j = 0; j < 4; j++) { s[i][j] = 0.f; c[i][j] = 0.f; }

    for (int k0 = 0; k0 < C_; k0 += 16) {
        float4 av = *(const float4*)(A + (size_t)(m0 + lr) * C_ + k0 + lc);
        float4 wv = *(const float4*)(W + (size_t)(n0 + lr) * C_ + k0 + lc);
        wv.x = (wv.x > 0.f) ? 1.f : ((wv.x < 0.f) ? -1.f : 0.f);
        wv.y = (wv.y > 0.f) ? 1.f : ((wv.y < 0.f) ? -1.f : 0.f);
        wv.z = (wv.z > 0.f) ? 1.f : ((wv.z < 0.f) ? -1.f : 0.f);
        wv.w = (wv.w > 0.f) ? 1.f : ((wv.w < 0.f) ? -1.f : 0.f);
        As[lc + 0][lr] = av.x; As[lc + 1][lr] = av.y;
        As[lc + 2][lr] = av.z; As[lc + 3][lr] = av.w;
        Ws[lc + 0][lr] = wv.x; Ws[lc + 1][lr] = wv.y;
        Ws[lc + 2][lr] = wv.z; Ws[lc + 3][lr] = wv.w;
        __syncthreads();

        float blk[4][4];
#pragma unroll
        for (int i = 0; i < 4; i++)
#pragma unroll
            for (int j = 0; j < 4; j++) blk[i][j] = 0.f;
#pragma unroll
        for (int kk = 0; kk < 16; kk++) {
            float4 aa = *(const float4*)&As[kk][ty * 4];
            float4 bb = *(const float4*)&Ws[kk][tx * 4];
            float a4[4] = {aa.x, aa.y, aa.z, aa.w};
            float b4[4] = {bb.x, bb.y, bb.z, bb.w};
#pragma unroll
            for (int i = 0; i < 4; i++)
#pragma unroll
                for (int j = 0; j < 4; j++)
                    blk[i][j] = fmaf(a4[i], b4[j], blk[i][j]);
        }
        // TwoSum flush (branch-free, reassociation-proof)
#pragma unroll
        for (int i = 0; i < 4; i++)
#pragma unroll
            for (int j = 0; j < 4; j++) {
                float t  = __fadd_rn(s[i][j], blk[i][j]);
                float bo = __fsub_rn(t, s[i][j]);
                float e1 = __fsub_rn(s[i][j], __fsub_rn(t, bo));
                float e2 = __fsub_rn(blk[i][j], bo);
                c[i][j] = __fadd_rn(c[i][j], __fadd_rn(e1, e2));
                s[i][j] = t;
            }
        __syncthreads();
    }

    const int h = n0 >> 6;
#pragma unroll
    for (int i = 0; i < 4; i++) {
        int m = m0 + ty * 4 + i;
        int bb = m >> 10, t = m & 1023;
#pragma unroll
        for (int j = 0; j < 4; j++) {
            int n = n0 + tx * 4 + j;
            int d = n & 63;
            float v = __fadd_rn(__fadd_rn(s[i][j], c[i][j]), bias[n]);
            Q[(((size_t)(bb * H_ + h)) * T_ + t) * DH_ + d] = v;
        }
    }
}

// ---------------- generic 128x128x8 SGEMM: C = A @ W^T + bias ----------------
__global__ __launch_bounds__(256) void gemm128(
    const float* __restrict__ A, const float* __restrict__ W,
    const float* __restrict__ bias, float* __restrict__ Cout,
    int Mdim, int Ndim, int Kdim, int mode)
{
    __shared__ float As[8][128];
    __shared__ float Ws[8][128];
    const int tid = threadIdx.x;
    const int tx = tid & 15, ty = tid >> 4;
    const int m0 = blockIdx.y * 128, n0 = blockIdx.x * 128;
    const int lrow = tid >> 1, lc4 = (tid & 1) * 4;

    float acc[8][8];
#pragma unroll
    for (int i = 0; i < 8; i++)
#pragma unroll
        for (int j = 0; j < 8; j++) acc[i][j] = 0.f;

    for (int k0 = 0; k0 < Kdim; k0 += 8) {
        float4 av = *(const float4*)(A + (size_t)(m0 + lrow) * Kdim + k0 + lc4);
        float4 wv = *(const float4*)(W + (size_t)(n0 + lrow) * Kdim + k0 + lc4);
        As[lc4 + 0][lrow] = av.x; As[lc4 + 1][lrow] = av.y;
        As[lc4 + 2][lrow] = av.z; As[lc4 + 3][lrow] = av.w;
        Ws[lc4 + 0][lrow] = wv.x; Ws[lc4 + 1][lrow] = wv.y;
        Ws[lc4 + 2][lrow] = wv.z; Ws[lc4 + 3][lrow] = wv.w;
        __syncthreads();
#pragma unroll
        for (int kk = 0; kk < 8; kk++) {
            float a[8], b[8];
            float4 t0 = *(const float4*)&As[kk][ty * 8];
            float4 t1 = *(const float4*)&As[kk][ty * 8 + 4];
            a[0]=t0.x; a[1]=t0.y; a[2]=t0.z; a[3]=t0.w;
            a[4]=t1.x; a[5]=t1.y; a[6]=t1.z; a[7]=t1.w;
            float4 u0 = *(const float4*)&Ws[kk][tx * 8];
            float4 u1 = *(const float4*)&Ws[kk][tx * 8 + 4];
            b[0]=u0.x; b[1]=u0.y; b[2]=u0.z; b[3]=u0.w;
            b[4]=u1.x; b[5]=u1.y; b[6]=u1.z; b[7]=u1.w;
#pragma unroll
            for (int i = 0; i < 8; i++)
#pragma unroll
                for (int j = 0; j < 8; j++) acc[i][j] += a[i] * b[j];
        }
        __syncthreads();
    }

    if (mode == 0) {
#pragma unroll
        for (int i = 0; i < 8; i++) {
            int m = m0 + ty * 8 + i;
#pragma unroll
            for (int j = 0; j < 8; j++) {
                int n = n0 + tx * 8 + j;
                Cout[(size_t)m * Ndim + n] = acc[i][j] + bias[n];
            }
        }
    } else {
#pragma unroll
        for (int i = 0; i < 8; i++) {
            int m = m0 + ty * 8 + i;
            int bb = m >> 10, t = m & 1023;
#pragma unroll
            for (int j = 0; j < 8; j++) {
                int n = n0 + tx * 8 + j;
                int h = n >> 6, d = n & 63;
                Cout[(((size_t)(bb * H_ + h)) * T_ + t) * DH_ + d] = acc[i][j] + bias[n];
            }
        }
    }
}

// -------------- q post: RMS norm + exact per-head top-k (one row / block) --------------
__global__ void qpost(float* __restrict__ q)
{
    int row = blockIdx.x;           // row = bh*T + t
    int lane = threadIdx.x;         // 64 threads
    float v = q[(size_t)row * 64 + lane];
    float ss = v * v;
#pragma unroll
    for (int o = 16; o > 0; o >>= 1) ss += __shfl_xor_sync(0xffffffffu, ss, o);
    __shared__ float ws[2];
    if ((lane & 31) == 0) ws[lane >> 5] = ss;
    __syncthreads();
    float rms = sqrtf((ws[0] + ws[1]) * (1.f / 64.f)) + 1e-6f;
    float vn = v / rms;
    float a = fabsf(vn);
    __shared__ float sa[64];
    sa[lane] = a;
    __syncthreads();
    int g = 0;
#pragma unroll 8
    for (int j = 0; j < 64; j++) g += (sa[j] > a);
    int h = (row >> 10) & 15;
    int kc = KEEPC[h];
    float cand = (g <= kc - 1) ? a : INFINITY;
#pragma unroll
    for (int o = 16; o > 0; o >>= 1)
        cand = fminf(cand, __shfl_xor_sync(0xffffffffu, cand, o));
    __shared__ float wm[2];
    if ((lane & 31) == 0) wm[lane >> 5] = cand;
    __syncthreads();
    float th = fminf(wm[0], wm[1]);
    q[(size_t)row * 64 + lane] = (a >= th) ? vn : 0.f;
}

// -------------- k RMS norm (4 rows / block) --------------
__global__ void knorm(float* __restrict__ k)
{
    int lane = threadIdx.x & 63;
    int row = blockIdx.x * 4 + (threadIdx.x >> 6);
    float v = k[(size_t)row * 64 + lane];
    float ss = v * v;
#pragma unroll
    for (int o = 16; o > 0; o >>= 1) ss += __shfl_xor_sync(0xffffffffu, ss, o);
    __shared__ float ws[8];
    if ((threadIdx.x & 31) == 0) ws[threadIdx.x >> 5] = ss;
    __syncthreads();
    int grp = threadIdx.x >> 6;
    float tot = ws[grp * 2] + ws[grp * 2 + 1];
    float rms = sqrtf(tot * (1.f / 64.f)) + 1e-6f;
    k[(size_t)row * 64 + lane] = v / rms;
}

// -------------- attention: logits + online softmax stats, then normalize + energy --------------
__global__ __launch_bounds__(256) void attn_kernel(
    const float* __restrict__ gq, const float* __restrict__ gk,
    float* __restrict__ gattn, float* __restrict__ gepart)
{
    const int qt = blockIdx.x, bh = blockIdx.y;
    const int q0 = qt * 64;
    __shared__ float Qs[64][64];   // [d][r]
    __shared__ float Ks[64][64];   // [d][c]
    __shared__ float mrow[64], lrow[64];
    __shared__ float red[256];
    const int tid = threadIdx.x;
    const int tx = tid & 15, ty = tid >> 4;

    const float* qbase = gq + (size_t)bh * T_ * 64;
    const float* kbase = gk + (size_t)bh * T_ * 64;
    float* abase = gattn + (size_t)bh * T_ * T_;

#pragma unroll
    for (int it = 0; it < 4; it++) {
        int idx = tid + it * 256;
        int r = idx & 63, d4 = (idx >> 6) * 4;
        float4 v = *(const float4*)(qbase + (size_t)(q0 + r) * 64 + d4);
        Qs[d4][r] = v.x; Qs[d4 + 1][r] = v.y; Qs[d4 + 2][r] = v.z; Qs[d4 + 3][r] = v.w;
    }
    if (tid < 64) { mrow[tid] = -INFINITY; lrow[tid] = 0.f; }
    __syncthreads();

    for (int kt = 0; kt <= qt; kt++) {
#pragma unroll
        for (int it = 0; it < 4; it++) {
            int idx = tid + it * 256;
            int r = idx & 63, d4 = (idx >> 6) * 4;
            float4 v = *(const float4*)(kbase + (size_t)(kt * 64 + r) * 64 + d4);
            Ks[d4][r] = v.x; Ks[d4 + 1][r] = v.y; Ks[d4 + 2][r] = v.z; Ks[d4 + 3][r] = v.w;
        }
        __syncthreads();

        float s[4][4];
#pragma unroll
        for (int i = 0; i < 4; i++)
#pragma unroll
            for (int j = 0; j < 4; j++) s[i][j] = 0.f;
#pragma unroll 16
        for (int d = 0; d < 64; d++) {
            float4 aa = *(const float4*)&Qs[d][ty * 4];
            float4 bb = *(const float4*)&Ks[d][tx * 4];
            float a4[4] = {aa.x, aa.y, aa.z, aa.w};
            float b4[4] = {bb.x, bb.y, bb.z, bb.w};
#pragma unroll
            for (int i = 0; i < 4; i++)
#pragma unroll
                for (int j = 0; j < 4; j++) s[i][j] += a4[i] * b4[j];
        }
        if (kt == qt) {
#pragma unroll
            for (int i = 0; i < 4; i++)
#pragma unroll
                for (int j = 0; j < 4; j++)
                    if (tx * 4 + j > ty * 4 + i) s[i][j] = -INFINITY;
        }
#pragma unroll
        for (int i = 0; i < 4; i++) {
            int r = ty * 4 + i;
            float tm = fmaxf(fmaxf(s[i][0], s[i][1]), fmaxf(s[i][2], s[i][3]));
#pragma unroll
            for (int o = 1; o < 16; o <<= 1) tm = fmaxf(tm, __shfl_xor_sync(0xffffffffu, tm, o));
            float mo = mrow[r];
            float mn = fmaxf(mo, tm);
            float se = __expf(s[i][0] - mn) + __expf(s[i][1] - mn)
                     + __expf(s[i][2] - mn) + __expf(s[i][3] - mn);
#pragma unroll
            for (int o = 1; o < 16; o <<= 1) se += __shfl_xor_sync(0xffffffffu, se, o);
            if (tx == 0) {
                lrow[r] = lrow[r] * __expf(mo - mn) + se;
                mrow[r] = mn;
            }
        }
#pragma unroll
        for (int i = 0; i < 4; i++) {
            float4 st = make_float4(s[i][0], s[i][1], s[i][2], s[i][3]);
            *(float4*)&abase[(size_t)(q0 + ty * 4 + i) * T_ + kt * 64 + tx * 4] = st;
        }
        __syncthreads();
    }

    // sweep 2: normalize in place + Kahan-accumulate sum(p^2)
    float mfin[4], linv[4];
#pragma unroll
    for (int i = 0; i < 4; i++) {
        mfin[i] = mrow[ty * 4 + i];
        linv[i] = 1.f / lrow[ty * 4 + i];
    }
    float esum = 0.f, ecomp = 0.f;
    for (int kt = 0; kt <= qt; kt++) {
#pragma unroll
        for (int i = 0; i < 4; i++) {
            float4* p = (float4*)&abase[(size_t)(q0 + ty * 4 + i) * T_ + kt * 64 + tx * 4];
            float4 sv = *p;
            float p0 = __expf(sv.x - mfin[i]) * linv[i];
            float p1 = __expf(sv.y - mfin[i]) * linv[i];
            float p2 = __expf(sv.z - mfin[i]) * linv[i];
            float p3 = __expf(sv.w - mfin[i]) * linv[i];
            float add = p0 * p0 + p1 * p1 + p2 * p2 + p3 * p3;
            // Kahan
            float y = __fsub_rn(add, ecomp);
            float t = __fadd_rn(esum, y);
            ecomp = __fsub_rn(__fsub_rn(t, esum), y);
            esum = t;
            *p = make_float4(p0, p1, p2, p3);
        }
    }
    red[tid] = esum;
    __syncthreads();
    for (int o = 128; o > 0; o >>= 1) {
        if (tid < o) red[tid] += red[tid + o];
        __syncthreads();
    }
    if (tid == 0) gepart[bh * 16 + qt] = red[0];
}

// -------------- head energy -> entropy -> adaptive head mask (double internals) --------------
__global__ void headmask(const float* __restrict__ epart, float* __restrict__ maskout)
{
    __shared__ double e[64];
    __shared__ double cand[64];
    int t = threadIdx.x;  // 64 = B*H
    double s = 0.0;
    for (int i = 0; i < 16; i++) s += (double)epart[t * 16 + i];
    e[t] = s / 1048576.0;
    __syncthreads();
    int b = t >> 4;
    double m = -1e300;
    for (int j = 0; j < 16; j++) m = fmax(m, e[b * 16 + j]);
    double Z = 0.0;
    for (int j = 0; j < 16; j++) Z += exp(e[b * 16 + j] - m);
    double ent = 0.0;
    for (int j = 0; j < 16; j++) {
        double p = exp(e[b * 16 + j] - m) / Z;
        ent -= p * log(p + 1e-9);
    }
    double entn = fmin(fmax(ent / log(16.0), 0.0), 1.0);
    int keep = (int)rint(2.0 + entn * 4.0);
    double eh = e[t];
    int g = 0;
    for (int j = 0; j < 16; j++) g += (e[b * 16 + j] > eh);
    cand[t] = (g <= keep - 1) ? eh : 1e300;
    __syncthreads();
    double th = 1e300;
    for (int j = 0; j < 16; j++) th = fmin(th, cand[b * 16 + j]);
    maskout[t] = (eh >= th) ? 1.f : 0.f;
}

// -------------- AV: out(b,t,h*64+d) = mask * sum_j attn * v --------------
__global__ __launch_bounds__(256) void av_kernel(
    const float* __restrict__ gattn, const float* __restrict__ gv,
    const float* __restrict__ maskin, float* __restrict__ ao)
{
    const int qt = blockIdx.x, bh = blockIdx.y;
    const int q0 = qt * 64;
    __shared__ float Ps[64][64];  // [c][r]
    __shared__ float Vs[64][64];  // [j][d]
    const int tid = threadIdx.x;
    const int tx = tid & 15, ty = tid >> 4;
    float hm = maskin[bh];

    float acc[4][4];
#pragma unroll
    for (int i = 0; i < 4; i++)
#pragma unroll
        for (int j = 0; j < 4; j++) acc[i][j] = 0.f;

    if (hm != 0.f) {
        const float* abase = gattn + (size_t)bh * T_ * T_;
        const float* vbase = gv + (size_t)bh * T_ * 64;
        for (int kt = 0; kt <= qt; kt++) {
#pragma unroll
            for (int it = 0; it < 4; it++) {
                int idx = tid + it * 256;
                int r = idx & 63, c4 = (idx >> 6) * 4;
                float4 pv = *(const float4*)(abase + (size_t)(q0 + r) * T_ + kt * 64 + c4);
                Ps[c4][r] = pv.x; Ps[c4 + 1][r] = pv.y; Ps[c4 + 2][r] = pv.z; Ps[c4 + 3][r] = pv.w;
                int jrow = idx >> 4, d4 = (idx & 15) * 4;
                float4 vv = *(const float4*)(vbase + (size_t)(kt * 64 + jrow) * 64 + d4);
                *(float4*)&Vs[jrow][d4] = vv;
            }
            __syncthreads();
#pragma unroll 16
            for (int jj = 0; jj < 64; jj++) {
                float4 aa = *(const float4*)&Ps[jj][ty * 4];
                float4 bb = *(const float4*)&Vs[jj][tx * 4];
                float a4[4] = {aa.x, aa.y, aa.z, aa.w};
                float b4[4] = {bb.x, bb.y, bb.z, bb.w};
#pragma unroll
                for (int i = 0; i < 4; i++)
#pragma unroll
                    for (int j = 0; j < 4; j++) acc[i][j] += a4[i] * b4[j];
            }
            __syncthreads();
        }
    }
    int b = bh >> 4, h = bh & 15;
#pragma unroll
    for (int i = 0; i < 4; i++) {
        float4 st = make_float4(acc[i][0] * hm, acc[i][1] * hm, acc[i][2] * hm, acc[i][3] * hm);
        *(float4*)&ao[(size_t)(b * T_ + q0 + ty * 4 + i) * C_ + h * DH_ + tx * 4] = st;
    }
}

// ---------------- launch ----------------
extern "C" void kernel_launch(void* const* d_in, const int* in_sizes, int n_in,
                              void* d_out, int out_size)
{
    const float* x  = (const float*)d_in[0];
    const float* qw = (const float*)d_in[1];
    const float* qb = (const float*)d_in[2];
    const float* kw = (const float*)d_in[3];
    const float* kb = (const float*)d_in[4];
    const float* vw = (const float*)d_in[5];
    const float* vb = (const float*)d_in[6];
    const float* ow = (const float*)d_in[7];
    const float* ob = (const float*)d_in[8];
    float* out = (float*)d_out;

    float *gq, *gk, *gv, *gattn, *gep, *gm, *gao;
    cudaGetSymbolAddress((void**)&gq, g_q);
    cudaGetSymbolAddress((void**)&gk, g_k);
    cudaGetSymbolAddress((void**)&gv, g_v);
    cudaGetSymbolAddress((void**)&gattn, g_attn);
    cudaGetSymbolAddress((void**)&gep, g_epart);
    cudaGetSymbolAddress((void**)&gm, g_mask);
    cudaGetSymbolAddress((void**)&gao, g_ao);

    dim3 gGrid(C_ / 128, M_ / 128);
    dim3 qGrid(C_ / 64, M_ / 64);
    qgemm<<<qGrid, 256>>>(x, qw, qb, gq);
    gemm128<<<gGrid, 256>>>(x, kw, kb, gk, M_, C_, C_, 1);
    gemm128<<<gGrid, 256>>>(x, vw, vb, gv, M_, C_, C_, 1);

    qpost<<<BH_ * T_, 64>>>(gq);
    knorm<<<BH_ * T_ / 4, 256>>>(gk);

    attn_kernel<<<dim3(16, BH_), 256>>>(gq, gk, gattn, gep);
    headmask<<<1, 64>>>(gep, gm);
    av_kernel<<<dim3(16, BH_), 256>>>(gattn, gv, gm, gao);

    gemm128<<<gGrid, 256>>>(gao, ow, ob, out, M_, C_, C_, 0);
}

// round 3
// speedup vs baseline: 1.0205x; 1.0205x over previous
#include <cuda_runtime.h>
#include <math.h>

#define B_  4
#define T_  1024
#define C_  1024
#define H_  16
#define DH_ 64
#define BH_ 64            // B_*H_
#define M_  4096          // B_*T_

typedef unsigned long long ull;

// ---------------- scratch (device globals: allocation-free) ----------------
__device__ float g_q[BH_ * T_ * DH_];       // 16 MB  (bh, t, d)
__device__ float g_k[BH_ * T_ * DH_];       // 16 MB
__device__ float g_v[BH_ * T_ * DH_];       // 16 MB
__device__ float g_epart[BH_ * 16];         // per (bh, qtile) energy partials
__device__ float g_mask[BH_];               // head mask 0/1
__device__ float g_ao[M_ * C_];             // 16 MB  attention output (b*t, h*Dh+d)

// keep counts: trunc(linspace(0.35,0.15,16)*64), min 1
__constant__ int KEEPC[16] = {22,21,20,19,18,18,17,16,15,14,13,13,12,11,10,9};

// ---------------- packed f32x2 helpers ----------------
__device__ __forceinline__ ull packdup(float a) {
    ull r; unsigned u = __float_as_uint(a);
    asm("mov.b64 %0, {%1, %2};" : "=l"(r) : "r"(u), "r"(u));
    return r;
}
__device__ __forceinline__ void unpack2(ull v, float& x, float& y) {
    unsigned a, b;
    asm("mov.b64 {%0, %1}, %2;" : "=r"(a), "=r"(b) : "l"(v));
    x = __uint_as_float(a); y = __uint_as_float(b);
}
__device__ __forceinline__ ull fma2(ull a, ull b, ull c) {
    ull d;
    asm("fma.rn.f32x2 %0, %1, %2, %3;" : "=l"(d) : "l"(a), "l"(b), "l"(c));
    return d;
}
__device__ __forceinline__ ull mul2(ull a, ull b) {
    ull d;
    asm("mul.rn.f32x2 %0, %1, %2;" : "=l"(d) : "l"(a), "l"(b));
    return d;
}
__device__ __forceinline__ void twosum(float& s, float& c, float v) {
    float t  = __fadd_rn(s, v);
    float bo = __fsub_rn(t, s);
    float e1 = __fsub_rn(s, __fsub_rn(t, bo));
    float e2 = __fsub_rn(v, bo);
    c = __fadd_rn(c, __fadd_rn(e1, e2));
    s = t;
}

// ---------------- high-accuracy q projection: q = x @ sign(W)^T + b ----------------
// 64x64 tile, 256 threads, 4x4/thread, K-slab 16, packed FMA, TwoSum flush.
__global__ __launch_bounds__(256) void qgemm(
    const float* __restrict__ A, const float* __restrict__ W,
    const float* __restrict__ bias, float* __restrict__ Q)
{
    __shared__ __align__(16) float As[16][64];
    __shared__ __align__(16) float Ws[16][64];
    const int tid = threadIdx.x;
    const int tx = tid & 15, ty = tid >> 4;
    const int m0 = blockIdx.y * 64, n0 = blockIdx.x * 64;
    const int lr = tid >> 2, lc = (tid & 3) * 4;

    float s[4][4], c[4][4];
#pragma unroll
    for (int i = 0; i < 4; i++)
#pragma unroll
        for (int j = 0; j < 4; j++) { s[i][j] = 0.f; c[i][j] = 0.f; }

    for (int k0 = 0; k0 < C_; k0 += 16) {
        float4 av = *(const float4*)(A + (size_t)(m0 + lr) * C_ + k0 + lc);
        float4 wv = *(const float4*)(W + (size_t)(n0 + lr) * C_ + k0 + lc);
        wv.x = (wv.x > 0.f) ? 1.f : ((wv.x < 0.f) ? -1.f : 0.f);
        wv.y = (wv.y > 0.f) ? 1.f : ((wv.y < 0.f) ? -1.f : 0.f);
        wv.z = (wv.z > 0.f) ? 1.f : ((wv.z < 0.f) ? -1.f : 0.f);
        wv.w = (wv.w > 0.f) ? 1.f : ((wv.w < 0.f) ? -1.f : 0.f);
        As[lc + 0][lr] = av.x; As[lc + 1][lr] = av.y;
        As[lc + 2][lr] = av.z; As[lc + 3][lr] = av.w;
        Ws[lc + 0][lr] = wv.x; Ws[lc + 1][lr] = wv.y;
        Ws[lc + 2][lr] = wv.z; Ws[lc + 3][lr] = wv.w;
        __syncthreads();

        ull blkP[4][2];
#pragma unroll
        for (int i = 0; i < 4; i++) { blkP[i][0] = 0ull; blkP[i][1] = 0ull; }
#pragma unroll
        for (int kk = 0; kk < 16; kk++) {
            float4 aa = *(const float4*)&As[kk][ty * 4];
            ulonglong2 bq = *(const ulonglong2*)&Ws[kk][tx * 4];
            ull a0 = packdup(aa.x), a1 = packdup(aa.y), a2 = packdup(aa.z), a3 = packdup(aa.w);
            blkP[0][0] = fma2(a0, bq.x, blkP[0][0]); blkP[0][1] = fma2(a0, bq.y, blkP[0][1]);
            blkP[1][0] = fma2(a1, bq.x, blkP[1][0]); blkP[1][1] = fma2(a1, bq.y, blkP[1][1]);
            blkP[2][0] = fma2(a2, bq.x, blkP[2][0]); blkP[2][1] = fma2(a2, bq.y, blkP[2][1]);
            blkP[3][0] = fma2(a3, bq.x, blkP[3][0]); blkP[3][1] = fma2(a3, bq.y, blkP[3][1]);
        }
#pragma unroll
        for (int i = 0; i < 4; i++)
#pragma unroll
            for (int p = 0; p < 2; p++) {
                float f0, f1;
                unpack2(blkP[i][p], f0, f1);
                twosum(s[i][2 * p], c[i][2 * p], f0);
                twosum(s[i][2 * p + 1], c[i][2 * p + 1], f1);
            }
        __syncthreads();
    }

    const int h = n0 >> 6;
#pragma unroll
    for (int i = 0; i < 4; i++) {
        int m = m0 + ty * 4 + i;
        int bb = m >> 10, t = m & 1023;
#pragma unroll
        for (int j = 0; j < 4; j++) {
            int n = n0 + tx * 4 + j;
            int d = n & 63;
            float v = __fadd_rn(__fadd_rn(s[i][j], c[i][j]), bias[n]);
            Q[(((size_t)(bb * H_ + h)) * T_ + t) * DH_ + d] = v;
        }
    }
}

// ---------------- 128x128x8 SGEMM (packed FMA): C = A @ W^T + bias ----------------
// mode 0: plain output (optionally head-masked A).  mode 1: scatter to (bh,t,d).
__global__ __launch_bounds__(256) void gemm128(
    const float* __restrict__ A, const float* __restrict__ W,
    const float* __restrict__ bias, float* __restrict__ Cout,
    int mode, const float* __restrict__ maskp)
{
    __shared__ __align__(16) float As[8][128];
    __shared__ __align__(16) float Ws[8][128];
    const int tid = threadIdx.x;
    const int tx = tid & 15, ty = tid >> 4;
    const int m0 = blockIdx.y * 128, n0 = blockIdx.x * 128;
    const int lrow = tid >> 1, lc4 = (tid & 1) * 4;

    ull accP[8][4];
#pragma unroll
    for (int i = 0; i < 8; i++)
#pragma unroll
        for (int p = 0; p < 4; p++) accP[i][p] = 0ull;

    for (int k0 = 0; k0 < C_; k0 += 8) {
        float4 av = *(const float4*)(A + (size_t)(m0 + lrow) * C_ + k0 + lc4);
        if (maskp) {
            float mk = maskp[(((m0 + lrow) >> 10) << 4) + ((k0 + lc4) >> 6)];
            av.x *= mk; av.y *= mk; av.z *= mk; av.w *= mk;
        }
        float4 wv = *(const float4*)(W + (size_t)(n0 + lrow) * C_ + k0 + lc4);
        As[lc4 + 0][lrow] = av.x; As[lc4 + 1][lrow] = av.y;
        As[lc4 + 2][lrow] = av.z; As[lc4 + 3][lrow] = av.w;
        Ws[lc4 + 0][lrow] = wv.x; Ws[lc4 + 1][lrow] = wv.y;
        Ws[lc4 + 2][lrow] = wv.z; Ws[lc4 + 3][lrow] = wv.w;
        __syncthreads();
#pragma unroll
        for (int kk = 0; kk < 8; kk++) {
            float4 t0 = *(const float4*)&As[kk][ty * 8];
            float4 t1 = *(const float4*)&As[kk][ty * 8 + 4];
            ulonglong2 b01 = *(const ulonglong2*)&Ws[kk][tx * 8];
            ulonglong2 b23 = *(const ulonglong2*)&Ws[kk][tx * 8 + 4];
            ull aP[8];
            aP[0] = packdup(t0.x); aP[1] = packdup(t0.y);
            aP[2] = packdup(t0.z); aP[3] = packdup(t0.w);
            aP[4] = packdup(t1.x); aP[5] = packdup(t1.y);
            aP[6] = packdup(t1.z); aP[7] = packdup(t1.w);
            ull bP[4] = {b01.x, b01.y, b23.x, b23.y};
#pragma unroll
            for (int i = 0; i < 8; i++) {
                accP[i][0] = fma2(aP[i], bP[0], accP[i][0]);
                accP[i][1] = fma2(aP[i], bP[1], accP[i][1]);
                accP[i][2] = fma2(aP[i], bP[2], accP[i][2]);
                accP[i][3] = fma2(aP[i], bP[3], accP[i][3]);
            }
        }
        __syncthreads();
    }

    if (mode == 0) {
#pragma unroll
        for (int i = 0; i < 8; i++) {
            int m = m0 + ty * 8 + i;
#pragma unroll
            for (int p = 0; p < 4; p++) {
                int n = n0 + tx * 8 + 2 * p;
                float f0, f1;
                unpack2(accP[i][p], f0, f1);
                Cout[(size_t)m * C_ + n] = f0 + bias[n];
                Cout[(size_t)m * C_ + n + 1] = f1 + bias[n + 1];
            }
        }
    } else {
#pragma unroll
        for (int i = 0; i < 8; i++) {
            int m = m0 + ty * 8 + i;
            int bb = m >> 10, t = m & 1023;
#pragma unroll
            for (int p = 0; p < 4; p++) {
                int n = n0 + tx * 8 + 2 * p;
                int h = n >> 6, d = n & 63;
                float f0, f1;
                unpack2(accP[i][p], f0, f1);
                float* dst = &((float*)Cout)[(((size_t)(bb * H_ + h)) * T_ + t) * DH_ + d];
                dst[0] = f0 + bias[n];
                dst[1] = f1 + bias[n + 1];
            }
        }
    }
}

// -------------- q post: RMS norm + exact per-head top-k (one row / block) --------------
__global__ void qpost(float* __restrict__ q)
{
    int row = blockIdx.x;           // row = bh*T + t
    int lane = threadIdx.x;         // 64 threads
    float v = q[(size_t)row * 64 + lane];
    float ss = v * v;
#pragma unroll
    for (int o = 16; o > 0; o >>= 1) ss += __shfl_xor_sync(0xffffffffu, ss, o);
    __shared__ float ws[2];
    if ((lane & 31) == 0) ws[lane >> 5] = ss;
    __syncthreads();
    float rms = sqrtf((ws[0] + ws[1]) * (1.f / 64.f)) + 1e-6f;
    float vn = v / rms;
    float a = fabsf(vn);
    __shared__ __align__(16) float sa[64];
    sa[lane] = a;
    __syncthreads();
    int g = 0;
    const float4* sv = (const float4*)sa;
#pragma unroll
    for (int j = 0; j < 16; j++) {
        float4 t = sv[j];
        g += (t.x > a) + (t.y > a) + (t.z > a) + (t.w > a);
    }
    int h = (row >> 10) & 15;
    int kc = KEEPC[h];
    float cand = (g <= kc - 1) ? a : INFINITY;
#pragma unroll
    for (int o = 16; o > 0; o >>= 1)
        cand = fminf(cand, __shfl_xor_sync(0xffffffffu, cand, o));
    __shared__ float wm[2];
    if ((lane & 31) == 0) wm[lane >> 5] = cand;
    __syncthreads();
    float th = fminf(wm[0], wm[1]);
    q[(size_t)row * 64 + lane] = (a >= th) ? vn : 0.f;
}

// -------------- k RMS norm (4 rows / block) --------------
__global__ void knorm(float* __restrict__ k)
{
    int lane = threadIdx.x & 63;
    int row = blockIdx.x * 4 + (threadIdx.x >> 6);
    float v = k[(size_t)row * 64 + lane];
    float ss = v * v;
#pragma unroll
    for (int o = 16; o > 0; o >>= 1) ss += __shfl_xor_sync(0xffffffffu, ss, o);
    __shared__ float ws[8];
    if ((threadIdx.x & 31) == 0) ws[threadIdx.x >> 5] = ss;
    __syncthreads();
    int grp = threadIdx.x >> 6;
    float tot = ws[grp * 2] + ws[grp * 2 + 1];
    float rms = sqrtf(tot * (1.f / 64.f)) + 1e-6f;
    k[(size_t)row * 64 + lane] = v / rms;
}

// -------------- fused flash attention: logits + online softmax + energy + AV --------------
// block = (qtile, bh), 256 threads, 4x4/thread. No attn matrix materialized.
// Writes UNMASKED ao (mask applied in O-GEMM) and per-(bh,qt) energy partials.
__global__ __launch_bounds__(256) void attn_fused(
    const float* __restrict__ gq, const float* __restrict__ gk,
    const float* __restrict__ gv, float* __restrict__ ao,
    float* __restrict__ gepart)
{
    const int qt = blockIdx.x, bh = blockIdx.y;
    const int q0 = qt * 64;
    __shared__ __align__(16) float Qs[64][64];  // [d][r]
    __shared__ __align__(16) float Ks[64][64];  // [d][c]; later reused as Ps[r][j] and red[]
    __shared__ __align__(16) float Vs[64][64];  // [j][d]
    const int tid = threadIdx.x;
    const int tx = tid & 15, ty = tid >> 4;

    const float* qbase = gq + (size_t)bh * T_ * 64;
    const float* kbase = gk + (size_t)bh * T_ * 64;
    const float* vbase = gv + (size_t)bh * T_ * 64;

#pragma unroll
    for (int it = 0; it < 4; it++) {
        int idx = tid + it * 256;
        int r = idx & 63, d4 = (idx >> 6) * 4;
        float4 v = *(const float4*)(qbase + (size_t)(q0 + r) * 64 + d4);
        Qs[d4][r] = v.x; Qs[d4 + 1][r] = v.y; Qs[d4 + 2][r] = v.z; Qs[d4 + 3][r] = v.w;
    }

    float m_[4], l_[4], e2_[4];
    ull accP[4][2];
#pragma unroll
    for (int i = 0; i < 4; i++) {
        m_[i] = -INFINITY; l_[i] = 0.f; e2_[i] = 0.f;
        accP[i][0] = 0ull; accP[i][1] = 0ull;
    }

    float (*Ps)[64] = Ks;  // reuse

    for (int kt = 0; kt <= qt; kt++) {
        __syncthreads();   // prior reads of Ks/Vs (or Qs stores first time) done
#pragma unroll
        for (int it = 0; it < 4; it++) {
            int idx = tid + it * 256;
            int r = idx & 63, d4 = (idx >> 6) * 4;
            float4 v = *(const float4*)(kbase + (size_t)(kt * 64 + r) * 64 + d4);
            Ks[d4][r] = v.x; Ks[d4 + 1][r] = v.y; Ks[d4 + 2][r] = v.z; Ks[d4 + 3][r] = v.w;
            int jr = idx >> 4, e4 = (idx & 15) * 4;
            float4 vv = *(const float4*)(vbase + (size_t)(kt * 64 + jr) * 64 + e4);
            *(float4*)&Vs[jr][e4] = vv;
        }
        __syncthreads();

        // S = Q K^T (packed)
        ull sP[4][2];
#pragma unroll
        for (int i = 0; i < 4; i++) { sP[i][0] = 0ull; sP[i][1] = 0ull; }
#pragma unroll 8
        for (int d = 0; d < 64; d++) {
            float4 aa = *(const float4*)&Qs[d][ty * 4];
            ulonglong2 bq = *(const ulonglong2*)&Ks[d][tx * 4];
            ull a0 = packdup(aa.x), a1 = packdup(aa.y), a2 = packdup(aa.z), a3 = packdup(aa.w);
            sP[0][0] = fma2(a0, bq.x, sP[0][0]); sP[0][1] = fma2(a0, bq.y, sP[0][1]);
            sP[1][0] = fma2(a1, bq.x, sP[1][0]); sP[1][1] = fma2(a1, bq.y, sP[1][1]);
            sP[2][0] = fma2(a2, bq.x, sP[2][0]); sP[2][1] = fma2(a2, bq.y, sP[2][1]);
            sP[3][0] = fma2(a3, bq.x, sP[3][0]); sP[3][1] = fma2(a3, bq.y, sP[3][1]);
        }
        float s[4][4];
#pragma unroll
        for (int i = 0; i < 4; i++) {
            unpack2(sP[i][0], s[i][0], s[i][1]);
            unpack2(sP[i][1], s[i][2], s[i][3]);
        }
        if (kt == qt) {
#pragma unroll
            for (int i = 0; i < 4; i++)
#pragma unroll
                for (int j = 0; j < 4; j++)
                    if (tx * 4 + j > ty * 4 + i) s[i][j] = -INFINITY;
        }

        float p[4][4];
#pragma unroll
        for (int i = 0; i < 4; i++) {
            float tm = fmaxf(fmaxf(s[i][0], s[i][1]), fmaxf(s[i][2], s[i][3]));
#pragma unroll
            for (int o = 1; o < 16; o <<= 1) tm = fmaxf(tm, __shfl_xor_sync(0xffffffffu, tm, o));
            float mn = fmaxf(m_[i], tm);
            float sc = __expf(m_[i] - mn);
            p[i][0] = __expf(s[i][0] - mn); p[i][1] = __expf(s[i][1] - mn);
            p[i][2] = __expf(s[i][2] - mn); p[i][3] = __expf(s[i][3] - mn);
            float se = p[i][0] + p[i][1] + p[i][2] + p[i][3];
            float s2 = p[i][0] * p[i][0] + p[i][1] * p[i][1]
                     + p[i][2] * p[i][2] + p[i][3] * p[i][3];
#pragma unroll
            for (int o = 1; o < 16; o <<= 1) {
                se += __shfl_xor_sync(0xffffffffu, se, o);
                s2 += __shfl_xor_sync(0xffffffffu, s2, o);
            }
            l_[i] = l_[i] * sc + se;
            e2_[i] = e2_[i] * sc * sc + s2;
            m_[i] = mn;
            ull scP = packdup(sc);
            accP[i][0] = mul2(accP[i][0], scP);
            accP[i][1] = mul2(accP[i][1], scP);
        }

        __syncthreads();   // all lanes done reading Ks for S
#pragma unroll
        for (int i = 0; i < 4; i++)
            *(float4*)&Ps[ty * 4 + i][tx * 4] = make_float4(p[i][0], p[i][1], p[i][2], p[i][3]);
        __syncthreads();

        // acc += P @ V (packed)
#pragma unroll 4
        for (int jb = 0; jb < 16; jb++) {
            float4 pv[4];
#pragma unroll
            for (int i = 0; i < 4; i++) pv[i] = *(const float4*)&Ps[ty * 4 + i][jb * 4];
            const float pvf[4][4] = {
                {pv[0].x, pv[0].y, pv[0].z, pv[0].w},
                {pv[1].x, pv[1].y, pv[1].z, pv[1].w},
                {pv[2].x, pv[2].y, pv[2].z, pv[2].w},
                {pv[3].x, pv[3].y, pv[3].z, pv[3].w}};
#pragma unroll
            for (int jj = 0; jj < 4; jj++) {
                ulonglong2 vq = *(const ulonglong2*)&Vs[jb * 4 + jj][tx * 4];
#pragma unroll
                for (int i = 0; i < 4; i++) {
                    ull pd = packdup(pvf[i][jj]);
                    accP[i][0] = fma2(pd, vq.x, accP[i][0]);
                    accP[i][1] = fma2(pd, vq.y, accP[i][1]);
                }
            }
        }
    }

    // epilogue: out = acc / l  (unmasked)
    const int b = bh >> 4, h = bh & 15;
    float linv[4];
#pragma unroll
    for (int i = 0; i < 4; i++) linv[i] = 1.f / l_[i];
#pragma unroll
    for (int i = 0; i < 4; i++) {
        float f0, f1, f2, f3;
        unpack2(accP[i][0], f0, f1);
        unpack2(accP[i][1], f2, f3);
        float4 st = make_float4(f0 * linv[i], f1 * linv[i], f2 * linv[i], f3 * linv[i]);
        *(float4*)&ao[(size_t)(b * T_ + q0 + ty * 4 + i) * C_ + h * DH_ + tx * 4] = st;
    }

    // energy partial: sum over rows of e2/l^2
    __syncthreads();           // Ks free now
    float* red = &Ks[0][0];
    float ev = 0.f;
    if (tx == 0) {
#pragma unroll
        for (int i = 0; i < 4; i++) ev += e2_[i] * linv[i] * linv[i];
    }
    red[tid] = ev;
    __syncthreads();
    for (int o = 128; o > 0; o >>= 1) {
        if (tid < o) red[tid] += red[tid + o];
        __syncthreads();
    }
    if (tid == 0) gepart[bh * 16 + qt] = red[0];
}

// -------------- head energy -> entropy -> adaptive head mask (double internals) --------------
__global__ void headmask(const float* __restrict__ epart, float* __restrict__ maskout)
{
    __shared__ double e[64];
    __shared__ double cand[64];
    int t = threadIdx.x;  // 64 = B*H
    double s = 0.0;
    for (int i = 0; i < 16; i++) s += (double)epart[t * 16 + i];
    e[t] = s / 1048576.0;
    __syncthreads();
    int b = t >> 4;
    double m = -1e300;
    for (int j = 0; j < 16; j++) m = fmax(m, e[b * 16 + j]);
    double Z = 0.0;
    for (int j = 0; j < 16; j++) Z += exp(e[b * 16 + j] - m);
    double ent = 0.0;
    for (int j = 0; j < 16; j++) {
        double p = exp(e[b * 16 + j] - m) / Z;
        ent -= p * log(p + 1e-9);
    }
    double entn = fmin(fmax(ent / log(16.0), 0.0), 1.0);
    int keep = (int)rint(2.0 + entn * 4.0);
    double eh = e[t];
    int g = 0;
    for (int j = 0; j < 16; j++) g += (e[b * 16 + j] > eh);
    cand[t] = (g <= keep - 1) ? eh : 1e300;
    __syncthreads();
    double th = 1e300;
    for (int j = 0; j < 16; j++) th = fmin(th, cand[b * 16 + j]);
    maskout[t] = (eh >= th) ? 1.f : 0.f;
}

// ---------------- launch ----------------
extern "C" void kernel_launch(void* const* d_in, const int* in_sizes, int n_in,
                              void* d_out, int out_size)
{
    const float* x  = (const float*)d_in[0];
    const float* qw = (const float*)d_in[1];
    const float* qb = (const float*)d_in[2];
    const float* kw = (const float*)d_in[3];
    const float* kb = (const float*)d_in[4];
    const float* vw = (const float*)d_in[5];
    const float* vb = (const float*)d_in[6];
    const float* ow = (const float*)d_in[7];
    const float* ob = (const float*)d_in[8];
    float* out = (float*)d_out;

    float *gq, *gk, *gv, *gep, *gm, *gao;
    cudaGetSymbolAddress((void**)&gq, g_q);
    cudaGetSymbolAddress((void**)&gk, g_k);
    cudaGetSymbolAddress((void**)&gv, g_v);
    cudaGetSymbolAddress((void**)&gep, g_epart);
    cudaGetSymbolAddress((void**)&gm, g_mask);
    cudaGetSymbolAddress((void**)&gao, g_ao);

    dim3 gGrid(C_ / 128, M_ / 128);
    dim3 qGrid(C_ / 64, M_ / 64);
    qgemm<<<qGrid, 256>>>(x, qw, qb, gq);
    gemm128<<<gGrid, 256>>>(x, kw, kb, gk, 1, nullptr);
    gemm128<<<gGrid, 256>>>(x, vw, vb, gv, 1, nullptr);

    qpost<<<BH_ * T_, 64>>>(gq);
    knorm<<<BH_ * T_ / 4, 256>>>(gk);

    attn_fused<<<dim3(16, BH_), 256>>>(gq, gk, gv, gao, gep);
    headmask<<<1, 64>>>(gep, gm);

    gemm128<<<gGrid, 256>>>(gao, ow, ob, out, 0, gm);
}

// round 5
// speedup vs baseline: 1.4526x; 1.4234x over previous
#include <cuda_runtime.h>
#include <cuda_bf16.h>
#include <math.h>
#include <stdint.h>

#define B_  4
#define T_  1024
#define C_  1024
#define H_  16
#define DH_ 64
#define BH_ 64            // B_*H_
#define M_  4096          // B_*T_

typedef unsigned long long ull;

// ---------------- scratch (device globals: allocation-free) ----------------
__device__ float g_q[BH_ * T_ * DH_];       // 16 MB  (bh, t, d)
__device__ float g_k[BH_ * T_ * DH_];       // 16 MB
__device__ float g_v[BH_ * T_ * DH_];       // 16 MB
__device__ float g_epart[BH_ * 16];
__device__ float g_mask[BH_];
__device__ float g_ao[M_ * C_];             // 16 MB  attention output (b*t, h*Dh+d)

// bf16 split buffers
__device__ __nv_bfloat16 g_xh[M_ * C_],  g_xl[M_ * C_];    // 8 MB each
__device__ __nv_bfloat16 g_kwh[C_ * C_], g_kwl[C_ * C_];   // 2 MB each
__device__ __nv_bfloat16 g_vwh[C_ * C_], g_vwl[C_ * C_];
__device__ __nv_bfloat16 g_owh[C_ * C_], g_owl[C_ * C_];
__device__ __nv_bfloat16 g_aoh[M_ * C_], g_aol[M_ * C_];

// keep counts: trunc(linspace(0.35,0.15,16)*64), min 1
__constant__ int KEEPC[16] = {22,21,20,19,18,18,17,16,15,14,13,13,12,11,10,9};

// ---------------- packed f32x2 helpers (attn / qgemm) ----------------
__device__ __forceinline__ ull packdup(float a) {
    ull r; unsigned u = __float_as_uint(a);
    asm("mov.b64 %0, {%1, %2};" : "=l"(r) : "r"(u), "r"(u));
    return r;
}
__device__ __forceinline__ void unpack2(ull v, float& x, float& y) {
    unsigned a, b;
    asm("mov.b64 {%0, %1}, %2;" : "=r"(a), "=r"(b) : "l"(v));
    x = __uint_as_float(a); y = __uint_as_float(b);
}
__device__ __forceinline__ ull fma2(ull a, ull b, ull c) {
    ull d;
    asm("fma.rn.f32x2 %0, %1, %2, %3;" : "=l"(d) : "l"(a), "l"(b), "l"(c));
    return d;
}
__device__ __forceinline__ ull mul2(ull a, ull b) {
    ull d;
    asm("mul.rn.f32x2 %0, %1, %2;" : "=l"(d) : "l"(a), "l"(b));
    return d;
}
__device__ __forceinline__ void twosum(float& s, float& c, float v) {
    float t  = __fadd_rn(s, v);
    float bo = __fsub_rn(t, s);
    float e1 = __fsub_rn(s, __fsub_rn(t, bo));
    float e2 = __fsub_rn(v, bo);
    c = __fadd_rn(c, __fadd_rn(e1, e2));
    s = t;
}

// ---------------- bf16 split kernels ----------------
__device__ __forceinline__ void split4(float4 v, ushort4& H, ushort4& L) {
    __nv_bfloat16 h0 = __float2bfloat16(v.x);
    __nv_bfloat16 h1 = __float2bfloat16(v.y);
    __nv_bfloat16 h2 = __float2bfloat16(v.z);
    __nv_bfloat16 h3 = __float2bfloat16(v.w);
    H.x = __bfloat16_as_ushort(h0); H.y = __bfloat16_as_ushort(h1);
    H.z = __bfloat16_as_ushort(h2); H.w = __bfloat16_as_ushort(h3);
    __nv_bfloat16 l0 = __float2bfloat16(v.x - __bfloat162float(h0));
    __nv_bfloat16 l1 = __float2bfloat16(v.y - __bfloat162float(h1));
    __nv_bfloat16 l2 = __float2bfloat16(v.z - __bfloat162float(h2));
    __nv_bfloat16 l3 = __float2bfloat16(v.w - __bfloat162float(h3));
    L.x = __bfloat16_as_ushort(l0); L.y = __bfloat16_as_ushort(l1);
    L.z = __bfloat16_as_ushort(l2); L.w = __bfloat16_as_ushort(l3);
}

__global__ void split2k(const float4* __restrict__ src, ushort4* __restrict__ hi,
                        ushort4* __restrict__ lo)
{
    int i = blockIdx.x * 256 + threadIdx.x;
    ushort4 H, L;
    split4(src[i], H, L);
    hi[i] = H; lo[i] = L;
}

__global__ void split_ao(const float4* __restrict__ src, const float* __restrict__ mask,
                         ushort4* __restrict__ hi, ushort4* __restrict__ lo)
{
    int i = blockIdx.x * 256 + threadIdx.x;   // float4 index over (m, n)
    int e = i * 4;
    int m = e >> 10, n = e & 1023;
    float mk = mask[((m >> 10) << 4) + (n >> 6)];
    float4 v = src[i];
    v.x *= mk; v.y *= mk; v.z *= mk; v.w *= mk;
    ushort4 H, L;
    split4(v, H, L);
    hi[i] = H; lo[i] = L;
}

// ---------------- mma.sync bf16 split GEMM: C = A @ W^T + bias ----------------
// 128x128 block tile, 8 warps (2m x 4n), 64x32 per warp, K-chunk 32,
// double-buffered cp.async, 3 MMA passes (AhBh + AlBh + AhBl), fp32 accum.
// smem per stage: Ah | Al | Wh | Wl, each 128 rows x 80B (32 bf16 + pad).
#define TILE_B   10240             // bytes per tile (128 * 80)
#define STAGE_B  40960             // 4 tiles
#define NCHUNK   32                // 1024 / 32

__device__ __forceinline__ void mma16816(float* d,
    uint32_t a0, uint32_t a1, uint32_t a2, uint32_t a3,
    uint32_t b0, uint32_t b1)
{
    asm volatile(
        "mma.sync.aligned.m16n8k16.row.col.f32.bf16.bf16.f32 "
        "{%0,%1,%2,%3}, {%4,%5,%6,%7}, {%8,%9}, {%0,%1,%2,%3};"
        : "+f"(d[0]), "+f"(d[1]), "+f"(d[2]), "+f"(d[3])
        : "r"(a0), "r"(a1), "r"(a2), "r"(a3), "r"(b0), "r"(b1));
}

__device__ __forceinline__ void load_chunk_async(
    uint32_t sbase,
    const __nv_bfloat16* __restrict__ Ahi, const __nv_bfloat16* __restrict__ Alo,
    const __nv_bfloat16* __restrict__ Bhi, const __nv_bfloat16* __restrict__ Blo,
    int m0, int n0, int k0, int tid)
{
#pragma unroll
    for (int i = 0; i < 8; i++) {
        int u = tid + i * 256;          // 0..2047
        int tile = u >> 9;
        int idx = u & 511;
        int row = idx >> 2;
        int jj = idx & 3;
        const __nv_bfloat16* g;
        if (tile == 0)      g = Ahi + (size_t)(m0 + row) * C_ + k0 + jj * 8;
        else if (tile == 1) g = Alo + (size_t)(m0 + row) * C_ + k0 + jj * 8;
        else if (tile == 2) g = Bhi + (size_t)(n0 + row) * C_ + k0 + jj * 8;
        else                g = Blo + (size_t)(n0 + row) * C_ + k0 + jj * 8;
        uint32_t dst = sbase + tile * TILE_B + row * 80 + jj * 16;
        asm volatile("cp.async.cg.shared.global [%0], [%1], 16;" :: "r"(dst), "l"(g));
    }
}

__global__ __launch_bounds__(256) void gemm_mma(
    const __nv_bfloat16* __restrict__ Ahi, const __nv_bfloat16* __restrict__ Alo,
    const __nv_bfloat16* __restrict__ Bhi, const __nv_bfloat16* __restrict__ Blo,
    const float* __restrict__ bias, float* __restrict__ Cout, int scatter)
{
    extern __shared__ char smc[];
    const int tid = threadIdx.x;
    const int lane = tid & 31, wid = tid >> 5;
    const int wm = wid >> 2, wn = wid & 3;      // 2 x 4 warps
    const int gID = lane >> 2, tg = lane & 3;
    const int m0 = blockIdx.y * 128, n0 = blockIdx.x * 128;
    uint32_t sbase = (uint32_t)__cvta_generic_to_shared(smc);

    float acc[4][4][4];
#pragma unroll
    for (int mt = 0; mt < 4; mt++)
#pragma unroll
        for (int nt = 0; nt < 4; nt++)
#pragma unroll
            for (int r = 0; r < 4; r++) acc[mt][nt][r] = 0.f;

    load_chunk_async(sbase, Ahi, Alo, Bhi, Blo, m0, n0, 0, tid);
    asm volatile("cp.async.commit_group;" ::: "memory");
    asm volatile("cp.async.wait_group 0;" ::: "memory");
    __syncthreads();

    for (int c = 0; c < NCHUNK; c++) {
        if (c + 1 < NCHUNK) {
            load_chunk_async(sbase + ((c + 1) & 1) * STAGE_B,
                             Ahi, Alo, Bhi, Blo, m0, n0, (c + 1) * 32, tid);
            asm volatile("cp.async.commit_group;" ::: "memory");
        }
        const char* st = smc + (c & 1) * STAGE_B;
#pragma unroll
        for (int ks = 0; ks < 2; ks++) {
            const int acol = ks * 32 + tg * 4;      // byte offset in row
            uint32_t ah[4][4], al[4][4], bh[4][2], bl[4][2];
#pragma unroll
            for (int nt = 0; nt < 4; nt++) {
                int ro = (wn * 32 + nt * 8 + gID) * 80 + acol;
                bh[nt][0] = *(const uint32_t*)(st + 2 * TILE_B + ro);
                bh[nt][1] = *(const uint32_t*)(st + 2 * TILE_B + ro + 16);
                bl[nt][0] = *(const uint32_t*)(st + 3 * TILE_B + ro);
                bl[nt][1] = *(const uint32_t*)(st + 3 * TILE_B + ro + 16);
            }
#pragma unroll
            for (int mt = 0; mt < 4; mt++) {
                int ro = (wm * 64 + mt * 16 + gID) * 80 + acol;
                ah[mt][0] = *(const uint32_t*)(st + ro);
                ah[mt][1] = *(const uint32_t*)(st + ro + 640);
                ah[mt][2] = *(const uint32_t*)(st + ro + 16);
                ah[mt][3] = *(const uint32_t*)(st + ro + 656);
                al[mt][0] = *(const uint32_t*)(st + TILE_B + ro);
                al[mt][1] = *(const uint32_t*)(st + TILE_B + ro + 640);
                al[mt][2] = *(const uint32_t*)(st + TILE_B + ro + 16);
                al[mt][3] = *(const uint32_t*)(st + TILE_B + ro + 656);
            }
#pragma unroll
            for (int mt = 0; mt < 4; mt++)
#pragma unroll
                for (int nt = 0; nt < 4; nt++) {
                    mma16816(acc[mt][nt], ah[mt][0], ah[mt][1], ah[mt][2], ah[mt][3],
                             bh[nt][0], bh[nt][1]);
                    mma16816(acc[mt][nt], al[mt][0], al[mt][1], al[mt][2], al[mt][3],
                             bh[nt][0], bh[nt][1]);
                    mma16816(acc[mt][nt], ah[mt][0], ah[mt][1], ah[mt][2], ah[mt][3],
                             bl[nt][0], bl[nt][1]);
                }
        }
        if (c + 1 < NCHUNK)
            asm volatile("cp.async.wait_group 0;" ::: "memory");
        __syncthreads();
    }

    // epilogue
#pragma unroll
    for (int mt = 0; mt < 4; mt++) {
        int m1 = m0 + wm * 64 + mt * 16 + gID;
#pragma unroll
        for (int nt = 0; nt < 4; nt++) {
            int n = n0 + wn * 32 + nt * 8 + tg * 2;
            float b0v = bias[n], b1v = bias[n + 1];
            float* a = acc[mt][nt];
            if (scatter) {
                int bb = m1 >> 10, t = m1 & 1023, h = n >> 6, d = n & 63;
                *(float2*)&Cout[(((size_t)(bb * H_ + h)) * T_ + t) * DH_ + d] =
                    make_float2(a[0] + b0v, a[1] + b1v);
                int m2 = m1 + 8;
                int bb2 = m2 >> 10, t2 = m2 & 1023;
                *(float2*)&Cout[(((size_t)(bb2 * H_ + h)) * T_ + t2) * DH_ + d] =
                    make_float2(a[2] + b0v, a[3] + b1v);
            } else {
                *(float2*)&Cout[(size_t)m1 * C_ + n] = make_float2(a[0] + b0v, a[1] + b1v);
                *(float2*)&Cout[(size_t)(m1 + 8) * C_ + n] = make_float2(a[2] + b0v, a[3] + b1v);
            }
        }
    }
}

// ---------------- high-accuracy q projection: q = x @ sign(W)^T + b ----------------
__global__ __launch_bounds__(256) void qgemm(
    const float* __restrict__ A, const float* __restrict__ W,
    const float* __restrict__ bias, float* __restrict__ Q)
{
    __shared__ __align__(16) float As[16][64];
    __shared__ __align__(16) float Ws[16][64];
    const int tid = threadIdx.x;
    const int tx = tid & 15, ty = tid >> 4;
    const int m0 = blockIdx.y * 64, n0 = blockIdx.x * 64;
    const int lr = tid >> 2, lc = (tid & 3) * 4;

    float s[4][4], c[4][4];
#pragma unroll
    for (int i = 0; i < 4; i++)
#pragma unroll
        for (int j = 0; j < 4; j++) { s[i][j] = 0.f; c[i][j] = 0.f; }

    for (int k0 = 0; k0 < C_; k0 += 16) {
        float4 av = *(const float4*)(A + (size_t)(m0 + lr) * C_ + k0 + lc);
        float4 wv = *(const float4*)(W + (size_t)(n0 + lr) * C_ + k0 + lc);
        wv.x = (wv.x > 0.f) ? 1.f : ((wv.x < 0.f) ? -1.f : 0.f);
        wv.y = (wv.y > 0.f) ? 1.f : ((wv.y < 0.f) ? -1.f : 0.f);
        wv.z = (wv.z > 0.f) ? 1.f : ((wv.z < 0.f) ? -1.f : 0.f);
        wv.w = (wv.w > 0.f) ? 1.f : ((wv.w < 0.f) ? -1.f : 0.f);
        As[lc + 0][lr] = av.x; As[lc + 1][lr] = av.y;
        As[lc + 2][lr] = av.z; As[lc + 3][lr] = av.w;
        Ws[lc + 0][lr] = wv.x; Ws[lc + 1][lr] = wv.y;
        Ws[lc + 2][lr] = wv.z; Ws[lc + 3][lr] = wv.w;
        __syncthreads();

        ull blkP[4][2];
#pragma unroll
        for (int i = 0; i < 4; i++) { blkP[i][0] = 0ull; blkP[i][1] = 0ull; }
#pragma unroll
        for (int kk = 0; kk < 16; kk++) {
            float4 aa = *(const float4*)&As[kk][ty * 4];
            ulonglong2 bq = *(const ulonglong2*)&Ws[kk][tx * 4];
            ull a0 = packdup(aa.x), a1 = packdup(aa.y), a2 = packdup(aa.z), a3 = packdup(aa.w);
            blkP[0][0] = fma2(a0, bq.x, blkP[0][0]); blkP[0][1] = fma2(a0, bq.y, blkP[0][1]);
            blkP[1][0] = fma2(a1, bq.x, blkP[1][0]); blkP[1][1] = fma2(a1, bq.y, blkP[1][1]);
            blkP[2][0] = fma2(a2, bq.x, blkP[2][0]); blkP[2][1] = fma2(a2, bq.y, blkP[2][1]);
            blkP[3][0] = fma2(a3, bq.x, blkP[3][0]); blkP[3][1] = fma2(a3, bq.y, blkP[3][1]);
        }
#pragma unroll
        for (int i = 0; i < 4; i++)
#pragma unroll
            for (int p = 0; p < 2; p++) {
                float f0, f1;
                unpack2(blkP[i][p], f0, f1);
                twosum(s[i][2 * p], c[i][2 * p], f0);
                twosum(s[i][2 * p + 1], c[i][2 * p + 1], f1);
            }
        __syncthreads();
    }

    const int h = n0 >> 6;
#pragma unroll
    for (int i = 0; i < 4; i++) {
        int m = m0 + ty * 4 + i;
        int bb = m >> 10, t = m & 1023;
#pragma unroll
        for (int j = 0; j < 4; j++) {
            int n = n0 + tx * 4 + j;
            int d = n & 63;
            float v = __fadd_rn(__fadd_rn(s[i][j], c[i][j]), bias[n]);
            Q[(((size_t)(bb * H_ + h)) * T_ + t) * DH_ + d] = v;
        }
    }
}

// -------------- q post: RMS norm + exact per-head top-k (one row / block) --------------
__global__ void qpost(float* __restrict__ q)
{
    int row = blockIdx.x;           // row = bh*T + t
    int lane = threadIdx.x;         // 64 threads
    float v = q[(size_t)row * 64 + lane];
    float ss = v * v;
#pragma unroll
    for (int o = 16; o > 0; o >>= 1) ss += __shfl_xor_sync(0xffffffffu, ss, o);
    __shared__ float ws[2];
    if ((lane & 31) == 0) ws[lane >> 5] = ss;
    __syncthreads();
    float rms = sqrtf((ws[0] + ws[1]) * (1.f / 64.f)) + 1e-6f;
    float vn = v / rms;
    float a = fabsf(vn);
    __shared__ __align__(16) float sa[64];
    sa[lane] = a;
    __syncthreads();
    int g = 0;
    const float4* sv = (const float4*)sa;
#pragma unroll
    for (int j = 0; j < 16; j++) {
        float4 t = sv[j];
        g += (t.x > a) + (t.y > a) + (t.z > a) + (t.w > a);
    }
    int h = (row >> 10) & 15;
    int kc = KEEPC[h];
    float cand = (g <= kc - 1) ? a : INFINITY;
#pragma unroll
    for (int o = 16; o > 0; o >>= 1)
        cand = fminf(cand, __shfl_xor_sync(0xffffffffu, cand, o));
    __shared__ float wm[2];
    if ((lane & 31) == 0) wm[lane >> 5] = cand;
    __syncthreads();
    float th = fminf(wm[0], wm[1]);
    q[(size_t)row * 64 + lane] = (a >= th) ? vn : 0.f;
}

// -------------- k RMS norm (4 rows / block) --------------
__global__ void knorm(float* __restrict__ k)
{
    int lane = threadIdx.x & 63;
    int row = blockIdx.x * 4 + (threadIdx.x >> 6);
    float v = k[(size_t)row * 64 + lane];
    float ss = v * v;
#pragma unroll
    for (int o = 16; o > 0; o >>= 1) ss += __shfl_xor_sync(0xffffffffu, ss, o);
    __shared__ float ws[8];
    if ((threadIdx.x & 31) == 0) ws[threadIdx.x >> 5] = ss;
    __syncthreads();
    int grp = threadIdx.x >> 6;
    float tot = ws[grp * 2] + ws[grp * 2 + 1];
    float rms = sqrtf(tot * (1.f / 64.f)) + 1e-6f;
    k[(size_t)row * 64 + lane] = v / rms;
}

// -------------- fused flash attention: logits + online softmax + energy + AV --------------
__global__ __launch_bounds__(256) void attn_fused(
    const float* __restrict__ gq, const float* __restrict__ gk,
    const float* __restrict__ gv, float* __restrict__ ao,
    float* __restrict__ gepart)
{
    const int qt = blockIdx.x, bh = blockIdx.y;
    const int q0 = qt * 64;
    __shared__ __align__(16) float Qs[64][64];  // [d][r]
    __shared__ __align__(16) float Ks[64][64];  // [d][c]; reused as Ps and red
    __shared__ __align__(16) float Vs[64][64];  // [j][d]
    const int tid = threadIdx.x;
    const int tx = tid & 15, ty = tid >> 4;

    const float* qbase = gq + (size_t)bh * T_ * 64;
    const float* kbase = gk + (size_t)bh * T_ * 64;
    const float* vbase = gv + (size_t)bh * T_ * 64;

#pragma unroll
    for (int it = 0; it < 4; it++) {
        int idx = tid + it * 256;
        int r = idx & 63, d4 = (idx >> 6) * 4;
        float4 v = *(const float4*)(qbase + (size_t)(q0 + r) * 64 + d4);
        Qs[d4][r] = v.x; Qs[d4 + 1][r] = v.y; Qs[d4 + 2][r] = v.z; Qs[d4 + 3][r] = v.w;
    }

    float m_[4], l_[4], e2_[4];
    ull accP[4][2];
#pragma unroll
    for (int i = 0; i < 4; i++) {
        m_[i] = -INFINITY; l_[i] = 0.f; e2_[i] = 0.f;
        accP[i][0] = 0ull; accP[i][1] = 0ull;
    }

    float (*Ps)[64] = Ks;  // reuse

    for (int kt = 0; kt <= qt; kt++) {
        __syncthreads();
#pragma unroll
        for (int it = 0; it < 4; it++) {
            int idx = tid + it * 256;
            int r = idx & 63, d4 = (idx >> 6) * 4;
            float4 v = *(const float4*)(kbase + (size_t)(kt * 64 + r) * 64 + d4);
            Ks[d4][r] = v.x; Ks[d4 + 1][r] = v.y; Ks[d4 + 2][r] = v.z; Ks[d4 + 3][r] = v.w;
            int jr = idx >> 4, e4 = (idx & 15) * 4;
            float4 vv = *(const float4*)(vbase + (size_t)(kt * 64 + jr) * 64 + e4);
            *(float4*)&Vs[jr][e4] = vv;
        }
        __syncthreads();

        ull sP[4][2];
#pragma unroll
        for (int i = 0; i < 4; i++) { sP[i][0] = 0ull; sP[i][1] = 0ull; }
#pragma unroll 8
        for (int d = 0; d < 64; d++) {
            float4 aa = *(const float4*)&Qs[d][ty * 4];
            ulonglong2 bq = *(const ulonglong2*)&Ks[d][tx * 4];
            ull a0 = packdup(aa.x), a1 = packdup(aa.y), a2 = packdup(aa.z), a3 = packdup(aa.w);
            sP[0][0] = fma2(a0, bq.x, sP[0][0]); sP[0][1] = fma2(a0, bq.y, sP[0][1]);
            sP[1][0] = fma2(a1, bq.x, sP[1][0]); sP[1][1] = fma2(a1, bq.y, sP[1][1]);
            sP[2][0] = fma2(a2, bq.x, sP[2][0]); sP[2][1] = fma2(a2, bq.y, sP[2][1]);
            sP[3][0] = fma2(a3, bq.x, sP[3][0]); sP[3][1] = fma2(a3, bq.y, sP[3][1]);
        }
        float s[4][4];
#pragma unroll
        for (int i = 0; i < 4; i++) {
            unpack2(sP[i][0], s[i][0], s[i][1]);
            unpack2(sP[i][1], s[i][2], s[i][3]);
        }
        if (kt == qt) {
#pragma unroll
            for (int i = 0; i < 4; i++)
#pragma unroll
                for (int j = 0; j < 4; j++)
                    if (tx * 4 + j > ty * 4 + i) s[i][j] = -INFINITY;
        }

        float p[4][4];
#pragma unroll
        for (int i = 0; i < 4; i++) {
            float tm = fmaxf(fmaxf(s[i][0], s[i][1]), fmaxf(s[i][2], s[i][3]));
#pragma unroll
            for (int o = 1; o < 16; o <<= 1) tm = fmaxf(tm, __shfl_xor_sync(0xffffffffu, tm, o));
            float mn = fmaxf(m_[i], tm);
            float sc = __expf(m_[i] - mn);
            p[i][0] = __expf(s[i][0] - mn); p[i][1] = __expf(s[i][1] - mn);
            p[i][2] = __expf(s[i][2] - mn); p[i][3] = __expf(s[i][3] - mn);
            float se = p[i][0] + p[i][1] + p[i][2] + p[i][3];
            float s2 = p[i][0] * p[i][0] + p[i][1] * p[i][1]
                     + p[i][2] * p[i][2] + p[i][3] * p[i][3];
#pragma unroll
            for (int o = 1; o < 16; o <<= 1) {
                se += __shfl_xor_sync(0xffffffffu, se, o);
                s2 += __shfl_xor_sync(0xffffffffu, s2, o);
            }
            l_[i] = l_[i] * sc + se;
            e2_[i] = e2_[i] * sc * sc + s2;
            m_[i] = mn;
            ull scP = packdup(sc);
            accP[i][0] = mul2(accP[i][0], scP);
            accP[i][1] = mul2(accP[i][1], scP);
        }

        __syncthreads();
#pragma unroll
        for (int i = 0; i < 4; i++)
            *(float4*)&Ps[ty * 4 + i][tx * 4] = make_float4(p[i][0], p[i][1], p[i][2], p[i][3]);
        __syncthreads();

#pragma unroll 4
        for (int jb = 0; jb < 16; jb++) {
            float4 pv[4];
#pragma unroll
            for (int i = 0; i < 4; i++) pv[i] = *(const float4*)&Ps[ty * 4 + i][jb * 4];
            const float pvf[4][4] = {
                {pv[0].x, pv[0].y, pv[0].z, pv[0].w},
                {pv[1].x, pv[1].y, pv[1].z, pv[1].w},
                {pv[2].x, pv[2].y, pv[2].z, pv[2].w},
                {pv[3].x, pv[3].y, pv[3].z, pv[3].w}};
#pragma unroll
            for (int jj = 0; jj < 4; jj++) {
                ulonglong2 vq = *(const ulonglong2*)&Vs[jb * 4 + jj][tx * 4];
#pragma unroll
                for (int i = 0; i < 4; i++) {
                    ull pd = packdup(pvf[i][jj]);
                    accP[i][0] = fma2(pd, vq.x, accP[i][0]);
                    accP[i][1] = fma2(pd, vq.y, accP[i][1]);
                }
            }
        }
    }

    const int b = bh >> 4, h = bh & 15;
    float linv[4];
#pragma unroll
    for (int i = 0; i < 4; i++) linv[i] = 1.f / l_[i];
#pragma unroll
    for (int i = 0; i < 4; i++) {
        float f0, f1, f2, f3;
        unpack2(accP[i][0], f0, f1);
        unpack2(accP[i][1], f2, f3);
        float4 st = make_float4(f0 * linv[i], f1 * linv[i], f2 * linv[i], f3 * linv[i]);
        *(float4*)&ao[(size_t)(b * T_ + q0 + ty * 4 + i) * C_ + h * DH_ + tx * 4] = st;
    }

    __syncthreads();
    float* red = &Ks[0][0];
    float ev = 0.f;
    if (tx == 0) {
#pragma unroll
        for (int i = 0; i < 4; i++) ev += e2_[i] * linv[i] * linv[i];
    }
    red[tid] = ev;
    __syncthreads();
    for (int o = 128; o > 0; o >>= 1) {
        if (tid < o) red[tid] += red[tid + o];
        __syncthreads();
    }
    if (tid == 0) gepart[bh * 16 + qt] = red[0];
}

// -------------- head energy -> entropy -> adaptive head mask (double internals) --------------
__global__ void headmask(const float* __restrict__ epart, float* __restrict__ maskout)
{
    __shared__ double e[64];
    __shared__ double cand[64];
    int t = threadIdx.x;  // 64 = B*H
    double s = 0.0;
    for (int i = 0; i < 16; i++) s += (double)epart[t * 16 + i];
    e[t] = s / 1048576.0;
    __syncthreads();
    int b = t >> 4;
    double m = -1e300;
    for (int j = 0; j < 16; j++) m = fmax(m, e[b * 16 + j]);
    double Z = 0.0;
    for (int j = 0; j < 16; j++) Z += exp(e[b * 16 + j] - m);
    double ent = 0.0;
    for (int j = 0; j < 16; j++) {
        double p = exp(e[b * 16 + j] - m) / Z;
        ent -= p * log(p + 1e-9);
    }
    double entn = fmin(fmax(ent / log(16.0), 0.0), 1.0);
    int keep = (int)rint(2.0 + entn * 4.0);
    double eh = e[t];
    int g = 0;
    for (int j = 0; j < 16; j++) g += (e[b * 16 + j] > eh);
    cand[t] = (g <= keep - 1) ? eh : 1e300;
    __syncthreads();
    double th = 1e300;
    for (int j = 0; j < 16; j++) th = fmin(th, cand[b * 16 + j]);
    maskout[t] = (eh >= th) ? 1.f : 0.f;
}

// ---------------- launch ----------------
extern "C" void kernel_launch(void* const* d_in, const int* in_sizes, int n_in,
                              void* d_out, int out_size)
{
    const float* x  = (const float*)d_in[0];
    const float* qw = (const float*)d_in[1];
    const float* qb = (const float*)d_in[2];
    const float* kw = (const float*)d_in[3];
    const float* kb = (const float*)d_in[4];
    const float* vw = (const float*)d_in[5];
    const float* vb = (const float*)d_in[6];
    const float* ow = (const float*)d_in[7];
    const float* ob = (const float*)d_in[8];
    float* out = (float*)d_out;

    float *gq, *gk, *gv, *gep, *gm, *gao;
    cudaGetSymbolAddress((void**)&gq, g_q);
    cudaGetSymbolAddress((void**)&gk, g_k);
    cudaGetSymbolAddress((void**)&gv, g_v);
    cudaGetSymbolAddress((void**)&gep, g_epart);
    cudaGetSymbolAddress((void**)&gm, g_mask);
    cudaGetSymbolAddress((void**)&gao, g_ao);

    __nv_bfloat16 *xh, *xl, *kwh, *kwl, *vwh, *vwl, *owh, *owl, *aoh, *aol;
    cudaGetSymbolAddress((void**)&xh, g_xh);   cudaGetSymbolAddress((void**)&xl, g_xl);
    cudaGetSymbolAddress((void**)&kwh, g_kwh); cudaGetSymbolAddress((void**)&kwl, g_kwl);
    cudaGetSymbolAddress((void**)&vwh, g_vwh); cudaGetSymbolAddress((void**)&vwl, g_vwl);
    cudaGetSymbolAddress((void**)&owh, g_owh); cudaGetSymbolAddress((void**)&owl, g_owl);
    cudaGetSymbolAddress((void**)&aoh, g_aoh); cudaGetSymbolAddress((void**)&aol, g_aol);

    cudaFuncSetAttribute((const void*)gemm_mma,
                         cudaFuncAttributeMaxDynamicSharedMemorySize, 2 * STAGE_B);

    // bf16 splits
    split2k<<<M_ * C_ / 1024, 256>>>((const float4*)x, (ushort4*)xh, (ushort4*)xl);
    split2k<<<C_ * C_ / 1024, 256>>>((const float4*)kw, (ushort4*)kwh, (ushort4*)kwl);
    split2k<<<C_ * C_ / 1024, 256>>>((const float4*)vw, (ushort4*)vwh, (ushort4*)vwl);
    split2k<<<C_ * C_ / 1024, 256>>>((const float4*)ow, (ushort4*)owh, (ushort4*)owl);

    // projections
    dim3 qGrid(C_ / 64, M_ / 64);
    qgemm<<<qGrid, 256>>>(x, qw, qb, gq);
    dim3 tGrid(C_ / 128, M_ / 128);
    gemm_mma<<<tGrid, 256, 2 * STAGE_B>>>(xh, xl, kwh, kwl, kb, gk, 1);
    gemm_mma<<<tGrid, 256, 2 * STAGE_B>>>(xh, xl, vwh, vwl, vb, gv, 1);

    qpost<<<BH_ * T_, 64>>>(gq);
    knorm<<<BH_ * T_ / 4, 256>>>(gk);

    attn_fused<<<dim3(16, BH_), 256>>>(gq, gk, gv, gao, gep);
    headmask<<<1, 64>>>(gep, gm);

    // mask + split ao, then O projection on tensor cores
    split_ao<<<M_ * C_ / 1024, 256>>>((const float4*)gao, gm, (ushort4*)aoh, (ushort4*)aol);
    gemm_mma<<<tGrid, 256, 2 * STAGE_B>>>(aoh, aol, owh, owl, ob, out, 0);
}

// round 6
// speedup vs baseline: 1.7900x; 1.2323x over previous
#include <cuda_runtime.h>
#include <cuda_bf16.h>
#include <math.h>
#include <stdint.h>

#define B_  4
#define T_  1024
#define C_  1024
#define H_  16
#define DH_ 64
#define BH_ 64            // B_*H_
#define M_  4096          // B_*T_

typedef unsigned long long ull;

// ---------------- scratch (device globals: allocation-free) ----------------
__device__ float g_q[BH_ * T_ * DH_];       // 16 MB  (bh, t, d)
__device__ float g_k[BH_ * T_ * DH_];       // 16 MB
__device__ float g_v[BH_ * T_ * DH_];       // 16 MB
__device__ float g_epart[BH_ * 16];
__device__ float g_mask[BH_];
__device__ float g_ao[M_ * C_];             // 16 MB

// bf16 split buffers
__device__ __nv_bfloat16 g_xh[M_ * C_],  g_xl[M_ * C_], g_x3[M_ * C_];
__device__ __nv_bfloat16 g_qws[C_ * C_];                   // sign(qw) in bf16 (exact)
__device__ __nv_bfloat16 g_kwh[C_ * C_], g_kwl[C_ * C_];
__device__ __nv_bfloat16 g_vwh[C_ * C_], g_vwl[C_ * C_];
__device__ __nv_bfloat16 g_owh[C_ * C_], g_owl[C_ * C_];
__device__ __nv_bfloat16 g_aoh[M_ * C_], g_aol[M_ * C_];

// keep counts: trunc(linspace(0.35,0.15,16)*64), min 1
__constant__ int KEEPC[16] = {22,21,20,19,18,18,17,16,15,14,13,13,12,11,10,9};

// ---------------- packed f32x2 helpers ----------------
__device__ __forceinline__ ull packdup(float a) {
    ull r; unsigned u = __float_as_uint(a);
    asm("mov.b64 %0, {%1, %2};" : "=l"(r) : "r"(u), "r"(u));
    return r;
}
__device__ __forceinline__ void unpack2(ull v, float& x, float& y) {
    unsigned a, b;
    asm("mov.b64 {%0, %1}, %2;" : "=r"(a), "=r"(b) : "l"(v));
    x = __uint_as_float(a); y = __uint_as_float(b);
}
__device__ __forceinline__ ull fma2(ull a, ull b, ull c) {
    ull d;
    asm("fma.rn.f32x2 %0, %1, %2, %3;" : "=l"(d) : "l"(a), "l"(b), "l"(c));
    return d;
}
__device__ __forceinline__ ull mul2(ull a, ull b) {
    ull d;
    asm("mul.rn.f32x2 %0, %1, %2;" : "=l"(d) : "l"(a), "l"(b));
    return d;
}
__device__ __forceinline__ void twosum(float& s, float& c, float v) {
    float t  = __fadd_rn(s, v);
    float bo = __fsub_rn(t, s);
    float e1 = __fsub_rn(s, __fsub_rn(t, bo));
    float e2 = __fsub_rn(v, bo);
    c = __fadd_rn(c, __fadd_rn(e1, e2));
    s = t;
}

// ---------------- fast exp (no MUFU): d <= 0, rel err ~2.4e-8 ----------------
__device__ __forceinline__ float fast_exp(float d) {
    d = fmaxf(d, -80.f);
    float t = d * 1.4426950408889634f;
    float n = rintf(t);
    float f = fmaf(n, -0.693147182464599609375f, d);
    f = fmaf(n, 1.9046542999577680452e-9f, f);
    float p = 1.3888888888888889e-3f;          // 1/720
    p = fmaf(p, f, 8.3333333333333332e-3f);    // 1/120
    p = fmaf(p, f, 4.1666666666666664e-2f);    // 1/24
    p = fmaf(p, f, 1.6666666666666666e-1f);    // 1/6
    p = fmaf(p, f, 0.5f);
    p = fmaf(p, f, 1.0f);
    p = fmaf(p, f, 1.0f);
    int j = (int)n;
    return p * __uint_as_float((unsigned)(127 + j) << 23);
}

// ---------------- split kernels ----------------
__global__ void split3x(const float4* __restrict__ src, ushort4* __restrict__ o1,
                        ushort4* __restrict__ o2, ushort4* __restrict__ o3)
{
    int i = blockIdx.x * 256 + threadIdx.x;
    float4 v = src[i];
    float a[4] = {v.x, v.y, v.z, v.w};
    ushort4 H, L, T3;
    unsigned short* hp = &H.x; unsigned short* lp = &L.x; unsigned short* tp = &T3.x;
#pragma unroll
    for (int j = 0; j < 4; j++) {
        __nv_bfloat16 h = __float2bfloat16(a[j]);
        float r1 = a[j] - __bfloat162float(h);
        __nv_bfloat16 l = __float2bfloat16(r1);
        float r2 = r1 - __bfloat162float(l);
        __nv_bfloat16 t3 = __float2bfloat16(r2);
        hp[j] = __bfloat16_as_ushort(h);
        lp[j] = __bfloat16_as_ushort(l);
        tp[j] = __bfloat16_as_ushort(t3);
    }
    o1[i] = H; o2[i] = L; o3[i] = T3;
}

__global__ void split2k(const float4* __restrict__ src, ushort4* __restrict__ hi,
                        ushort4* __restrict__ lo)
{
    int i = blockIdx.x * 256 + threadIdx.x;
    float4 v = src[i];
    float a[4] = {v.x, v.y, v.z, v.w};
    ushort4 H, L;
    unsigned short* hp = &H.x; unsigned short* lp = &L.x;
#pragma unroll
    for (int j = 0; j < 4; j++) {
        __nv_bfloat16 h = __float2bfloat16(a[j]);
        __nv_bfloat16 l = __float2bfloat16(a[j] - __bfloat162float(h));
        hp[j] = __bfloat16_as_ushort(h);
        lp[j] = __bfloat16_as_ushort(l);
    }
    hi[i] = H; lo[i] = L;
}

__global__ void signw_bf16(const float4* __restrict__ w, ushort4* __restrict__ out)
{
    int i = blockIdx.x * 256 + threadIdx.x;
    float4 v = w[i];
    ushort4 o;
    o.x = (v.x > 0.f) ? 0x3F80 : ((v.x < 0.f) ? 0xBF80 : 0);
    o.y = (v.y > 0.f) ? 0x3F80 : ((v.y < 0.f) ? 0xBF80 : 0);
    o.z = (v.z > 0.f) ? 0x3F80 : ((v.z < 0.f) ? 0xBF80 : 0);
    o.w = (v.w > 0.f) ? 0x3F80 : ((v.w < 0.f) ? 0xBF80 : 0);
    out[i] = o;
}

__global__ void split_ao(const float4* __restrict__ src, const float* __restrict__ mask,
                         ushort4* __restrict__ hi, ushort4* __restrict__ lo)
{
    int i = blockIdx.x * 256 + threadIdx.x;
    int e = i * 4;
    int m = e >> 10, n = e & 1023;
    float mk = mask[((m >> 10) << 4) + (n >> 6)];
    float4 v = src[i];
    v.x *= mk; v.y *= mk; v.z *= mk; v.w *= mk;
    float a[4] = {v.x, v.y, v.z, v.w};
    ushort4 H, L;
    unsigned short* hp = &H.x; unsigned short* lp = &L.x;
#pragma unroll
    for (int j = 0; j < 4; j++) {
        __nv_bfloat16 h = __float2bfloat16(a[j]);
        __nv_bfloat16 l = __float2bfloat16(a[j] - __bfloat162float(h));
        hp[j] = __bfloat16_as_ushort(h);
        lp[j] = __bfloat16_as_ushort(l);
    }
    hi[i] = H; lo[i] = L;
}

// ---------------- mma helpers ----------------
__device__ __forceinline__ void mma16816(float* d,
    uint32_t a0, uint32_t a1, uint32_t a2, uint32_t a3,
    uint32_t b0, uint32_t b1)
{
    asm volatile(
        "mma.sync.aligned.m16n8k16.row.col.f32.bf16.bf16.f32 "
        "{%0,%1,%2,%3}, {%4,%5,%6,%7}, {%8,%9}, {%0,%1,%2,%3};"
        : "+f"(d[0]), "+f"(d[1]), "+f"(d[2]), "+f"(d[3])
        : "r"(a0), "r"(a1), "r"(a2), "r"(a3), "r"(b0), "r"(b1));
}

// ---------------- K/V/O GEMM (2-term split): 128x128, 8 warps ----------------
#define TILE_B   10240             // 128 * 80
#define STAGE_B  40960
#define NCHUNK   32

__device__ __forceinline__ void load_chunk_async(
    uint32_t sbase,
    const __nv_bfloat16* __restrict__ Ahi, const __nv_bfloat16* __restrict__ Alo,
    const __nv_bfloat16* __restrict__ Bhi, const __nv_bfloat16* __restrict__ Blo,
    int m0, int n0, int k0, int tid)
{
#pragma unroll
    for (int i = 0; i < 8; i++) {
        int u = tid + i * 256;
        int tile = u >> 9;
        int idx = u & 511;
        int row = idx >> 2;
        int jj = idx & 3;
        const __nv_bfloat16* g;
        if (tile == 0)      g = Ahi + (size_t)(m0 + row) * C_ + k0 + jj * 8;
        else if (tile == 1) g = Alo + (size_t)(m0 + row) * C_ + k0 + jj * 8;
        else if (tile == 2) g = Bhi + (size_t)(n0 + row) * C_ + k0 + jj * 8;
        else                g = Blo + (size_t)(n0 + row) * C_ + k0 + jj * 8;
        uint32_t dst = sbase + tile * TILE_B + row * 80 + jj * 16;
        asm volatile("cp.async.cg.shared.global [%0], [%1], 16;" :: "r"(dst), "l"(g));
    }
}

__global__ __launch_bounds__(256) void gemm_mma(
    const __nv_bfloat16* __restrict__ Ahi, const __nv_bfloat16* __restrict__ Alo,
    const __nv_bfloat16* __restrict__ Bhi, const __nv_bfloat16* __restrict__ Blo,
    const float* __restrict__ bias, float* __restrict__ Cout, int scatter)
{
    extern __shared__ char smc[];
    const int tid = threadIdx.x;
    const int lane = tid & 31, wid = tid >> 5;
    const int wm = wid >> 2, wn = wid & 3;
    const int gID = lane >> 2, tg = lane & 3;
    const int m0 = blockIdx.y * 128, n0 = blockIdx.x * 128;
    uint32_t sbase = (uint32_t)__cvta_generic_to_shared(smc);

    float acc[4][4][4];
#pragma unroll
    for (int mt = 0; mt < 4; mt++)
#pragma unroll
        for (int nt = 0; nt < 4; nt++)
#pragma unroll
            for (int r = 0; r < 4; r++) acc[mt][nt][r] = 0.f;

    load_chunk_async(sbase, Ahi, Alo, Bhi, Blo, m0, n0, 0, tid);
    asm volatile("cp.async.commit_group;" ::: "memory");
    asm volatile("cp.async.wait_group 0;" ::: "memory");
    __syncthreads();

    for (int c = 0; c < NCHUNK; c++) {
        if (c + 1 < NCHUNK) {
            load_chunk_async(sbase + ((c + 1) & 1) * STAGE_B,
                             Ahi, Alo, Bhi, Blo, m0, n0, (c + 1) * 32, tid);
            asm volatile("cp.async.commit_group;" ::: "memory");
        }
        const char* st = smc + (c & 1) * STAGE_B;
#pragma unroll
        for (int ks = 0; ks < 2; ks++) {
            const int acol = ks * 32 + tg * 4;
            uint32_t ah[4][4], al[4][4], bh[4][2], bl[4][2];
#pragma unroll
            for (int nt = 0; nt < 4; nt++) {
                int ro = (wn * 32 + nt * 8 + gID) * 80 + acol;
                bh[nt][0] = *(const uint32_t*)(st + 2 * TILE_B + ro);
                bh[nt][1] = *(const uint32_t*)(st + 2 * TILE_B + ro + 16);
                bl[nt][0] = *(const uint32_t*)(st + 3 * TILE_B + ro);
                bl[nt][1] = *(const uint32_t*)(st + 3 * TILE_B + ro + 16);
            }
#pragma unroll
            for (int mt = 0; mt < 4; mt++) {
                int ro = (wm * 64 + mt * 16 + gID) * 80 + acol;
                ah[mt][0] = *(const uint32_t*)(st + ro);
                ah[mt][1] = *(const uint32_t*)(st + ro + 640);
                ah[mt][2] = *(const uint32_t*)(st + ro + 16);
                ah[mt][3] = *(const uint32_t*)(st + ro + 656);
                al[mt][0] = *(const uint32_t*)(st + TILE_B + ro);
                al[mt][1] = *(const uint32_t*)(st + TILE_B + ro + 640);
                al[mt][2] = *(const uint32_t*)(st + TILE_B + ro + 16);
                al[mt][3] = *(const uint32_t*)(st + TILE_B + ro + 656);
            }
#pragma unroll
            for (int mt = 0; mt < 4; mt++)
#pragma unroll
                for (int nt = 0; nt < 4; nt++) {
                    mma16816(acc[mt][nt], ah[mt][0], ah[mt][1], ah[mt][2], ah[mt][3],
                             bh[nt][0], bh[nt][1]);
                    mma16816(acc[mt][nt], al[mt][0], al[mt][1], al[mt][2], al[mt][3],
                             bh[nt][0], bh[nt][1]);
                    mma16816(acc[mt][nt], ah[mt][0], ah[mt][1], ah[mt][2], ah[mt][3],
                             bl[nt][0], bl[nt][1]);
                }
        }
        if (c + 1 < NCHUNK)
            asm volatile("cp.async.wait_group 0;" ::: "memory");
        __syncthreads();
    }

#pragma unroll
    for (int mt = 0; mt < 4; mt++) {
        int m1 = m0 + wm * 64 + mt * 16 + gID;
#pragma unroll
        for (int nt = 0; nt < 4; nt++) {
            int n = n0 + wn * 32 + nt * 8 + tg * 2;
            float b0v = bias[n], b1v = bias[n + 1];
            float* a = acc[mt][nt];
            if (scatter) {
                int bb = m1 >> 10, t = m1 & 1023, h = n >> 6, d = n & 63;
                *(float2*)&Cout[(((size_t)(bb * H_ + h)) * T_ + t) * DH_ + d] =
                    make_float2(a[0] + b0v, a[1] + b1v);
                int m2 = m1 + 8;
                int bb2 = m2 >> 10, t2 = m2 & 1023;
                *(float2*)&Cout[(((size_t)(bb2 * H_ + h)) * T_ + t2) * DH_ + d] =
                    make_float2(a[2] + b0v, a[3] + b1v);
            } else {
                *(float2*)&Cout[(size_t)m1 * C_ + n] = make_float2(a[0] + b0v, a[1] + b1v);
                *(float2*)&Cout[(size_t)(m1 + 8) * C_ + n] = make_float2(a[2] + b0v, a[3] + b1v);
            }
        }
    }
}

// ---------------- q GEMM (exact 3-term split + chunked TwoSum): 64x128 ----------------
#define QTILE_B  5120              // 64 * 80
#define QW_B     10240             // 128 * 80
#define QSTAGE_B 25600             // 3*QTILE_B + QW_B
#define QNCH     32

__device__ __forceinline__ void qload_chunk_async(
    uint32_t sbase,
    const __nv_bfloat16* __restrict__ X1, const __nv_bfloat16* __restrict__ X2,
    const __nv_bfloat16* __restrict__ X3, const __nv_bfloat16* __restrict__ Ws,
    int m0, int n0, int k0, int tid)
{
#pragma unroll
    for (int i = 0; i < 5; i++) {
        int u = tid + i * 256;              // 0..1279
        const __nv_bfloat16* g;
        uint32_t dst;
        if (u < 768) {
            int term = u >> 8;
            int idx = u & 255;
            int row = idx >> 2, jj = idx & 3;
            const __nv_bfloat16* base = (term == 0) ? X1 : (term == 1) ? X2 : X3;
            g = base + (size_t)(m0 + row) * C_ + k0 + jj * 8;
            dst = sbase + term * QTILE_B + row * 80 + jj * 16;
        } else {
            int v = u - 768;                // 0..511
            int row = v >> 2, jj = v & 3;
            g = Ws + (size_t)(n0 + row) * C_ + k0 + jj * 8;
            dst = sbase + 3 * QTILE_B + row * 80 + jj * 16;
        }
        asm volatile("cp.async.cg.shared.global [%0], [%1], 16;" :: "r"(dst), "l"(g));
    }
}

__global__ __launch_bounds__(256) void qgemm_mma(
    const __nv_bfloat16* __restrict__ X1, const __nv_bfloat16* __restrict__ X2,
    const __nv_bfloat16* __restrict__ X3, const __nv_bfloat16* __restrict__ Ws,
    const float* __restrict__ bias, float* __restrict__ Q)
{
    extern __shared__ char smc[];
    const int tid = threadIdx.x;
    const int lane = tid & 31, wid = tid >> 5;
    const int wm = wid >> 2, wn = wid & 3;      // 2m x 4n, warp tile 32x32
    const int gID = lane >> 2, tg = lane & 3;
    const int m0 = blockIdx.y * 64, n0 = blockIdx.x * 128;
    uint32_t sbase = (uint32_t)__cvta_generic_to_shared(smc);

    float s_[2][4][4], c_[2][4][4];
#pragma unroll
    for (int mt = 0; mt < 2; mt++)
#pragma unroll
        for (int nt = 0; nt < 4; nt++)
#pragma unroll
            for (int r = 0; r < 4; r++) { s_[mt][nt][r] = 0.f; c_[mt][nt][r] = 0.f; }

    qload_chunk_async(sbase, X1, X2, X3, Ws, m0, n0, 0, tid);
    asm volatile("cp.async.commit_group;" ::: "memory");
    asm volatile("cp.async.wait_group 0;" ::: "memory");
    __syncthreads();

    for (int c = 0; c < QNCH; c++) {
        if (c + 1 < QNCH) {
            qload_chunk_async(sbase + ((c + 1) & 1) * QSTAGE_B,
                              X1, X2, X3, Ws, m0, n0, (c + 1) * 32, tid);
            asm volatile("cp.async.commit_group;" ::: "memory");
        }
        const char* st = smc + (c & 1) * QSTAGE_B;

        float tacc[2][4][4];
#pragma unroll
        for (int mt = 0; mt < 2; mt++)
#pragma unroll
            for (int nt = 0; nt < 4; nt++)
#pragma unroll
                for (int r = 0; r < 4; r++) tacc[mt][nt][r] = 0.f;

#pragma unroll
        for (int ks = 0; ks < 2; ks++) {
            const int acol = ks * 32 + tg * 4;
            uint32_t bw[4][2];
#pragma unroll
            for (int nt = 0; nt < 4; nt++) {
                int ro = (wn * 32 + nt * 8 + gID) * 80 + acol;
                bw[nt][0] = *(const uint32_t*)(st + 3 * QTILE_B + ro);
                bw[nt][1] = *(const uint32_t*)(st + 3 * QTILE_B + ro + 16);
            }
#pragma unroll
            for (int term = 0; term < 3; term++) {
                const char* at = st + term * QTILE_B;
                uint32_t ah[2][4];
#pragma unroll
                for (int mt = 0; mt < 2; mt++) {
                    int ro = (wm * 32 + mt * 16 + gID) * 80 + acol;
                    ah[mt][0] = *(const uint32_t*)(at + ro);
                    ah[mt][1] = *(const uint32_t*)(at + ro + 640);
                    ah[mt][2] = *(const uint32_t*)(at + ro + 16);
                    ah[mt][3] = *(const uint32_t*)(at + ro + 656);
                }
#pragma unroll
                for (int mt = 0; mt < 2; mt++)
#pragma unroll
                    for (int nt = 0; nt < 4; nt++)
                        mma16816(tacc[mt][nt], ah[mt][0], ah[mt][1], ah[mt][2], ah[mt][3],
                                 bw[nt][0], bw[nt][1]);
            }
        }
        // TwoSum flush (per K=32 chunk)
#pragma unroll
        for (int mt = 0; mt < 2; mt++)
#pragma unroll
            for (int nt = 0; nt < 4; nt++)
#pragma unroll
                for (int r = 0; r < 4; r++)
                    twosum(s_[mt][nt][r], c_[mt][nt][r], tacc[mt][nt][r]);

        if (c + 1 < QNCH)
            asm volatile("cp.async.wait_group 0;" ::: "memory");
        __syncthreads();
    }

    // epilogue: scatter to (bh, t, d)
#pragma unroll
    for (int mt = 0; mt < 2; mt++) {
        int m1 = m0 + wm * 32 + mt * 16 + gID;
#pragma unroll
        for (int nt = 0; nt < 4; nt++) {
            int n = n0 + wn * 32 + nt * 8 + tg * 2;
            int h = n >> 6, d = n & 63;
            float b0v = bias[n], b1v = bias[n + 1];
            float v0 = __fadd_rn(__fadd_rn(s_[mt][nt][0], c_[mt][nt][0]), b0v);
            float v1 = __fadd_rn(__fadd_rn(s_[mt][nt][1], c_[mt][nt][1]), b1v);
            float v2 = __fadd_rn(__fadd_rn(s_[mt][nt][2], c_[mt][nt][2]), b0v);
            float v3 = __fadd_rn(__fadd_rn(s_[mt][nt][3], c_[mt][nt][3]), b1v);
            int bb = m1 >> 10, t = m1 & 1023;
            *(float2*)&Q[(((size_t)(bb * H_ + h)) * T_ + t) * DH_ + d] = make_float2(v0, v1);
            int m2 = m1 + 8;
            int bb2 = m2 >> 10, t2 = m2 & 1023;
            *(float2*)&Q[(((size_t)(bb2 * H_ + h)) * T_ + t2) * DH_ + d] = make_float2(v2, v3);
        }
    }
}

// -------------- q post: RMS norm + exact per-head top-k (4 rows / block) --------------
__global__ __launch_bounds__(256) void qpost(float* __restrict__ q)
{
    int grp = threadIdx.x >> 6;      // 0..3
    int lane = threadIdx.x & 63;
    int row = blockIdx.x * 4 + grp;  // row = bh*T + t
    float v = q[(size_t)row * 64 + lane];
    float ss = v * v;
#pragma unroll
    for (int o = 16; o > 0; o >>= 1) ss += __shfl_xor_sync(0xffffffffu, ss, o);
    __shared__ float ws[8];
    if ((threadIdx.x & 31) == 0) ws[threadIdx.x >> 5] = ss;
    __syncthreads();
    float rms = sqrtf((ws[grp * 2] + ws[grp * 2 + 1]) * (1.f / 64.f)) + 1e-6f;
    float vn = v / rms;
    float a = fabsf(vn);
    __shared__ __align__(16) float sa[4][64];
    sa[grp][lane] = a;
    __syncthreads();
    int g = 0;
    const float4* sv = (const float4*)sa[grp];
#pragma unroll
    for (int j = 0; j < 16; j++) {
        float4 t = sv[j];
        g += (t.x > a) + (t.y > a) + (t.z > a) + (t.w > a);
    }
    int h = (row >> 10) & 15;
    int kc = KEEPC[h];
    float cand = (g <= kc - 1) ? a : INFINITY;
#pragma unroll
    for (int o = 16; o > 0; o >>= 1)
        cand = fminf(cand, __shfl_xor_sync(0xffffffffu, cand, o));
    __shared__ float wm_[8];
    if ((threadIdx.x & 31) == 0) wm_[threadIdx.x >> 5] = cand;
    __syncthreads();
    float th = fminf(wm_[grp * 2], wm_[grp * 2 + 1]);
    q[(size_t)row * 64 + lane] = (a >= th) ? vn : 0.f;
}

// -------------- k RMS norm (4 rows / block) --------------
__global__ void knorm(float* __restrict__ k)
{
    int lane = threadIdx.x & 63;
    int row = blockIdx.x * 4 + (threadIdx.x >> 6);
    float v = k[(size_t)row * 64 + lane];
    float ss = v * v;
#pragma unroll
    for (int o = 16; o > 0; o >>= 1) ss += __shfl_xor_sync(0xffffffffu, ss, o);
    __shared__ float ws[8];
    if ((threadIdx.x & 31) == 0) ws[threadIdx.x >> 5] = ss;
    __syncthreads();
    int grp = threadIdx.x >> 6;
    float tot = ws[grp * 2] + ws[grp * 2 + 1];
    float rms = sqrtf(tot * (1.f / 64.f)) + 1e-6f;
    k[(size_t)row * 64 + lane] = v / rms;
}

// -------------- fused flash attention (software exp) --------------
__global__ __launch_bounds__(256) void attn_fused(
    const float* __restrict__ gq, const float* __restrict__ gk,
    const float* __restrict__ gv, float* __restrict__ ao,
    float* __restrict__ gepart)
{
    const int qt = blockIdx.x, bh = blockIdx.y;
    const int q0 = qt * 64;
    __shared__ __align__(16) float Qs[64][64];  // [d][r]
    __shared__ __align__(16) float Ks[64][64];  // [d][c]; reused as Ps and red
    __shared__ __align__(16) float Vs[64][64];  // [j][d]
    const int tid = threadIdx.x;
    const int tx = tid & 15, ty = tid >> 4;

    const float* qbase = gq + (size_t)bh * T_ * 64;
    const float* kbase = gk + (size_t)bh * T_ * 64;
    const float* vbase = gv + (size_t)bh * T_ * 64;

#pragma unroll
    for (int it = 0; it < 4; it++) {
        int idx = tid + it * 256;
        int r = idx & 63, d4 = (idx >> 6) * 4;
        float4 v = *(const float4*)(qbase + (size_t)(q0 + r) * 64 + d4);
        Qs[d4][r] = v.x; Qs[d4 + 1][r] = v.y; Qs[d4 + 2][r] = v.z; Qs[d4 + 3][r] = v.w;
    }

    float m_[4], l_[4], e2_[4];
    ull accP[4][2];
#pragma unroll
    for (int i = 0; i < 4; i++) {
        m_[i] = -INFINITY; l_[i] = 0.f; e2_[i] = 0.f;
        accP[i][0] = 0ull; accP[i][1] = 0ull;
    }

    float (*Ps)[64] = Ks;

    for (int kt = 0; kt <= qt; kt++) {
        __syncthreads();
#pragma unroll
        for (int it = 0; it < 4; it++) {
            int idx = tid + it * 256;
            int r = idx & 63, d4 = (idx >> 6) * 4;
            float4 v = *(const float4*)(kbase + (size_t)(kt * 64 + r) * 64 + d4);
            Ks[d4][r] = v.x; Ks[d4 + 1][r] = v.y; Ks[d4 + 2][r] = v.z; Ks[d4 + 3][r] = v.w;
            int jr = idx >> 4, e4 = (idx & 15) * 4;
            float4 vv = *(const float4*)(vbase + (size_t)(kt * 64 + jr) * 64 + e4);
            *(float4*)&Vs[jr][e4] = vv;
        }
        __syncthreads();

        ull sP[4][2];
#pragma unroll
        for (int i = 0; i < 4; i++) { sP[i][0] = 0ull; sP[i][1] = 0ull; }
#pragma unroll 8
        for (int d = 0; d < 64; d++) {
            float4 aa = *(const float4*)&Qs[d][ty * 4];
            ulonglong2 bq = *(const ulonglong2*)&Ks[d][tx * 4];
            ull a0 = packdup(aa.x), a1 = packdup(aa.y), a2 = packdup(aa.z), a3 = packdup(aa.w);
            sP[0][0] = fma2(a0, bq.x, sP[0][0]); sP[0][1] = fma2(a0, bq.y, sP[0][1]);
            sP[1][0] = fma2(a1, bq.x, sP[1][0]); sP[1][1] = fma2(a1, bq.y, sP[1][1]);
            sP[2][0] = fma2(a2, bq.x, sP[2][0]); sP[2][1] = fma2(a2, bq.y, sP[2][1]);
            sP[3][0] = fma2(a3, bq.x, sP[3][0]); sP[3][1] = fma2(a3, bq.y, sP[3][1]);
        }
        float s[4][4];
#pragma unroll
        for (int i = 0; i < 4; i++) {
            unpack2(sP[i][0], s[i][0], s[i][1]);
            unpack2(sP[i][1], s[i][2], s[i][3]);
        }
        if (kt == qt) {
#pragma unroll
            for (int i = 0; i < 4; i++)
#pragma unroll
                for (int j = 0; j < 4; j++)
                    if (tx * 4 + j > ty * 4 + i) s[i][j] = -INFINITY;
        }

        float p[4][4];
#pragma unroll
        for (int i = 0; i < 4; i++) {
            float tm = fmaxf(fmaxf(s[i][0], s[i][1]), fmaxf(s[i][2], s[i][3]));
#pragma unroll
            for (int o = 1; o < 16; o <<= 1) tm = fmaxf(tm, __shfl_xor_sync(0xffffffffu, tm, o));
            float mn = fmaxf(m_[i], tm);
            float sc = fast_exp(m_[i] - mn);
            p[i][0] = fast_exp(s[i][0] - mn); p[i][1] = fast_exp(s[i][1] - mn);
            p[i][2] = fast_exp(s[i][2] - mn); p[i][3] = fast_exp(s[i][3] - mn);
            float se = p[i][0] + p[i][1] + p[i][2] + p[i][3];
            float s2 = p[i][0] * p[i][0] + p[i][1] * p[i][1]
                     + p[i][2] * p[i][2] + p[i][3] * p[i][3];
#pragma unroll
            for (int o = 1; o < 16; o <<= 1) {
                se += __shfl_xor_sync(0xffffffffu, se, o);
                s2 += __shfl_xor_sync(0xffffffffu, s2, o);
            }
            l_[i] = l_[i] * sc + se;
            e2_[i] = e2_[i] * sc * sc + s2;
            m_[i] = mn;
            ull scP = packdup(sc);
            accP[i][0] = mul2(accP[i][0], scP);
            accP[i][1] = mul2(accP[i][1], scP);
        }

        __syncthreads();
#pragma unroll
        for (int i = 0; i < 4; i++)
            *(float4*)&Ps[ty * 4 + i][tx * 4] = make_float4(p[i][0], p[i][1], p[i][2], p[i][3]);
        __syncthreads();

#pragma unroll 4
        for (int jb = 0; jb < 16; jb++) {
            float4 pv[4];
#pragma unroll
            for (int i = 0; i < 4; i++) pv[i] = *(const float4*)&Ps[ty * 4 + i][jb * 4];
            const float pvf[4][4] = {
                {pv[0].x, pv[0].y, pv[0].z, pv[0].w},
                {pv[1].x, pv[1].y, pv[1].z, pv[1].w},
                {pv[2].x, pv[2].y, pv[2].z, pv[2].w},
                {pv[3].x, pv[3].y, pv[3].z, pv[3].w}};
#pragma unroll
            for (int jj = 0; jj < 4; jj++) {
                ulonglong2 vq = *(const ulonglong2*)&Vs[jb * 4 + jj][tx * 4];
#pragma unroll
                for (int i = 0; i < 4; i++) {
                    ull pd = packdup(pvf[i][jj]);
                    accP[i][0] = fma2(pd, vq.x, accP[i][0]);
                    accP[i][1] = fma2(pd, vq.y, accP[i][1]);
                }
            }
        }
    }

    const int b = bh >> 4, h = bh & 15;
    float linv[4];
#pragma unroll
    for (int i = 0; i < 4; i++) linv[i] = 1.f / l_[i];
#pragma unroll
    for (int i = 0; i < 4; i++) {
        float f0, f1, f2, f3;
        unpack2(accP[i][0], f0, f1);
        unpack2(accP[i][1], f2, f3);
        float4 st = make_float4(f0 * linv[i], f1 * linv[i], f2 * linv[i], f3 * linv[i]);
        *(float4*)&ao[(size_t)(b * T_ + q0 + ty * 4 + i) * C_ + h * DH_ + tx * 4] = st;
    }

    __syncthreads();
    float* red = &Ks[0][0];
    float ev = 0.f;
    if (tx == 0) {
#pragma unroll
        for (int i = 0; i < 4; i++) ev += e2_[i] * linv[i] * linv[i];
    }
    red[tid] = ev;
    __syncthreads();
    for (int o = 128; o > 0; o >>= 1) {
        if (tid < o) red[tid] += red[tid + o];
        __syncthreads();
    }
    if (tid == 0) gepart[bh * 16 + qt] = red[0];
}

// -------------- head energy -> entropy -> adaptive head mask --------------
__global__ void headmask(const float* __restrict__ epart, float* __restrict__ maskout)
{
    __shared__ double e[64];
    __shared__ double cand[64];
    int t = threadIdx.x;
    double s = 0.0;
    for (int i = 0; i < 16; i++) s += (double)epart[t * 16 + i];
    e[t] = s / 1048576.0;
    __syncthreads();
    int b = t >> 4;
    double m = -1e300;
    for (int j = 0; j < 16; j++) m = fmax(m, e[b * 16 + j]);
    double Z = 0.0;
    for (int j = 0; j < 16; j++) Z += exp(e[b * 16 + j] - m);
    double ent = 0.0;
    for (int j = 0; j < 16; j++) {
        double p = exp(e[b * 16 + j] - m) / Z;
        ent -= p * log(p + 1e-9);
    }
    double entn = fmin(fmax(ent / log(16.0), 0.0), 1.0);
    int keep = (int)rint(2.0 + entn * 4.0);
    double eh = e[t];
    int g = 0;
    for (int j = 0; j < 16; j++) g += (e[b * 16 + j] > eh);
    cand[t] = (g <= keep - 1) ? eh : 1e300;
    __syncthreads();
    double th = 1e300;
    for (int j = 0; j < 16; j++) th = fmin(th, cand[b * 16 + j]);
    maskout[t] = (eh >= th) ? 1.f : 0.f;
}

// ---------------- launch ----------------
extern "C" void kernel_launch(void* const* d_in, const int* in_sizes, int n_in,
                              void* d_out, int out_size)
{
    const float* x  = (const float*)d_in[0];
    const float* qw = (const float*)d_in[1];
    const float* qb = (const float*)d_in[2];
    const float* kw = (const float*)d_in[3];
    const float* kb = (const float*)d_in[4];
    const float* vw = (const float*)d_in[5];
    const float* vb = (const float*)d_in[6];
    const float* ow = (const float*)d_in[7];
    const float* ob = (const float*)d_in[8];
    float* out = (float*)d_out;

    float *gq, *gk, *gv, *gep, *gm, *gao;
    cudaGetSymbolAddress((void**)&gq, g_q);
    cudaGetSymbolAddress((void**)&gk, g_k);
    cudaGetSymbolAddress((void**)&gv, g_v);
    cudaGetSymbolAddress((void**)&gep, g_epart);
    cudaGetSymbolAddress((void**)&gm, g_mask);
    cudaGetSymbolAddress((void**)&gao, g_ao);

    __nv_bfloat16 *xh, *xl, *x3, *qws, *kwh, *kwl, *vwh, *vwl, *owh, *owl, *aoh, *aol;
    cudaGetSymbolAddress((void**)&xh, g_xh);   cudaGetSymbolAddress((void**)&xl, g_xl);
    cudaGetSymbolAddress((void**)&x3, g_x3);   cudaGetSymbolAddress((void**)&qws, g_qws);
    cudaGetSymbolAddress((void**)&kwh, g_kwh); cudaGetSymbolAddress((void**)&kwl, g_kwl);
    cudaGetSymbolAddress((void**)&vwh, g_vwh); cudaGetSymbolAddress((void**)&vwl, g_vwl);
    cudaGetSymbolAddress((void**)&owh, g_owh); cudaGetSymbolAddress((void**)&owl, g_owl);
    cudaGetSymbolAddress((void**)&aoh, g_aoh); cudaGetSymbolAddress((void**)&aol, g_aol);

    cudaFuncSetAttribute((const void*)gemm_mma,
                         cudaFuncAttributeMaxDynamicSharedMemorySize, 2 * STAGE_B);
    cudaFuncSetAttribute((const void*)qgemm_mma,
                         cudaFuncAttributeMaxDynamicSharedMemorySize, 2 * QSTAGE_B);

    // splits
    split3x<<<M_ * C_ / 1024, 256>>>((const float4*)x, (ushort4*)xh, (ushort4*)xl, (ushort4*)x3);
    signw_bf16<<<C_ * C_ / 1024, 256>>>((const float4*)qw, (ushort4*)qws);
    split2k<<<C_ * C_ / 1024, 256>>>((const float4*)kw, (ushort4*)kwh, (ushort4*)kwl);
    split2k<<<C_ * C_ / 1024, 256>>>((const float4*)vw, (ushort4*)vwh, (ushort4*)vwl);
    split2k<<<C_ * C_ / 1024, 256>>>((const float4*)ow, (ushort4*)owh, (ushort4*)owl);

    // projections
    qgemm_mma<<<dim3(C_ / 128, M_ / 64), 256, 2 * QSTAGE_B>>>(xh, xl, x3, qws, qb, gq);
    dim3 tGrid(C_ / 128, M_ / 128);
    gemm_mma<<<tGrid, 256, 2 * STAGE_B>>>(xh, xl, kwh, kwl, kb, gk, 1);
    gemm_mma<<<tGrid, 256, 2 * STAGE_B>>>(xh, xl, vwh, vwl, vb, gv, 1);

    qpost<<<BH_ * T_ / 4, 256>>>(gq);
    knorm<<<BH_ * T_ / 4, 256>>>(gk);

    attn_fused<<<dim3(16, BH_), 256>>>(gq, gk, gv, gao, gep);
    headmask<<<1, 64>>>(gep, gm);

    split_ao<<<M_ * C_ / 1024, 256>>>((const float4*)gao, gm, (ushort4*)aoh, (ushort4*)aol);
    gemm_mma<<<tGrid, 256, 2 * STAGE_B>>>(aoh, aol, owh, owl, ob, out, 0);
}

// round 7
// speedup vs baseline: 2.3357x; 1.3049x over previous
#include <cuda_runtime.h>
#include <cuda_bf16.h>
#include <math.h>
#include <stdint.h>

#define B_  4
#define T_  1024
#define C_  1024
#define H_  16
#define DH_ 64
#define BH_ 64            // B_*H_
#define M_  4096          // B_*T_

// ---------------- scratch (device globals: allocation-free) ----------------
__device__ float g_q[BH_ * T_ * DH_];       // fp32 q after projection
__device__ float g_k[BH_ * T_ * DH_];
__device__ float g_v[BH_ * T_ * DH_];
__device__ float g_epart[BH_ * 16];
__device__ float g_mask[BH_];
__device__ float g_ao[M_ * C_];

// bf16 split buffers
__device__ __nv_bfloat16 g_xh[M_ * C_],  g_xl[M_ * C_], g_x3[M_ * C_];
__device__ __nv_bfloat16 g_qws[C_ * C_];
__device__ __nv_bfloat16 g_kwh[C_ * C_], g_kwl[C_ * C_];
__device__ __nv_bfloat16 g_vwh[C_ * C_], g_vwl[C_ * C_];
__device__ __nv_bfloat16 g_owh[C_ * C_], g_owl[C_ * C_];
__device__ __nv_bfloat16 g_aoh[M_ * C_], g_aol[M_ * C_];
// attention operand splits
__device__ __nv_bfloat16 g_qsh[BH_ * T_ * DH_], g_qsl[BH_ * T_ * DH_];   // (bh,t,d)
__device__ __nv_bfloat16 g_ksh[BH_ * T_ * DH_], g_ksl[BH_ * T_ * DH_];   // (bh,t,d)
__device__ __nv_bfloat16 g_vth[BH_ * T_ * DH_], g_vtl[BH_ * T_ * DH_];   // (bh,d,t)

__constant__ int KEEPC[16] = {22,21,20,19,18,18,17,16,15,14,13,13,12,11,10,9};

// ---------------- helpers ----------------
__device__ __forceinline__ void twosum(float& s, float& c, float v) {
    float t  = __fadd_rn(s, v);
    float bo = __fsub_rn(t, s);
    float e1 = __fsub_rn(s, __fsub_rn(t, bo));
    float e2 = __fsub_rn(v, bo);
    c = __fadd_rn(c, __fadd_rn(e1, e2));
    s = t;
}

// fast exp (no MUFU): d <= 0, rel err ~2.4e-8
__device__ __forceinline__ float fast_exp(float d) {
    d = fmaxf(d, -80.f);
    float t = d * 1.4426950408889634f;
    float n = rintf(t);
    float f = fmaf(n, -0.693147182464599609375f, d);
    f = fmaf(n, 1.9046542999577680452e-9f, f);
    float p = 1.3888888888888889e-3f;
    p = fmaf(p, f, 8.3333333333333332e-3f);
    p = fmaf(p, f, 4.1666666666666664e-2f);
    p = fmaf(p, f, 1.6666666666666666e-1f);
    p = fmaf(p, f, 0.5f);
    p = fmaf(p, f, 1.0f);
    p = fmaf(p, f, 1.0f);
    int j = (int)n;
    return p * __uint_as_float((unsigned)(127 + j) << 23);
}

__device__ __forceinline__ uint32_t pack_bf16x2(float lo, float hi) {
    uint32_t r;
    asm("cvt.rn.bf16x2.f32 %0, %1, %2;" : "=r"(r) : "f"(hi), "f"(lo));
    return r;
}

__device__ __forceinline__ void mma16816(float* d,
    uint32_t a0, uint32_t a1, uint32_t a2, uint32_t a3,
    uint32_t b0, uint32_t b1)
{
    asm volatile(
        "mma.sync.aligned.m16n8k16.row.col.f32.bf16.bf16.f32 "
        "{%0,%1,%2,%3}, {%4,%5,%6,%7}, {%8,%9}, {%0,%1,%2,%3};"
        : "+f"(d[0]), "+f"(d[1]), "+f"(d[2]), "+f"(d[3])
        : "r"(a0), "r"(a1), "r"(a2), "r"(a3), "r"(b0), "r"(b1));
}

// ---------------- split kernels ----------------
__global__ void split3x(const float4* __restrict__ src, ushort4* __restrict__ o1,
                        ushort4* __restrict__ o2, ushort4* __restrict__ o3)
{
    int i = blockIdx.x * 256 + threadIdx.x;
    float4 v = src[i];
    float a[4] = {v.x, v.y, v.z, v.w};
    ushort4 H, L, T3;
    unsigned short* hp = &H.x; unsigned short* lp = &L.x; unsigned short* tp = &T3.x;
#pragma unroll
    for (int j = 0; j < 4; j++) {
        __nv_bfloat16 h = __float2bfloat16(a[j]);
        float r1 = a[j] - __bfloat162float(h);
        __nv_bfloat16 l = __float2bfloat16(r1);
        float r2 = r1 - __bfloat162float(l);
        tp[j] = __bfloat16_as_ushort(__float2bfloat16(r2));
        hp[j] = __bfloat16_as_ushort(h);
        lp[j] = __bfloat16_as_ushort(l);
    }
    o1[i] = H; o2[i] = L; o3[i] = T3;
}

__global__ void split2k(const float4* __restrict__ src, ushort4* __restrict__ hi,
                        ushort4* __restrict__ lo)
{
    int i = blockIdx.x * 256 + threadIdx.x;
    float4 v = src[i];
    float a[4] = {v.x, v.y, v.z, v.w};
    ushort4 H, L;
    unsigned short* hp = &H.x; unsigned short* lp = &L.x;
#pragma unroll
    for (int j = 0; j < 4; j++) {
        __nv_bfloat16 h = __float2bfloat16(a[j]);
        __nv_bfloat16 l = __float2bfloat16(a[j] - __bfloat162float(h));
        hp[j] = __bfloat16_as_ushort(h);
        lp[j] = __bfloat16_as_ushort(l);
    }
    hi[i] = H; lo[i] = L;
}

__global__ void signw_bf16(const float4* __restrict__ w, ushort4* __restrict__ out)
{
    int i = blockIdx.x * 256 + threadIdx.x;
    float4 v = w[i];
    ushort4 o;
    o.x = (v.x > 0.f) ? 0x3F80 : ((v.x < 0.f) ? 0xBF80 : 0);
    o.y = (v.y > 0.f) ? 0x3F80 : ((v.y < 0.f) ? 0xBF80 : 0);
    o.z = (v.z > 0.f) ? 0x3F80 : ((v.z < 0.f) ? 0xBF80 : 0);
    o.w = (v.w > 0.f) ? 0x3F80 : ((v.w < 0.f) ? 0xBF80 : 0);
    out[i] = o;
}

__global__ void split_ao(const float4* __restrict__ src, const float* __restrict__ mask,
                         ushort4* __restrict__ hi, ushort4* __restrict__ lo)
{
    int i = blockIdx.x * 256 + threadIdx.x;
    int e = i * 4;
    int m = e >> 10, n = e & 1023;
    float mk = mask[((m >> 10) << 4) + (n >> 6)];
    float4 v = src[i];
    v.x *= mk; v.y *= mk; v.z *= mk; v.w *= mk;
    float a[4] = {v.x, v.y, v.z, v.w};
    ushort4 H, L;
    unsigned short* hp = &H.x; unsigned short* lp = &L.x;
#pragma unroll
    for (int j = 0; j < 4; j++) {
        __nv_bfloat16 h = __float2bfloat16(a[j]);
        __nv_bfloat16 l = __float2bfloat16(a[j] - __bfloat162float(h));
        hp[j] = __bfloat16_as_ushort(h);
        lp[j] = __bfloat16_as_ushort(l);
    }
    hi[i] = H; lo[i] = L;
}

// ---------------- K/V/O GEMM (2-term split): 128x128, 8 warps ----------------
#define TILE_B   10240
#define STAGE_B  40960
#define NCHUNK   32

__device__ __forceinline__ void load_chunk_async(
    uint32_t sbase,
    const __nv_bfloat16* __restrict__ Ahi, const __nv_bfloat16* __restrict__ Alo,
    const __nv_bfloat16* __restrict__ Bhi, const __nv_bfloat16* __restrict__ Blo,
    int m0, int n0, int k0, int tid)
{
#pragma unroll
    for (int i = 0; i < 8; i++) {
        int u = tid + i * 256;
        int tile = u >> 9;
        int idx = u & 511;
        int row = idx >> 2;
        int jj = idx & 3;
        const __nv_bfloat16* g;
        if (tile == 0)      g = Ahi + (size_t)(m0 + row) * C_ + k0 + jj * 8;
        else if (tile == 1) g = Alo + (size_t)(m0 + row) * C_ + k0 + jj * 8;
        else if (tile == 2) g = Bhi + (size_t)(n0 + row) * C_ + k0 + jj * 8;
        else                g = Blo + (size_t)(n0 + row) * C_ + k0 + jj * 8;
        uint32_t dst = sbase + tile * TILE_B + row * 80 + jj * 16;
        asm volatile("cp.async.cg.shared.global [%0], [%1], 16;" :: "r"(dst), "l"(g));
    }
}

__global__ __launch_bounds__(256) void gemm_mma(
    const __nv_bfloat16* __restrict__ Ahi, const __nv_bfloat16* __restrict__ Alo,
    const __nv_bfloat16* __restrict__ Bhi, const __nv_bfloat16* __restrict__ Blo,
    const float* __restrict__ bias, float* __restrict__ Cout, int scatter)
{
    extern __shared__ char smc[];
    const int tid = threadIdx.x;
    const int lane = tid & 31, wid = tid >> 5;
    const int wm = wid >> 2, wn = wid & 3;
    const int gID = lane >> 2, tg = lane & 3;
    const int m0 = blockIdx.y * 128, n0 = blockIdx.x * 128;
    uint32_t sbase = (uint32_t)__cvta_generic_to_shared(smc);

    float acc[4][4][4];
#pragma unroll
    for (int mt = 0; mt < 4; mt++)
#pragma unroll
        for (int nt = 0; nt < 4; nt++)
#pragma unroll
            for (int r = 0; r < 4; r++) acc[mt][nt][r] = 0.f;

    load_chunk_async(sbase, Ahi, Alo, Bhi, Blo, m0, n0, 0, tid);
    asm volatile("cp.async.commit_group;" ::: "memory");
    asm volatile("cp.async.wait_group 0;" ::: "memory");
    __syncthreads();

    for (int c = 0; c < NCHUNK; c++) {
        if (c + 1 < NCHUNK) {
            load_chunk_async(sbase + ((c + 1) & 1) * STAGE_B,
                             Ahi, Alo, Bhi, Blo, m0, n0, (c + 1) * 32, tid);
            asm volatile("cp.async.commit_group;" ::: "memory");
        }
        const char* st = smc + (c & 1) * STAGE_B;
#pragma unroll
        for (int ks = 0; ks < 2; ks++) {
            const int acol = ks * 32 + tg * 4;
            uint32_t ah[4][4], al[4][4], bhf[4][2], blf[4][2];
#pragma unroll
            for (int nt = 0; nt < 4; nt++) {
                int ro = (wn * 32 + nt * 8 + gID) * 80 + acol;
                bhf[nt][0] = *(const uint32_t*)(st + 2 * TILE_B + ro);
                bhf[nt][1] = *(const uint32_t*)(st + 2 * TILE_B + ro + 16);
                blf[nt][0] = *(const uint32_t*)(st + 3 * TILE_B + ro);
                blf[nt][1] = *(const uint32_t*)(st + 3 * TILE_B + ro + 16);
            }
#pragma unroll
            for (int mt = 0; mt < 4; mt++) {
                int ro = (wm * 64 + mt * 16 + gID) * 80 + acol;
                ah[mt][0] = *(const uint32_t*)(st + ro);
                ah[mt][1] = *(const uint32_t*)(st + ro + 640);
                ah[mt][2] = *(const uint32_t*)(st + ro + 16);
                ah[mt][3] = *(const uint32_t*)(st + ro + 656);
                al[mt][0] = *(const uint32_t*)(st + TILE_B + ro);
                al[mt][1] = *(const uint32_t*)(st + TILE_B + ro + 640);
                al[mt][2] = *(const uint32_t*)(st + TILE_B + ro + 16);
                al[mt][3] = *(const uint32_t*)(st + TILE_B + ro + 656);
            }
#pragma unroll
            for (int mt = 0; mt < 4; mt++)
#pragma unroll
                for (int nt = 0; nt < 4; nt++) {
                    mma16816(acc[mt][nt], ah[mt][0], ah[mt][1], ah[mt][2], ah[mt][3],
                             bhf[nt][0], bhf[nt][1]);
                    mma16816(acc[mt][nt], al[mt][0], al[mt][1], al[mt][2], al[mt][3],
                             bhf[nt][0], bhf[nt][1]);
                    mma16816(acc[mt][nt], ah[mt][0], ah[mt][1], ah[mt][2], ah[mt][3],
                             blf[nt][0], blf[nt][1]);
                }
        }
        if (c + 1 < NCHUNK)
            asm volatile("cp.async.wait_group 0;" ::: "memory");
        __syncthreads();
    }

#pragma unroll
    for (int mt = 0; mt < 4; mt++) {
        int m1 = m0 + wm * 64 + mt * 16 + gID;
#pragma unroll
        for (int nt = 0; nt < 4; nt++) {
            int n = n0 + wn * 32 + nt * 8 + tg * 2;
            float b0v = bias[n], b1v = bias[n + 1];
            float* a = acc[mt][nt];
            if (scatter) {
                int bb = m1 >> 10, t = m1 & 1023, h = n >> 6, d = n & 63;
                *(float2*)&Cout[(((size_t)(bb * H_ + h)) * T_ + t) * DH_ + d] =
                    make_float2(a[0] + b0v, a[1] + b1v);
                int m2 = m1 + 8;
                int bb2 = m2 >> 10, t2 = m2 & 1023;
                *(float2*)&Cout[(((size_t)(bb2 * H_ + h)) * T_ + t2) * DH_ + d] =
                    make_float2(a[2] + b0v, a[3] + b1v);
            } else {
                *(float2*)&Cout[(size_t)m1 * C_ + n] = make_float2(a[0] + b0v, a[1] + b1v);
                *(float2*)&Cout[(size_t)(m1 + 8) * C_ + n] = make_float2(a[2] + b0v, a[3] + b1v);
            }
        }
    }
}

// ---------------- q GEMM (exact 3-term split + chunked TwoSum): 64x128 ----------------
#define QTILE_B  5120
#define QSTAGE_B 25600
#define QNCH     32

__device__ __forceinline__ void qload_chunk_async(
    uint32_t sbase,
    const __nv_bfloat16* __restrict__ X1, const __nv_bfloat16* __restrict__ X2,
    const __nv_bfloat16* __restrict__ X3, const __nv_bfloat16* __restrict__ Ws,
    int m0, int n0, int k0, int tid)
{
#pragma unroll
    for (int i = 0; i < 5; i++) {
        int u = tid + i * 256;
        const __nv_bfloat16* g;
        uint32_t dst;
        if (u < 768) {
            int term = u >> 8;
            int idx = u & 255;
            int row = idx >> 2, jj = idx & 3;
            const __nv_bfloat16* base = (term == 0) ? X1 : (term == 1) ? X2 : X3;
            g = base + (size_t)(m0 + row) * C_ + k0 + jj * 8;
            dst = sbase + term * QTILE_B + row * 80 + jj * 16;
        } else {
            int v = u - 768;
            int row = v >> 2, jj = v & 3;
            g = Ws + (size_t)(n0 + row) * C_ + k0 + jj * 8;
            dst = sbase + 3 * QTILE_B + row * 80 + jj * 16;
        }
        asm volatile("cp.async.cg.shared.global [%0], [%1], 16;" :: "r"(dst), "l"(g));
    }
}

__global__ __launch_bounds__(256) void qgemm_mma(
    const __nv_bfloat16* __restrict__ X1, const __nv_bfloat16* __restrict__ X2,
    const __nv_bfloat16* __restrict__ X3, const __nv_bfloat16* __restrict__ Ws,
    const float* __restrict__ bias, float* __restrict__ Q)
{
    extern __shared__ char smc[];
    const int tid = threadIdx.x;
    const int lane = tid & 31, wid = tid >> 5;
    const int wm = wid >> 2, wn = wid & 3;
    const int gID = lane >> 2, tg = lane & 3;
    const int m0 = blockIdx.y * 64, n0 = blockIdx.x * 128;
    uint32_t sbase = (uint32_t)__cvta_generic_to_shared(smc);

    float s_[2][4][4], c_[2][4][4];
#pragma unroll
    for (int mt = 0; mt < 2; mt++)
#pragma unroll
        for (int nt = 0; nt < 4; nt++)
#pragma unroll
            for (int r = 0; r < 4; r++) { s_[mt][nt][r] = 0.f; c_[mt][nt][r] = 0.f; }

    qload_chunk_async(sbase, X1, X2, X3, Ws, m0, n0, 0, tid);
    asm volatile("cp.async.commit_group;" ::: "memory");
    asm volatile("cp.async.wait_group 0;" ::: "memory");
    __syncthreads();

    for (int c = 0; c < QNCH; c++) {
        if (c + 1 < QNCH) {
            qload_chunk_async(sbase + ((c + 1) & 1) * QSTAGE_B,
                              X1, X2, X3, Ws, m0, n0, (c + 1) * 32, tid);
            asm volatile("cp.async.commit_group;" ::: "memory");
        }
        const char* st = smc + (c & 1) * QSTAGE_B;

        float tacc[2][4][4];
#pragma unroll
        for (int mt = 0; mt < 2; mt++)
#pragma unroll
            for (int nt = 0; nt < 4; nt++)
#pragma unroll
                for (int r = 0; r < 4; r++) tacc[mt][nt][r] = 0.f;

#pragma unroll
        for (int ks = 0; ks < 2; ks++) {
            const int acol = ks * 32 + tg * 4;
            uint32_t bw[4][2];
#pragma unroll
            for (int nt = 0; nt < 4; nt++) {
                int ro = (wn * 32 + nt * 8 + gID) * 80 + acol;
                bw[nt][0] = *(const uint32_t*)(st + 3 * QTILE_B + ro);
                bw[nt][1] = *(const uint32_t*)(st + 3 * QTILE_B + ro + 16);
            }
#pragma unroll
            for (int term = 0; term < 3; term++) {
                const char* at = st + term * QTILE_B;
                uint32_t ah[2][4];
#pragma unroll
                for (int mt = 0; mt < 2; mt++) {
                    int ro = (wm * 32 + mt * 16 + gID) * 80 + acol;
                    ah[mt][0] = *(const uint32_t*)(at + ro);
                    ah[mt][1] = *(const uint32_t*)(at + ro + 640);
                    ah[mt][2] = *(const uint32_t*)(at + ro + 16);
                    ah[mt][3] = *(const uint32_t*)(at + ro + 656);
                }
#pragma unroll
                for (int mt = 0; mt < 2; mt++)
#pragma unroll
                    for (int nt = 0; nt < 4; nt++)
                        mma16816(tacc[mt][nt], ah[mt][0], ah[mt][1], ah[mt][2], ah[mt][3],
                                 bw[nt][0], bw[nt][1]);
            }
        }
#pragma unroll
        for (int mt = 0; mt < 2; mt++)
#pragma unroll
            for (int nt = 0; nt < 4; nt++)
#pragma unroll
                for (int r = 0; r < 4; r++)
                    twosum(s_[mt][nt][r], c_[mt][nt][r], tacc[mt][nt][r]);

        if (c + 1 < QNCH)
            asm volatile("cp.async.wait_group 0;" ::: "memory");
        __syncthreads();
    }

#pragma unroll
    for (int mt = 0; mt < 2; mt++) {
        int m1 = m0 + wm * 32 + mt * 16 + gID;
#pragma unroll
        for (int nt = 0; nt < 4; nt++) {
            int n = n0 + wn * 32 + nt * 8 + tg * 2;
            int h = n >> 6, d = n & 63;
            float b0v = bias[n], b1v = bias[n + 1];
            float v0 = __fadd_rn(__fadd_rn(s_[mt][nt][0], c_[mt][nt][0]), b0v);
            float v1 = __fadd_rn(__fadd_rn(s_[mt][nt][1], c_[mt][nt][1]), b1v);
            float v2 = __fadd_rn(__fadd_rn(s_[mt][nt][2], c_[mt][nt][2]), b0v);
            float v3 = __fadd_rn(__fadd_rn(s_[mt][nt][3], c_[mt][nt][3]), b1v);
            int bb = m1 >> 10, t = m1 & 1023;
            *(float2*)&Q[(((size_t)(bb * H_ + h)) * T_ + t) * DH_ + d] = make_float2(v0, v1);
            int m2 = m1 + 8;
            int bb2 = m2 >> 10, t2 = m2 & 1023;
            *(float2*)&Q[(((size_t)(bb2 * H_ + h)) * T_ + t2) * DH_ + d] = make_float2(v2, v3);
        }
    }
}

// -------------- q post: RMS norm + exact top-k, emits bf16 split --------------
__global__ __launch_bounds__(256) void qpost(
    const float* __restrict__ q,
    __nv_bfloat16* __restrict__ qh, __nv_bfloat16* __restrict__ ql)
{
    int grp = threadIdx.x >> 6;
    int lane = threadIdx.x & 63;
    int row = blockIdx.x * 4 + grp;
    float v = q[(size_t)row * 64 + lane];
    float ss = v * v;
#pragma unroll
    for (int o = 16; o > 0; o >>= 1) ss += __shfl_xor_sync(0xffffffffu, ss, o);
    __shared__ float ws[8];
    if ((threadIdx.x & 31) == 0) ws[threadIdx.x >> 5] = ss;
    __syncthreads();
    float rms = sqrtf((ws[grp * 2] + ws[grp * 2 + 1]) * (1.f / 64.f)) + 1e-6f;
    float vn = v / rms;
    float a = fabsf(vn);
    __shared__ __align__(16) float sa[4][64];
    sa[grp][lane] = a;
    __syncthreads();
    int g = 0;
    const float4* sv = (const float4*)sa[grp];
#pragma unroll
    for (int j = 0; j < 16; j++) {
        float4 t = sv[j];
        g += (t.x > a) + (t.y > a) + (t.z > a) + (t.w > a);
    }
    int h = (row >> 10) & 15;
    int kc = KEEPC[h];
    float cand = (g <= kc - 1) ? a : INFINITY;
#pragma unroll
    for (int o = 16; o > 0; o >>= 1)
        cand = fminf(cand, __shfl_xor_sync(0xffffffffu, cand, o));
    __shared__ float wm_[8];
    if ((threadIdx.x & 31) == 0) wm_[threadIdx.x >> 5] = cand;
    __syncthreads();
    float th = fminf(wm_[grp * 2], wm_[grp * 2 + 1]);
    float vnm = (a >= th) ? vn : 0.f;
    __nv_bfloat16 hh = __float2bfloat16(vnm);
    qh[(size_t)row * 64 + lane] = hh;
    ql[(size_t)row * 64 + lane] = __float2bfloat16(vnm - __bfloat162float(hh));
}

// -------------- k RMS norm, emits bf16 split --------------
__global__ void knorm(const float* __restrict__ k,
                      __nv_bfloat16* __restrict__ kh, __nv_bfloat16* __restrict__ kl)
{
    int lane = threadIdx.x & 63;
    int row = blockIdx.x * 4 + (threadIdx.x >> 6);
    float v = k[(size_t)row * 64 + lane];
    float ss = v * v;
#pragma unroll
    for (int o = 16; o > 0; o >>= 1) ss += __shfl_xor_sync(0xffffffffu, ss, o);
    __shared__ float ws[8];
    if ((threadIdx.x & 31) == 0) ws[threadIdx.x >> 5] = ss;
    __syncthreads();
    int grp = threadIdx.x >> 6;
    float tot = ws[grp * 2] + ws[grp * 2 + 1];
    float rms = sqrtf(tot * (1.f / 64.f)) + 1e-6f;
    float kn = v / rms;
    __nv_bfloat16 hh = __float2bfloat16(kn);
    kh[(size_t)row * 64 + lane] = hh;
    kl[(size_t)row * 64 + lane] = __float2bfloat16(kn - __bfloat162float(hh));
}

// -------------- V split + transpose: (bh,t,d) fp32 -> (bh,d,t) bf16 hi/lo --------------
__global__ __launch_bounds__(256) void vsplitT(
    const float* __restrict__ v,
    __nv_bfloat16* __restrict__ vth, __nv_bfloat16* __restrict__ vtl)
{
    __shared__ float s[64][65];
    const int tt = blockIdx.x, bh = blockIdx.y;
    const int t0 = tt * 64;
    const float* vb = v + (size_t)bh * T_ * 64;
    int tid = threadIdx.x;
#pragma unroll
    for (int i = 0; i < 4; i++) {
        int u = tid + i * 256;           // 0..1023: 64 rows x 16 float4
        int r = u >> 4, c4 = (u & 15) * 4;
        float4 val = *(const float4*)(vb + (size_t)(t0 + r) * 64 + c4);
        s[r][c4] = val.x; s[r][c4 + 1] = val.y; s[r][c4 + 2] = val.z; s[r][c4 + 3] = val.w;
    }
    __syncthreads();
    __nv_bfloat16* oh = vth + (size_t)bh * 64 * T_ + t0;
    __nv_bfloat16* ol = vtl + (size_t)bh * 64 * T_ + t0;
#pragma unroll
    for (int i = 0; i < 2; i++) {
        int u = tid + i * 256;           // 0..511: 64 d x 8 chunks
        int d = u >> 3, c8 = (u & 7) * 8;
        ushort4 Hv[2], Lv[2];
        unsigned short* hp = &Hv[0].x;
        unsigned short* lp = &Lv[0].x;
#pragma unroll
        for (int j = 0; j < 8; j++) {
            float x = s[c8 + j][d];
            __nv_bfloat16 hh = __float2bfloat16(x);
            hp[j] = __bfloat16_as_ushort(hh);
            lp[j] = __bfloat16_as_ushort(__float2bfloat16(x - __bfloat162float(hh)));
        }
        *(ushort4*)(oh + (size_t)d * T_ + c8) = Hv[0];
        *(ushort4*)(oh + (size_t)d * T_ + c8 + 4) = Hv[1];
        *(ushort4*)(ol + (size_t)d * T_ + c8) = Lv[0];
        *(ushort4*)(ol + (size_t)d * T_ + c8 + 4) = Lv[1];
    }
}

// -------------- MMA flash attention --------------
#define APAD_B 144
#define ATS 9216
#define ATT_SMEM (2 * ATS + 2 * 4 * ATS)   // 92160

__device__ __forceinline__ void att_kvload(
    uint32_t sb, int s, int kt, size_t hoff, int tid,
    const __nv_bfloat16* __restrict__ kh_g, const __nv_bfloat16* __restrict__ kl_g,
    const __nv_bfloat16* __restrict__ vth_g, const __nv_bfloat16* __restrict__ vtl_g)
{
    uint32_t st = sb + 2 * ATS + s * 4 * ATS;
#pragma unroll
    for (int i = 0; i < 16; i++) {
        int u = tid + i * 128;
        int t = u >> 9, row = (u >> 3) & 63, c = u & 7;
        const __nv_bfloat16* src;
        if (t == 0)      src = kh_g + hoff + (size_t)(kt * 64 + row) * 64 + c * 8;
        else if (t == 1) src = kl_g + hoff + (size_t)(kt * 64 + row) * 64 + c * 8;
        else if (t == 2) src = vth_g + hoff + (size_t)row * T_ + kt * 64 + c * 8;
        else             src = vtl_g + hoff + (size_t)row * T_ + kt * 64 + c * 8;
        uint32_t dst = st + t * ATS + row * APAD_B + c * 16;
        asm volatile("cp.async.cg.shared.global [%0], [%1], 16;" :: "r"(dst), "l"(src));
    }
}

__global__ __launch_bounds__(128) void attn_mma(
    const __nv_bfloat16* __restrict__ qh_g, const __nv_bfloat16* __restrict__ ql_g,
    const __nv_bfloat16* __restrict__ kh_g, const __nv_bfloat16* __restrict__ kl_g,
    const __nv_bfloat16* __restrict__ vth_g, const __nv_bfloat16* __restrict__ vtl_g,
    float* __restrict__ ao, float* __restrict__ gepart)
{
    extern __shared__ char smr[];
    __shared__ float red[128];
    const int qt = blockIdx.x, bh = blockIdx.y, q0 = qt * 64;
    const int tid = threadIdx.x, lane = tid & 31, w = tid >> 5;
    const int gID = lane >> 2, tg = lane & 3;
    uint32_t sb = (uint32_t)__cvta_generic_to_shared(smr);
    const size_t hoff = (size_t)bh * (T_ * 64);

    // Q tiles (hi/lo)
#pragma unroll
    for (int i = 0; i < 8; i++) {
        int u = tid + i * 128;
        int t = u >> 9, row = (u >> 3) & 63, c = u & 7;
        const __nv_bfloat16* src = (t ? ql_g : qh_g) + hoff + (size_t)(q0 + row) * 64 + c * 8;
        uint32_t dst = sb + t * ATS + row * APAD_B + c * 16;
        asm volatile("cp.async.cg.shared.global [%0], [%1], 16;" :: "r"(dst), "l"(src));
    }
    att_kvload(sb, 0, 0, hoff, tid, kh_g, kl_g, vth_g, vtl_g);
    asm volatile("cp.async.commit_group;" ::: "memory");
    asm volatile("cp.async.wait_group 0;" ::: "memory");
    __syncthreads();

    float oacc[8][4];
#pragma unroll
    for (int nt = 0; nt < 8; nt++)
#pragma unroll
        for (int r = 0; r < 4; r++) oacc[nt][r] = 0.f;
    float mrow[2] = {-1e30f, -1e30f}, lrow[2] = {0.f, 0.f}, erow[2] = {0.f, 0.f};

    for (int kt = 0; kt <= qt; kt++) {
        if (kt < qt) {
            att_kvload(sb, (kt + 1) & 1, kt + 1, hoff, tid, kh_g, kl_g, vth_g, vtl_g);
            asm volatile("cp.async.commit_group;" ::: "memory");
        }
        uint32_t st = sb + 2 * ATS + (kt & 1) * 4 * ATS;

        float sacc[8][4];
#pragma unroll
        for (int nt = 0; nt < 8; nt++)
#pragma unroll
            for (int r = 0; r < 4; r++) sacc[nt][r] = 0.f;

#pragma unroll
        for (int ks = 0; ks < 4; ks++) {
            uint32_t aoff = sb + (w * 16 + gID) * APAD_B + (ks * 16 + tg * 2) * 2;
            uint32_t qh0 = *(const uint32_t*)(smr + (aoff - sb));
            uint32_t qh2 = *(const uint32_t*)(smr + (aoff - sb) + 16);
            uint32_t qh1 = *(const uint32_t*)(smr + (aoff - sb) + 8 * APAD_B);
            uint32_t qh3 = *(const uint32_t*)(smr + (aoff - sb) + 8 * APAD_B + 16);
            uint32_t ql0 = *(const uint32_t*)(smr + (aoff - sb) + ATS);
            uint32_t ql2 = *(const uint32_t*)(smr + (aoff - sb) + ATS + 16);
            uint32_t ql1 = *(const uint32_t*)(smr + (aoff - sb) + ATS + 8 * APAD_B);
            uint32_t ql3 = *(const uint32_t*)(smr + (aoff - sb) + ATS + 8 * APAD_B + 16);
#pragma unroll
            for (int nt = 0; nt < 8; nt++) {
                uint32_t bo = (st - sb) + (nt * 8 + gID) * APAD_B + (ks * 16 + tg * 2) * 2;
                uint32_t kb0 = *(const uint32_t*)(smr + bo);
                uint32_t kb1 = *(const uint32_t*)(smr + bo + 16);
                uint32_t kl0 = *(const uint32_t*)(smr + bo + ATS);
                uint32_t kl1 = *(const uint32_t*)(smr + bo + ATS + 16);
                mma16816(sacc[nt], qh0, qh1, qh2, qh3, kb0, kb1);
                mma16816(sacc[nt], ql0, ql1, ql2, ql3, kb0, kb1);
                mma16816(sacc[nt], qh0, qh1, qh2, qh3, kl0, kl1);
            }
        }

        if (kt == qt) {
            int r0 = w * 16 + gID, r1 = r0 + 8;
#pragma unroll
            for (int nt = 0; nt < 8; nt++) {
                int c0 = nt * 8 + tg * 2, c1 = c0 + 1;
                if (c0 > r0) sacc[nt][0] = -1e30f;
                if (c1 > r0) sacc[nt][1] = -1e30f;
                if (c0 > r1) sacc[nt][2] = -1e30f;
                if (c1 > r1) sacc[nt][3] = -1e30f;
            }
        }

#pragma unroll
        for (int r = 0; r < 2; r++) {
            float tm = -1e30f;
#pragma unroll
            for (int nt = 0; nt < 8; nt++)
                tm = fmaxf(tm, fmaxf(sacc[nt][2 * r], sacc[nt][2 * r + 1]));
            tm = fmaxf(tm, __shfl_xor_sync(0xffffffffu, tm, 1));
            tm = fmaxf(tm, __shfl_xor_sync(0xffffffffu, tm, 2));
            float mn = fmaxf(mrow[r], tm);
            float sc = fast_exp(mrow[r] - mn);
            mrow[r] = mn;
            float se = 0.f, s2 = 0.f;
#pragma unroll
            for (int nt = 0; nt < 8; nt++) {
                float p0 = fast_exp(sacc[nt][2 * r] - mn);
                float p1 = fast_exp(sacc[nt][2 * r + 1] - mn);
                sacc[nt][2 * r] = p0; sacc[nt][2 * r + 1] = p1;
                se += p0 + p1;
                s2 += p0 * p0 + p1 * p1;
            }
            se += __shfl_xor_sync(0xffffffffu, se, 1);
            se += __shfl_xor_sync(0xffffffffu, se, 2);
            s2 += __shfl_xor_sync(0xffffffffu, s2, 1);
            s2 += __shfl_xor_sync(0xffffffffu, s2, 2);
            lrow[r] = lrow[r] * sc + se;
            erow[r] = erow[r] * sc * sc + s2;
#pragma unroll
            for (int nt = 0; nt < 8; nt++) {
                oacc[nt][2 * r] *= sc;
                oacc[nt][2 * r + 1] *= sc;
            }
        }

        // PV
#pragma unroll
        for (int ks = 0; ks < 4; ks++) {
            float* pa = sacc[2 * ks];
            float* pb = sacc[2 * ks + 1];
            uint32_t ph[4], pl[4];
            float hx, hy;
            ph[0] = pack_bf16x2(pa[0], pa[1]);
            hx = __bfloat162float(__float2bfloat16(pa[0]));
            hy = __bfloat162float(__float2bfloat16(pa[1]));
            pl[0] = pack_bf16x2(pa[0] - hx, pa[1] - hy);
            ph[1] = pack_bf16x2(pa[2], pa[3]);
            hx = __bfloat162float(__float2bfloat16(pa[2]));
            hy = __bfloat162float(__float2bfloat16(pa[3]));
            pl[1] = pack_bf16x2(pa[2] - hx, pa[3] - hy);
            ph[2] = pack_bf16x2(pb[0], pb[1]);
            hx = __bfloat162float(__float2bfloat16(pb[0]));
            hy = __bfloat162float(__float2bfloat16(pb[1]));
            pl[2] = pack_bf16x2(pb[0] - hx, pb[1] - hy);
            ph[3] = pack_bf16x2(pb[2], pb[3]);
            hx = __bfloat162float(__float2bfloat16(pb[2]));
            hy = __bfloat162float(__float2bfloat16(pb[3]));
            pl[3] = pack_bf16x2(pb[2] - hx, pb[3] - hy);
#pragma unroll
            for (int nt = 0; nt < 8; nt++) {
                uint32_t bo = (st - sb) + 2 * ATS + (nt * 8 + gID) * APAD_B + (ks * 16 + tg * 2) * 2;
                uint32_t vh0 = *(const uint32_t*)(smr + bo);
                uint32_t vh1 = *(const uint32_t*)(smr + bo + 16);
                uint32_t vl0 = *(const uint32_t*)(smr + bo + ATS);
                uint32_t vl1 = *(const uint32_t*)(smr + bo + ATS + 16);
                mma16816(oacc[nt], ph[0], ph[1], ph[2], ph[3], vh0, vh1);
                mma16816(oacc[nt], pl[0], pl[1], pl[2], pl[3], vh0, vh1);
                mma16816(oacc[nt], ph[0], ph[1], ph[2], ph[3], vl0, vl1);
            }
        }

        asm volatile("cp.async.wait_group 0;" ::: "memory");
        __syncthreads();
    }

    // epilogue
    float linv0 = 1.f / lrow[0], linv1 = 1.f / lrow[1];
    int r0 = w * 16 + gID, r1 = r0 + 8;
    int b = bh >> 4, h = bh & 15;
    float* ar0 = ao + (size_t)(b * T_ + q0 + r0) * C_ + h * DH_;
    float* ar1 = ao + (size_t)(b * T_ + q0 + r1) * C_ + h * DH_;
#pragma unroll
    for (int nt = 0; nt < 8; nt++) {
        *(float2*)&ar0[nt * 8 + tg * 2] = make_float2(oacc[nt][0] * linv0, oacc[nt][1] * linv0);
        *(float2*)&ar1[nt * 8 + tg * 2] = make_float2(oacc[nt][2] * linv1, oacc[nt][3] * linv1);
    }

    red[tid] = (tg == 0) ? (erow[0] * linv0 * linv0 + erow[1] * linv1 * linv1) : 0.f;
    __syncthreads();
    for (int o = 64; o > 0; o >>= 1) {
        if (tid < o) red[tid] += red[tid + o];
        __syncthreads();
    }
    if (tid == 0) gepart[bh * 16 + qt] = red[0];
}

// -------------- head energy -> entropy -> adaptive head mask --------------
__global__ void headmask(const float* __restrict__ epart, float* __restrict__ maskout)
{
    __shared__ double e[64];
    __shared__ double cand[64];
    int t = threadIdx.x;
    double s = 0.0;
    for (int i = 0; i < 16; i++) s += (double)epart[t * 16 + i];
    e[t] = s / 1048576.0;
    __syncthreads();
    int b = t >> 4;
    double m = -1e300;
    for (int j = 0; j < 16; j++) m = fmax(m, e[b * 16 + j]);
    double Z = 0.0;
    for (int j = 0; j < 16; j++) Z += exp(e[b * 16 + j] - m);
    double ent = 0.0;
    for (int j = 0; j < 16; j++) {
        double p = exp(e[b * 16 + j] - m) / Z;
        ent -= p * log(p + 1e-9);
    }
    double entn = fmin(fmax(ent / log(16.0), 0.0), 1.0);
    int keep = (int)rint(2.0 + entn * 4.0);
    double eh = e[t];
    int g = 0;
    for (int j = 0; j < 16; j++) g += (e[b * 16 + j] > eh);
    cand[t] = (g <= keep - 1) ? eh : 1e300;
    __syncthreads();
    double th = 1e300;
    for (int j = 0; j < 16; j++) th = fmin(th, cand[b * 16 + j]);
    maskout[t] = (eh >= th) ? 1.f : 0.f;
}

// ---------------- launch ----------------
extern "C" void kernel_launch(void* const* d_in, const int* in_sizes, int n_in,
                              void* d_out, int out_size)
{
    const float* x  = (const float*)d_in[0];
    const float* qw = (const float*)d_in[1];
    const float* qb = (const float*)d_in[2];
    const float* kw = (const float*)d_in[3];
    const float* kb = (const float*)d_in[4];
    const float* vw = (const float*)d_in[5];
    const float* vb = (const float*)d_in[6];
    const float* ow = (const float*)d_in[7];
    const float* ob = (const float*)d_in[8];
    float* out = (float*)d_out;

    float *gq, *gk, *gv, *gep, *gm, *gao;
    cudaGetSymbolAddress((void**)&gq, g_q);
    cudaGetSymbolAddress((void**)&gk, g_k);
    cudaGetSymbolAddress((void**)&gv, g_v);
    cudaGetSymbolAddress((void**)&gep, g_epart);
    cudaGetSymbolAddress((void**)&gm, g_mask);
    cudaGetSymbolAddress((void**)&gao, g_ao);

    __nv_bfloat16 *xh, *xl, *x3, *qws, *kwh, *kwl, *vwh, *vwl, *owh, *owl, *aoh, *aol;
    __nv_bfloat16 *qsh, *qsl, *ksh, *ksl, *vth, *vtl;
    cudaGetSymbolAddress((void**)&xh, g_xh);   cudaGetSymbolAddress((void**)&xl, g_xl);
    cudaGetSymbolAddress((void**)&x3, g_x3);   cudaGetSymbolAddress((void**)&qws, g_qws);
    cudaGetSymbolAddress((void**)&kwh, g_kwh); cudaGetSymbolAddress((void**)&kwl, g_kwl);
    cudaGetSymbolAddress((void**)&vwh, g_vwh); cudaGetSymbolAddress((void**)&vwl, g_vwl);
    cudaGetSymbolAddress((void**)&owh, g_owh); cudaGetSymbolAddress((void**)&owl, g_owl);
    cudaGetSymbolAddress((void**)&aoh, g_aoh); cudaGetSymbolAddress((void**)&aol, g_aol);
    cudaGetSymbolAddress((void**)&qsh, g_qsh); cudaGetSymbolAddress((void**)&qsl, g_qsl);
    cudaGetSymbolAddress((void**)&ksh, g_ksh); cudaGetSymbolAddress((void**)&ksl, g_ksl);
    cudaGetSymbolAddress((void**)&vth, g_vth); cudaGetSymbolAddress((void**)&vtl, g_vtl);

    cudaFuncSetAttribute((const void*)gemm_mma,
                         cudaFuncAttributeMaxDynamicSharedMemorySize, 2 * STAGE_B);
    cudaFuncSetAttribute((const void*)qgemm_mma,
                         cudaFuncAttributeMaxDynamicSharedMemorySize, 2 * QSTAGE_B);
    cudaFuncSetAttribute((const void*)attn_mma,
                         cudaFuncAttributeMaxDynamicSharedMemorySize, ATT_SMEM);

    // splits
    split3x<<<M_ * C_ / 1024, 256>>>((const float4*)x, (ushort4*)xh, (ushort4*)xl, (ushort4*)x3);
    signw_bf16<<<C_ * C_ / 1024, 256>>>((const float4*)qw, (ushort4*)qws);
    split2k<<<C_ * C_ / 1024, 256>>>((const float4*)kw, (ushort4*)kwh, (ushort4*)kwl);
    split2k<<<C_ * C_ / 1024, 256>>>((const float4*)vw, (ushort4*)vwh, (ushort4*)vwl);
    split2k<<<C_ * C_ / 1024, 256>>>((const float4*)ow, (ushort4*)owh, (ushort4*)owl);

    // projections
    qgemm_mma<<<dim3(C_ / 128, M_ / 64), 256, 2 * QSTAGE_B>>>(xh, xl, x3, qws, qb, gq);
    dim3 tGrid(C_ / 128, M_ / 128);
    gemm_mma<<<tGrid, 256, 2 * STAGE_B>>>(xh, xl, kwh, kwl, kb, gk, 1);
    gemm_mma<<<tGrid, 256, 2 * STAGE_B>>>(xh, xl, vwh, vwl, vb, gv, 1);

    qpost<<<BH_ * T_ / 4, 256>>>(gq, qsh, qsl);
    knorm<<<BH_ * T_ / 4, 256>>>(gk, ksh, ksl);
    vsplitT<<<dim3(16, BH_), 256>>>(gv, vth, vtl);

    attn_mma<<<dim3(16, BH_), 128, ATT_SMEM>>>(qsh, qsl, ksh, ksl, vth, vtl, gao, gep);
    headmask<<<1, 64>>>(gep, gm);

    split_ao<<<M_ * C_ / 1024, 256>>>((const float4*)gao, gm, (ushort4*)aoh, (ushort4*)aol);
    gemm_mma<<<tGrid, 256, 2 * STAGE_B>>>(aoh, aol, owh, owl, ob, out, 0);
}

// round 8
// speedup vs baseline: 2.5428x; 1.0887x over previous
#include <cuda_runtime.h>
#include <cuda_bf16.h>
#include <math.h>
#include <stdint.h>

#define B_  4
#define T_  1024
#define C_  1024
#define H_  16
#define DH_ 64
#define BH_ 64            // B_*H_
#define M_  4096          // B_*T_

// ---------------- scratch (device globals: allocation-free) ----------------
__device__ float g_q[BH_ * T_ * DH_];       // fp32 q after projection
__device__ float g_k[BH_ * T_ * DH_];
__device__ float g_v[BH_ * T_ * DH_];
__device__ float g_epart[BH_ * 16];
__device__ float g_mask[BH_];
__device__ float g_ao[M_ * C_];

// bf16 split buffers
__device__ __nv_bfloat16 g_xh[M_ * C_],  g_xl[M_ * C_], g_x3[M_ * C_];
__device__ __nv_bfloat16 g_qws[C_ * C_];
__device__ __nv_bfloat16 g_kwh[C_ * C_], g_kwl[C_ * C_];
__device__ __nv_bfloat16 g_vwh[C_ * C_], g_vwl[C_ * C_];
__device__ __nv_bfloat16 g_owh[C_ * C_], g_owl[C_ * C_];
__device__ __nv_bfloat16 g_aoh[M_ * C_], g_aol[M_ * C_];
// attention operand splits
__device__ __nv_bfloat16 g_qsh[BH_ * T_ * DH_], g_qsl[BH_ * T_ * DH_];   // (bh,t,d)
__device__ __nv_bfloat16 g_ksh[BH_ * T_ * DH_], g_ksl[BH_ * T_ * DH_];   // (bh,t,d)
__device__ __nv_bfloat16 g_vth[BH_ * T_ * DH_], g_vtl[BH_ * T_ * DH_];   // (bh,d,t)

__constant__ int KEEPC[16] = {22,21,20,19,18,18,17,16,15,14,13,13,12,11,10,9};

// ---------------- helpers ----------------
__device__ __forceinline__ void twosum(float& s, float& c, float v) {
    float t  = __fadd_rn(s, v);
    float bo = __fsub_rn(t, s);
    float e1 = __fsub_rn(s, __fsub_rn(t, bo));
    float e2 = __fsub_rn(v, bo);
    c = __fadd_rn(c, __fadd_rn(e1, e2));
    s = t;
}

// fast exp (no MUFU): d <= 0, rel err ~2.4e-8
__device__ __forceinline__ float fast_exp(float d) {
    d = fmaxf(d, -80.f);
    float t = d * 1.4426950408889634f;
    float n = rintf(t);
    float f = fmaf(n, -0.693147182464599609375f, d);
    f = fmaf(n, 1.9046542999577680452e-9f, f);
    float p = 1.3888888888888889e-3f;
    p = fmaf(p, f, 8.3333333333333332e-3f);
    p = fmaf(p, f, 4.1666666666666664e-2f);
    p = fmaf(p, f, 1.6666666666666666e-1f);
    p = fmaf(p, f, 0.5f);
    p = fmaf(p, f, 1.0f);
    p = fmaf(p, f, 1.0f);
    int j = (int)n;
    return p * __uint_as_float((unsigned)(127 + j) << 23);
}

__device__ __forceinline__ uint32_t pack_bf16x2(float lo, float hi) {
    uint32_t r;
    asm("cvt.rn.bf16x2.f32 %0, %1, %2;" : "=r"(r) : "f"(hi), "f"(lo));
    return r;
}

__device__ __forceinline__ void mma16816(float* d,
    uint32_t a0, uint32_t a1, uint32_t a2, uint32_t a3,
    uint32_t b0, uint32_t b1)
{
    asm volatile(
        "mma.sync.aligned.m16n8k16.row.col.f32.bf16.bf16.f32 "
        "{%0,%1,%2,%3}, {%4,%5,%6,%7}, {%8,%9}, {%0,%1,%2,%3};"
        : "+f"(d[0]), "+f"(d[1]), "+f"(d[2]), "+f"(d[3])
        : "r"(a0), "r"(a1), "r"(a2), "r"(a3), "r"(b0), "r"(b1));
}

// ---------------- split kernels ----------------
__global__ void split3x(const float4* __restrict__ src, ushort4* __restrict__ o1,
                        ushort4* __restrict__ o2, ushort4* __restrict__ o3)
{
    int i = blockIdx.x * 256 + threadIdx.x;
    float4 v = src[i];
    float a[4] = {v.x, v.y, v.z, v.w};
    ushort4 H, L, T3;
    unsigned short* hp = &H.x; unsigned short* lp = &L.x; unsigned short* tp = &T3.x;
#pragma unroll
    for (int j = 0; j < 4; j++) {
        __nv_bfloat16 h = __float2bfloat16(a[j]);
        float r1 = a[j] - __bfloat162float(h);
        __nv_bfloat16 l = __float2bfloat16(r1);
        float r2 = r1 - __bfloat162float(l);
        tp[j] = __bfloat16_as_ushort(__float2bfloat16(r2));
        hp[j] = __bfloat16_as_ushort(h);
        lp[j] = __bfloat16_as_ushort(l);
    }
    o1[i] = H; o2[i] = L; o3[i] = T3;
}

__global__ void split2k(const float4* __restrict__ src, ushort4* __restrict__ hi,
                        ushort4* __restrict__ lo)
{
    int i = blockIdx.x * 256 + threadIdx.x;
    float4 v = src[i];
    float a[4] = {v.x, v.y, v.z, v.w};
    ushort4 H, L;
    unsigned short* hp = &H.x; unsigned short* lp = &L.x;
#pragma unroll
    for (int j = 0; j < 4; j++) {
        __nv_bfloat16 h = __float2bfloat16(a[j]);
        __nv_bfloat16 l = __float2bfloat16(a[j] - __bfloat162float(h));
        hp[j] = __bfloat16_as_ushort(h);
        lp[j] = __bfloat16_as_ushort(l);
    }
    hi[i] = H; lo[i] = L;
}

__global__ void signw_bf16(const float4* __restrict__ w, ushort4* __restrict__ out)
{
    int i = blockIdx.x * 256 + threadIdx.x;
    float4 v = w[i];
    ushort4 o;
    o.x = (v.x > 0.f) ? 0x3F80 : ((v.x < 0.f) ? 0xBF80 : 0);
    o.y = (v.y > 0.f) ? 0x3F80 : ((v.y < 0.f) ? 0xBF80 : 0);
    o.z = (v.z > 0.f) ? 0x3F80 : ((v.z < 0.f) ? 0xBF80 : 0);
    o.w = (v.w > 0.f) ? 0x3F80 : ((v.w < 0.f) ? 0xBF80 : 0);
    out[i] = o;
}

__global__ void split_ao(const float4* __restrict__ src, const float* __restrict__ mask,
                         ushort4* __restrict__ hi, ushort4* __restrict__ lo)
{
    int i = blockIdx.x * 256 + threadIdx.x;
    int e = i * 4;
    int m = e >> 10, n = e & 1023;
    float mk = mask[((m >> 10) << 4) + (n >> 6)];
    float4 v = src[i];
    v.x *= mk; v.y *= mk; v.z *= mk; v.w *= mk;
    float a[4] = {v.x, v.y, v.z, v.w};
    ushort4 H, L;
    unsigned short* hp = &H.x; unsigned short* lp = &L.x;
#pragma unroll
    for (int j = 0; j < 4; j++) {
        __nv_bfloat16 h = __float2bfloat16(a[j]);
        __nv_bfloat16 l = __float2bfloat16(a[j] - __bfloat162float(h));
        hp[j] = __bfloat16_as_ushort(h);
        lp[j] = __bfloat16_as_ushort(l);
    }
    hi[i] = H; lo[i] = L;
}

// ---------------- K/V/O GEMM (2-term split): 128x128, 8 warps ----------------
// maskp != nullptr: skip K-chunks whose head (chunk>>1) is masked off for this
// block's batch — bitwise identical (skipped chunks contribute exact zeros).
#define TILE_B   10240
#define STAGE_B  40960
#define NCHUNK   32

__device__ __forceinline__ void load_chunk_async(
    uint32_t sbase,
    const __nv_bfloat16* __restrict__ Ahi, const __nv_bfloat16* __restrict__ Alo,
    const __nv_bfloat16* __restrict__ Bhi, const __nv_bfloat16* __restrict__ Blo,
    int m0, int n0, int k0, int tid)
{
#pragma unroll
    for (int i = 0; i < 8; i++) {
        int u = tid + i * 256;
        int tile = u >> 9;
        int idx = u & 511;
        int row = idx >> 2;
        int jj = idx & 3;
        const __nv_bfloat16* g;
        if (tile == 0)      g = Ahi + (size_t)(m0 + row) * C_ + k0 + jj * 8;
        else if (tile == 1) g = Alo + (size_t)(m0 + row) * C_ + k0 + jj * 8;
        else if (tile == 2) g = Bhi + (size_t)(n0 + row) * C_ + k0 + jj * 8;
        else                g = Blo + (size_t)(n0 + row) * C_ + k0 + jj * 8;
        uint32_t dst = sbase + tile * TILE_B + row * 80 + jj * 16;
        asm volatile("cp.async.cg.shared.global [%0], [%1], 16;" :: "r"(dst), "l"(g));
    }
}

__global__ __launch_bounds__(256) void gemm_mma(
    const __nv_bfloat16* __restrict__ Ahi, const __nv_bfloat16* __restrict__ Alo,
    const __nv_bfloat16* __restrict__ Bhi, const __nv_bfloat16* __restrict__ Blo,
    const float* __restrict__ bias, float* __restrict__ Cout, int scatter,
    const float* __restrict__ maskp)
{
    extern __shared__ char smc[];
    const int tid = threadIdx.x;
    const int lane = tid & 31, wid = tid >> 5;
    const int wm = wid >> 2, wn = wid & 3;
    const int gID = lane >> 2, tg = lane & 3;
    const int m0 = blockIdx.y * 128, n0 = blockIdx.x * 128;
    uint32_t sbase = (uint32_t)__cvta_generic_to_shared(smc);

    // active chunk list (head mask for this block's batch)
    __shared__ int act[NCHUNK];
    __shared__ int s_na;
    if (tid == 0) {
        int n = 0;
        int b16 = (m0 >> 10) << 4;
        for (int ch = 0; ch < NCHUNK; ch++)
            if (!maskp || maskp[b16 + (ch >> 1)] != 0.f) act[n++] = ch;
        s_na = n;
    }
    __syncthreads();
    const int na = s_na;

    float acc[4][4][4];
#pragma unroll
    for (int mt = 0; mt < 4; mt++)
#pragma unroll
        for (int nt = 0; nt < 4; nt++)
#pragma unroll
            for (int r = 0; r < 4; r++) acc[mt][nt][r] = 0.f;

    load_chunk_async(sbase, Ahi, Alo, Bhi, Blo, m0, n0, act[0] * 32, tid);
    asm volatile("cp.async.commit_group;" ::: "memory");
    asm volatile("cp.async.wait_group 0;" ::: "memory");
    __syncthreads();

    for (int c = 0; c < na; c++) {
        if (c + 1 < na) {
            load_chunk_async(sbase + ((c + 1) & 1) * STAGE_B,
                             Ahi, Alo, Bhi, Blo, m0, n0, act[c + 1] * 32, tid);
            asm volatile("cp.async.commit_group;" ::: "memory");
        }
        const char* st = smc + (c & 1) * STAGE_B;
#pragma unroll
        for (int ks = 0; ks < 2; ks++) {
            const int acol = ks * 32 + tg * 4;
            uint32_t ah[4][4], al[4][4], bhf[4][2], blf[4][2];
#pragma unroll
            for (int nt = 0; nt < 4; nt++) {
                int ro = (wn * 32 + nt * 8 + gID) * 80 + acol;
                bhf[nt][0] = *(const uint32_t*)(st + 2 * TILE_B + ro);
                bhf[nt][1] = *(const uint32_t*)(st + 2 * TILE_B + ro + 16);
                blf[nt][0] = *(const uint32_t*)(st + 3 * TILE_B + ro);
                blf[nt][1] = *(const uint32_t*)(st + 3 * TILE_B + ro + 16);
            }
#pragma unroll
            for (int mt = 0; mt < 4; mt++) {
                int ro = (wm * 64 + mt * 16 + gID) * 80 + acol;
                ah[mt][0] = *(const uint32_t*)(st + ro);
                ah[mt][1] = *(const uint32_t*)(st + ro + 640);
                ah[mt][2] = *(const uint32_t*)(st + ro + 16);
                ah[mt][3] = *(const uint32_t*)(st + ro + 656);
                al[mt][0] = *(const uint32_t*)(st + TILE_B + ro);
                al[mt][1] = *(const uint32_t*)(st + TILE_B + ro + 640);
                al[mt][2] = *(const uint32_t*)(st + TILE_B + ro + 16);
                al[mt][3] = *(const uint32_t*)(st + TILE_B + ro + 656);
            }
#pragma unroll
            for (int mt = 0; mt < 4; mt++)
#pragma unroll
                for (int nt = 0; nt < 4; nt++) {
                    mma16816(acc[mt][nt], ah[mt][0], ah[mt][1], ah[mt][2], ah[mt][3],
                             bhf[nt][0], bhf[nt][1]);
                    mma16816(acc[mt][nt], al[mt][0], al[mt][1], al[mt][2], al[mt][3],
                             bhf[nt][0], bhf[nt][1]);
                    mma16816(acc[mt][nt], ah[mt][0], ah[mt][1], ah[mt][2], ah[mt][3],
                             blf[nt][0], blf[nt][1]);
                }
        }
        if (c + 1 < na)
            asm volatile("cp.async.wait_group 0;" ::: "memory");
        __syncthreads();
    }

#pragma unroll
    for (int mt = 0; mt < 4; mt++) {
        int m1 = m0 + wm * 64 + mt * 16 + gID;
#pragma unroll
        for (int nt = 0; nt < 4; nt++) {
            int n = n0 + wn * 32 + nt * 8 + tg * 2;
            float b0v = bias[n], b1v = bias[n + 1];
            float* a = acc[mt][nt];
            if (scatter) {
                int bb = m1 >> 10, t = m1 & 1023, h = n >> 6, d = n & 63;
                *(float2*)&Cout[(((size_t)(bb * H_ + h)) * T_ + t) * DH_ + d] =
                    make_float2(a[0] + b0v, a[1] + b1v);
                int m2 = m1 + 8;
                int bb2 = m2 >> 10, t2 = m2 & 1023;
                *(float2*)&Cout[(((size_t)(bb2 * H_ + h)) * T_ + t2) * DH_ + d] =
                    make_float2(a[2] + b0v, a[3] + b1v);
            } else {
                *(float2*)&Cout[(size_t)m1 * C_ + n] = make_float2(a[0] + b0v, a[1] + b1v);
                *(float2*)&Cout[(size_t)(m1 + 8) * C_ + n] = make_float2(a[2] + b0v, a[3] + b1v);
            }
        }
    }
}

// ---------------- q GEMM (exact 3-term split + chunked TwoSum): 64x128 ----------------
#define QTILE_B  5120
#define QSTAGE_B 25600
#define QNCH     32

__device__ __forceinline__ void qload_chunk_async(
    uint32_t sbase,
    const __nv_bfloat16* __restrict__ X1, const __nv_bfloat16* __restrict__ X2,
    const __nv_bfloat16* __restrict__ X3, const __nv_bfloat16* __restrict__ Ws,
    int m0, int n0, int k0, int tid)
{
#pragma unroll
    for (int i = 0; i < 5; i++) {
        int u = tid + i * 256;
        const __nv_bfloat16* g;
        uint32_t dst;
        if (u < 768) {
            int term = u >> 8;
            int idx = u & 255;
            int row = idx >> 2, jj = idx & 3;
            const __nv_bfloat16* base = (term == 0) ? X1 : (term == 1) ? X2 : X3;
            g = base + (size_t)(m0 + row) * C_ + k0 + jj * 8;
            dst = sbase + term * QTILE_B + row * 80 + jj * 16;
        } else {
            int v = u - 768;
            int row = v >> 2, jj = v & 3;
            g = Ws + (size_t)(n0 + row) * C_ + k0 + jj * 8;
            dst = sbase + 3 * QTILE_B + row * 80 + jj * 16;
        }
        asm volatile("cp.async.cg.shared.global [%0], [%1], 16;" :: "r"(dst), "l"(g));
    }
}

__global__ __launch_bounds__(256) void qgemm_mma(
    const __nv_bfloat16* __restrict__ X1, const __nv_bfloat16* __restrict__ X2,
    const __nv_bfloat16* __restrict__ X3, const __nv_bfloat16* __restrict__ Ws,
    const float* __restrict__ bias, float* __restrict__ Q)
{
    extern __shared__ char smc[];
    const int tid = threadIdx.x;
    const int lane = tid & 31, wid = tid >> 5;
    const int wm = wid >> 2, wn = wid & 3;
    const int gID = lane >> 2, tg = lane & 3;
    const int m0 = blockIdx.y * 64, n0 = blockIdx.x * 128;
    uint32_t sbase = (uint32_t)__cvta_generic_to_shared(smc);

    float s_[2][4][4], c_[2][4][4];
#pragma unroll
    for (int mt = 0; mt < 2; mt++)
#pragma unroll
        for (int nt = 0; nt < 4; nt++)
#pragma unroll
            for (int r = 0; r < 4; r++) { s_[mt][nt][r] = 0.f; c_[mt][nt][r] = 0.f; }

    qload_chunk_async(sbase, X1, X2, X3, Ws, m0, n0, 0, tid);
    asm volatile("cp.async.commit_group;" ::: "memory");
    asm volatile("cp.async.wait_group 0;" ::: "memory");
    __syncthreads();

    for (int c = 0; c < QNCH; c++) {
        if (c + 1 < QNCH) {
            qload_chunk_async(sbase + ((c + 1) & 1) * QSTAGE_B,
                              X1, X2, X3, Ws, m0, n0, (c + 1) * 32, tid);
            asm volatile("cp.async.commit_group;" ::: "memory");
        }
        const char* st = smc + (c & 1) * QSTAGE_B;

        float tacc[2][4][4];
#pragma unroll
        for (int mt = 0; mt < 2; mt++)
#pragma unroll
            for (int nt = 0; nt < 4; nt++)
#pragma unroll
                for (int r = 0; r < 4; r++) tacc[mt][nt][r] = 0.f;

#pragma unroll
        for (int ks = 0; ks < 2; ks++) {
            const int acol = ks * 32 + tg * 4;
            uint32_t bw[4][2];
#pragma unroll
            for (int nt = 0; nt < 4; nt++) {
                int ro = (wn * 32 + nt * 8 + gID) * 80 + acol;
                bw[nt][0] = *(const uint32_t*)(st + 3 * QTILE_B + ro);
                bw[nt][1] = *(const uint32_t*)(st + 3 * QTILE_B + ro + 16);
            }
#pragma unroll
            for (int term = 0; term < 3; term++) {
                const char* at = st + term * QTILE_B;
                uint32_t ah[2][4];
#pragma unroll
                for (int mt = 0; mt < 2; mt++) {
                    int ro = (wm * 32 + mt * 16 + gID) * 80 + acol;
                    ah[mt][0] = *(const uint32_t*)(at + ro);
                    ah[mt][1] = *(const uint32_t*)(at + ro + 640);
                    ah[mt][2] = *(const uint32_t*)(at + ro + 16);
                    ah[mt][3] = *(const uint32_t*)(at + ro + 656);
                }
#pragma unroll
                for (int mt = 0; mt < 2; mt++)
#pragma unroll
                    for (int nt = 0; nt < 4; nt++)
                        mma16816(tacc[mt][nt], ah[mt][0], ah[mt][1], ah[mt][2], ah[mt][3],
                                 bw[nt][0], bw[nt][1]);
            }
        }
#pragma unroll
        for (int mt = 0; mt < 2; mt++)
#pragma unroll
            for (int nt = 0; nt < 4; nt++)
#pragma unroll
                for (int r = 0; r < 4; r++)
                    twosum(s_[mt][nt][r], c_[mt][nt][r], tacc[mt][nt][r]);

        if (c + 1 < QNCH)
            asm volatile("cp.async.wait_group 0;" ::: "memory");
        __syncthreads();
    }

#pragma unroll
    for (int mt = 0; mt < 2; mt++) {
        int m1 = m0 + wm * 32 + mt * 16 + gID;
#pragma unroll
        for (int nt = 0; nt < 4; nt++) {
            int n = n0 + wn * 32 + nt * 8 + tg * 2;
            int h = n >> 6, d = n & 63;
            float b0v = bias[n], b1v = bias[n + 1];
            float v0 = __fadd_rn(__fadd_rn(s_[mt][nt][0], c_[mt][nt][0]), b0v);
            float v1 = __fadd_rn(__fadd_rn(s_[mt][nt][1], c_[mt][nt][1]), b1v);
            float v2 = __fadd_rn(__fadd_rn(s_[mt][nt][2], c_[mt][nt][2]), b0v);
            float v3 = __fadd_rn(__fadd_rn(s_[mt][nt][3], c_[mt][nt][3]), b1v);
            int bb = m1 >> 10, t = m1 & 1023;
            *(float2*)&Q[(((size_t)(bb * H_ + h)) * T_ + t) * DH_ + d] = make_float2(v0, v1);
            int m2 = m1 + 8;
            int bb2 = m2 >> 10, t2 = m2 & 1023;
            *(float2*)&Q[(((size_t)(bb2 * H_ + h)) * T_ + t2) * DH_ + d] = make_float2(v2, v3);
        }
    }
}

// -------------- q post: RMS norm + exact top-k, emits bf16 split --------------
__global__ __launch_bounds__(256) void qpost(
    const float* __restrict__ q,
    __nv_bfloat16* __restrict__ qh, __nv_bfloat16* __restrict__ ql)
{
    int grp = threadIdx.x >> 6;
    int lane = threadIdx.x & 63;
    int row = blockIdx.x * 4 + grp;
    float v = q[(size_t)row * 64 + lane];
    float ss = v * v;
#pragma unroll
    for (int o = 16; o > 0; o >>= 1) ss += __shfl_xor_sync(0xffffffffu, ss, o);
    __shared__ float ws[8];
    if ((threadIdx.x & 31) == 0) ws[threadIdx.x >> 5] = ss;
    __syncthreads();
    float rms = sqrtf((ws[grp * 2] + ws[grp * 2 + 1]) * (1.f / 64.f)) + 1e-6f;
    float vn = v / rms;
    float a = fabsf(vn);
    __shared__ __align__(16) float sa[4][64];
    sa[grp][lane] = a;
    __syncthreads();
    int g = 0;
    const float4* sv = (const float4*)sa[grp];
#pragma unroll
    for (int j = 0; j < 16; j++) {
        float4 t = sv[j];
        g += (t.x > a) + (t.y > a) + (t.z > a) + (t.w > a);
    }
    int h = (row >> 10) & 15;
    int kc = KEEPC[h];
    float cand = (g <= kc - 1) ? a : INFINITY;
#pragma unroll
    for (int o = 16; o > 0; o >>= 1)
        cand = fminf(cand, __shfl_xor_sync(0xffffffffu, cand, o));
    __shared__ float wm_[8];
    if ((threadIdx.x & 31) == 0) wm_[threadIdx.x >> 5] = cand;
    __syncthreads();
    float th = fminf(wm_[grp * 2], wm_[grp * 2 + 1]);
    float vnm = (a >= th) ? vn : 0.f;
    __nv_bfloat16 hh = __float2bfloat16(vnm);
    qh[(size_t)row * 64 + lane] = hh;
    ql[(size_t)row * 64 + lane] = __float2bfloat16(vnm - __bfloat162float(hh));
}

// -------------- k RMS norm, emits bf16 split --------------
__global__ void knorm(const float* __restrict__ k,
                      __nv_bfloat16* __restrict__ kh, __nv_bfloat16* __restrict__ kl)
{
    int lane = threadIdx.x & 63;
    int row = blockIdx.x * 4 + (threadIdx.x >> 6);
    float v = k[(size_t)row * 64 + lane];
    float ss = v * v;
#pragma unroll
    for (int o = 16; o > 0; o >>= 1) ss += __shfl_xor_sync(0xffffffffu, ss, o);
    __shared__ float ws[8];
    if ((threadIdx.x & 31) == 0) ws[threadIdx.x >> 5] = ss;
    __syncthreads();
    int grp = threadIdx.x >> 6;
    float tot = ws[grp * 2] + ws[grp * 2 + 1];
    float rms = sqrtf(tot * (1.f / 64.f)) + 1e-6f;
    float kn = v / rms;
    __nv_bfloat16 hh = __float2bfloat16(kn);
    kh[(size_t)row * 64 + lane] = hh;
    kl[(size_t)row * 64 + lane] = __float2bfloat16(kn - __bfloat162float(hh));
}

// -------------- V split + transpose: (bh,t,d) fp32 -> (bh,d,t) bf16 hi/lo --------------
__global__ __launch_bounds__(256) void vsplitT(
    const float* __restrict__ v,
    __nv_bfloat16* __restrict__ vth, __nv_bfloat16* __restrict__ vtl)
{
    __shared__ float s[64][65];
    const int tt = blockIdx.x, bh = blockIdx.y;
    const int t0 = tt * 64;
    const float* vb = v + (size_t)bh * T_ * 64;
    int tid = threadIdx.x;
#pragma unroll
    for (int i = 0; i < 4; i++) {
        int u = tid + i * 256;
        int r = u >> 4, c4 = (u & 15) * 4;
        float4 val = *(const float4*)(vb + (size_t)(t0 + r) * 64 + c4);
        s[r][c4] = val.x; s[r][c4 + 1] = val.y; s[r][c4 + 2] = val.z; s[r][c4 + 3] = val.w;
    }
    __syncthreads();
    __nv_bfloat16* oh = vth + (size_t)bh * 64 * T_ + t0;
    __nv_bfloat16* ol = vtl + (size_t)bh * 64 * T_ + t0;
#pragma unroll
    for (int i = 0; i < 2; i++) {
        int u = tid + i * 256;
        int d = u >> 3, c8 = (u & 7) * 8;
        ushort4 Hv[2], Lv[2];
        unsigned short* hp = &Hv[0].x;
        unsigned short* lp = &Lv[0].x;
#pragma unroll
        for (int j = 0; j < 8; j++) {
            float x = s[c8 + j][d];
            __nv_bfloat16 hh = __float2bfloat16(x);
            hp[j] = __bfloat16_as_ushort(hh);
            lp[j] = __bfloat16_as_ushort(__float2bfloat16(x - __bfloat162float(hh)));
        }
        *(ushort4*)(oh + (size_t)d * T_ + c8) = Hv[0];
        *(ushort4*)(oh + (size_t)d * T_ + c8 + 4) = Hv[1];
        *(ushort4*)(ol + (size_t)d * T_ + c8) = Lv[0];
        *(ushort4*)(ol + (size_t)d * T_ + c8 + 4) = Lv[1];
    }
}

// -------------- MMA flash attention --------------
#define APAD_B 144
#define ATS 9216
#define ATT_SMEM (2 * ATS + 2 * 4 * ATS)   // 92160

__device__ __forceinline__ void att_kvload(
    uint32_t sb, int s, int kt, size_t hoff, int tid,
    const __nv_bfloat16* __restrict__ kh_g, const __nv_bfloat16* __restrict__ kl_g,
    const __nv_bfloat16* __restrict__ vth_g, const __nv_bfloat16* __restrict__ vtl_g)
{
    uint32_t st = sb + 2 * ATS + s * 4 * ATS;
#pragma unroll
    for (int i = 0; i < 16; i++) {
        int u = tid + i * 128;
        int t = u >> 9, row = (u >> 3) & 63, c = u & 7;
        const __nv_bfloat16* src;
        if (t == 0)      src = kh_g + hoff + (size_t)(kt * 64 + row) * 64 + c * 8;
        else if (t == 1) src = kl_g + hoff + (size_t)(kt * 64 + row) * 64 + c * 8;
        else if (t == 2) src = vth_g + hoff + (size_t)row * T_ + kt * 64 + c * 8;
        else             src = vtl_g + hoff + (size_t)row * T_ + kt * 64 + c * 8;
        uint32_t dst = st + t * ATS + row * APAD_B + c * 16;
        asm volatile("cp.async.cg.shared.global [%0], [%1], 16;" :: "r"(dst), "l"(src));
    }
}

__global__ __launch_bounds__(128) void attn_mma(
    const __nv_bfloat16* __restrict__ qh_g, const __nv_bfloat16* __restrict__ ql_g,
    const __nv_bfloat16* __restrict__ kh_g, const __nv_bfloat16* __restrict__ kl_g,
    const __nv_bfloat16* __restrict__ vth_g, const __nv_bfloat16* __restrict__ vtl_g,
    float* __restrict__ ao, float* __restrict__ gepart)
{
    extern __shared__ char smr[];
    __shared__ float red[128];
    const int qt = (int)(gridDim.x - 1) - (int)blockIdx.x;   // heavy tiles first
    const int bh = blockIdx.y, q0 = qt * 64;
    const int tid = threadIdx.x, lane = tid & 31, w = tid >> 5;
    const int gID = lane >> 2, tg = lane & 3;
    uint32_t sb = (uint32_t)__cvta_generic_to_shared(smr);
    const size_t hoff = (size_t)bh * (T_ * 64);

    // Q tiles (hi/lo)
#pragma unroll
    for (int i = 0; i < 8; i++) {
        int u = tid + i * 128;
        int t = u >> 9, row = (u >> 3) & 63, c = u & 7;
        const __nv_bfloat16* src = (t ? ql_g : qh_g) + hoff + (size_t)(q0 + row) * 64 + c * 8;
        uint32_t dst = sb + t * ATS + row * APAD_B + c * 16;
        asm volatile("cp.async.cg.shared.global [%0], [%1], 16;" :: "r"(dst), "l"(src));
    }
    att_kvload(sb, 0, 0, hoff, tid, kh_g, kl_g, vth_g, vtl_g);
    asm volatile("cp.async.commit_group;" ::: "memory");
    asm volatile("cp.async.wait_group 0;" ::: "memory");
    __syncthreads();

    float oacc[8][4];
#pragma unroll
    for (int nt = 0; nt < 8; nt++)
#pragma unroll
        for (int r = 0; r < 4; r++) oacc[nt][r] = 0.f;
    float mrow[2] = {-1e30f, -1e30f}, lrow[2] = {0.f, 0.f}, erow[2] = {0.f, 0.f};

    for (int kt = 0; kt <= qt; kt++) {
        if (kt < qt) {
            att_kvload(sb, (kt + 1) & 1, kt + 1, hoff, tid, kh_g, kl_g, vth_g, vtl_g);
            asm volatile("cp.async.commit_group;" ::: "memory");
        }
        uint32_t st = sb + 2 * ATS + (kt & 1) * 4 * ATS;

        float sacc[8][4];
#pragma unroll
        for (int nt = 0; nt < 8; nt++)
#pragma unroll
            for (int r = 0; r < 4; r++) sacc[nt][r] = 0.f;

#pragma unroll
        for (int ks = 0; ks < 4; ks++) {
            uint32_t aoff = sb + (w * 16 + gID) * APAD_B + (ks * 16 + tg * 2) * 2;
            uint32_t qh0 = *(const uint32_t*)(smr + (aoff - sb));
            uint32_t qh2 = *(const uint32_t*)(smr + (aoff - sb) + 16);
            uint32_t qh1 = *(const uint32_t*)(smr + (aoff - sb) + 8 * APAD_B);
            uint32_t qh3 = *(const uint32_t*)(smr + (aoff - sb) + 8 * APAD_B + 16);
            uint32_t ql0 = *(const uint32_t*)(smr + (aoff - sb) + ATS);
            uint32_t ql2 = *(const uint32_t*)(smr + (aoff - sb) + ATS + 16);
            uint32_t ql1 = *(const uint32_t*)(smr + (aoff - sb) + ATS + 8 * APAD_B);
            uint32_t ql3 = *(const uint32_t*)(smr + (aoff - sb) + ATS + 8 * APAD_B + 16);
#pragma unroll
            for (int nt = 0; nt < 8; nt++) {
                uint32_t bo = (st - sb) + (nt * 8 + gID) * APAD_B + (ks * 16 + tg * 2) * 2;
                uint32_t kb0 = *(const uint32_t*)(smr + bo);
                uint32_t kb1 = *(const uint32_t*)(smr + bo + 16);
                uint32_t kl0 = *(const uint32_t*)(smr + bo + ATS);
                uint32_t kl1 = *(const uint32_t*)(smr + bo + ATS + 16);
                mma16816(sacc[nt], qh0, qh1, qh2, qh3, kb0, kb1);
                mma16816(sacc[nt], ql0, ql1, ql2, ql3, kb0, kb1);
                mma16816(sacc[nt], qh0, qh1, qh2, qh3, kl0, kl1);
            }
        }

        if (kt == qt) {
            int r0 = w * 16 + gID, r1 = r0 + 8;
#pragma unroll
            for (int nt = 0; nt < 8; nt++) {
                int c0 = nt * 8 + tg * 2, c1 = c0 + 1;
                if (c0 > r0) sacc[nt][0] = -1e30f;
                if (c1 > r0) sacc[nt][1] = -1e30f;
                if (c0 > r1) sacc[nt][2] = -1e30f;
                if (c1 > r1) sacc[nt][3] = -1e30f;
            }
        }

#pragma unroll
        for (int r = 0; r < 2; r++) {
            float tm = -1e30f;
#pragma unroll
            for (int nt = 0; nt < 8; nt++)
                tm = fmaxf(tm, fmaxf(sacc[nt][2 * r], sacc[nt][2 * r + 1]));
            tm = fmaxf(tm, __shfl_xor_sync(0xffffffffu, tm, 1));
            tm = fmaxf(tm, __shfl_xor_sync(0xffffffffu, tm, 2));
            float mn = fmaxf(mrow[r], tm);
            float sc = fast_exp(mrow[r] - mn);
            mrow[r] = mn;
            float se = 0.f, s2 = 0.f;
#pragma unroll
            for (int nt = 0; nt < 8; nt++) {
                float p0 = fast_exp(sacc[nt][2 * r] - mn);
                float p1 = fast_exp(sacc[nt][2 * r + 1] - mn);
                sacc[nt][2 * r] = p0; sacc[nt][2 * r + 1] = p1;
                se += p0 + p1;
                s2 += p0 * p0 + p1 * p1;
            }
            se += __shfl_xor_sync(0xffffffffu, se, 1);
            se += __shfl_xor_sync(0xffffffffu, se, 2);
            s2 += __shfl_xor_sync(0xffffffffu, s2, 1);
            s2 += __shfl_xor_sync(0xffffffffu, s2, 2);
            lrow[r] = lrow[r] * sc + se;
            erow[r] = erow[r] * sc * sc + s2;
#pragma unroll
            for (int nt = 0; nt < 8; nt++) {
                oacc[nt][2 * r] *= sc;
                oacc[nt][2 * r + 1] *= sc;
            }
        }

        // PV
#pragma unroll
        for (int ks = 0; ks < 4; ks++) {
            float* pa = sacc[2 * ks];
            float* pb = sacc[2 * ks + 1];
            uint32_t ph[4], pl[4];
            float hx, hy;
            ph[0] = pack_bf16x2(pa[0], pa[1]);
            hx = __bfloat162float(__float2bfloat16(pa[0]));
            hy = __bfloat162float(__float2bfloat16(pa[1]));
            pl[0] = pack_bf16x2(pa[0] - hx, pa[1] - hy);
            ph[1] = pack_bf16x2(pa[2], pa[3]);
            hx = __bfloat162float(__float2bfloat16(pa[2]));
            hy = __bfloat162float(__float2bfloat16(pa[3]));
            pl[1] = pack_bf16x2(pa[2] - hx, pa[3] - hy);
            ph[2] = pack_bf16x2(pb[0], pb[1]);
            hx = __bfloat162float(__float2bfloat16(pb[0]));
            hy = __bfloat162float(__float2bfloat16(pb[1]));
            pl[2] = pack_bf16x2(pb[0] - hx, pb[1] - hy);
            ph[3] = pack_bf16x2(pb[2], pb[3]);
            hx = __bfloat162float(__float2bfloat16(pb[2]));
            hy = __bfloat162float(__float2bfloat16(pb[3]));
            pl[3] = pack_bf16x2(pb[2] - hx, pb[3] - hy);
#pragma unroll
            for (int nt = 0; nt < 8; nt++) {
                uint32_t bo = (st - sb) + 2 * ATS + (nt * 8 + gID) * APAD_B + (ks * 16 + tg * 2) * 2;
                uint32_t vh0 = *(const uint32_t*)(smr + bo);
                uint32_t vh1 = *(const uint32_t*)(smr + bo + 16);
                uint32_t vl0 = *(const uint32_t*)(smr + bo + ATS);
                uint32_t vl1 = *(const uint32_t*)(smr + bo + ATS + 16);
                mma16816(oacc[nt], ph[0], ph[1], ph[2], ph[3], vh0, vh1);
                mma16816(oacc[nt], pl[0], pl[1], pl[2], pl[3], vh0, vh1);
                mma16816(oacc[nt], ph[0], ph[1], ph[2], ph[3], vl0, vl1);
            }
        }

        asm volatile("cp.async.wait_group 0;" ::: "memory");
        __syncthreads();
    }

    // epilogue
    float linv0 = 1.f / lrow[0], linv1 = 1.f / lrow[1];
    int r0 = w * 16 + gID, r1 = r0 + 8;
    int b = bh >> 4, h = bh & 15;
    float* ar0 = ao + (size_t)(b * T_ + q0 + r0) * C_ + h * DH_;
    float* ar1 = ao + (size_t)(b * T_ + q0 + r1) * C_ + h * DH_;
#pragma unroll
    for (int nt = 0; nt < 8; nt++) {
        *(float2*)&ar0[nt * 8 + tg * 2] = make_float2(oacc[nt][0] * linv0, oacc[nt][1] * linv0);
        *(float2*)&ar1[nt * 8 + tg * 2] = make_float2(oacc[nt][2] * linv1, oacc[nt][3] * linv1);
    }

    red[tid] = (tg == 0) ? (erow[0] * linv0 * linv0 + erow[1] * linv1 * linv1) : 0.f;
    __syncthreads();
    for (int o = 64; o > 0; o >>= 1) {
        if (tid < o) red[tid] += red[tid + o];
        __syncthreads();
    }
    if (tid == 0) gepart[bh * 16 + qt] = red[0];
}

// -------------- head energy -> entropy -> adaptive head mask --------------
__global__ void headmask(const float* __restrict__ epart, float* __restrict__ maskout)
{
    __shared__ double e[64];
    __shared__ double cand[64];
    int t = threadIdx.x;
    double s = 0.0;
    for (int i = 0; i < 16; i++) s += (double)epart[t * 16 + i];
    e[t] = s / 1048576.0;
    __syncthreads();
    int b = t >> 4;
    double m = -1e300;
    for (int j = 0; j < 16; j++) m = fmax(m, e[b * 16 + j]);
    double Z = 0.0;
    for (int j = 0; j < 16; j++) Z += exp(e[b * 16 + j] - m);
    double ent = 0.0;
    for (int j = 0; j < 16; j++) {
        double p = exp(e[b * 16 + j] - m) / Z;
        ent -= p * log(p + 1e-9);
    }
    double entn = fmin(fmax(ent / log(16.0), 0.0), 1.0);
    int keep = (int)rint(2.0 + entn * 4.0);
    double eh = e[t];
    int g = 0;
    for (int j = 0; j < 16; j++) g += (e[b * 16 + j] > eh);
    cand[t] = (g <= keep - 1) ? eh : 1e300;
    __syncthreads();
    double th = 1e300;
    for (int j = 0; j < 16; j++) th = fmin(th, cand[b * 16 + j]);
    maskout[t] = (eh >= th) ? 1.f : 0.f;
}

// ---------------- launch ----------------
extern "C" void kernel_launch(void* const* d_in, const int* in_sizes, int n_in,
                              void* d_out, int out_size)
{
    const float* x  = (const float*)d_in[0];
    const float* qw = (const float*)d_in[1];
    const float* qb = (const float*)d_in[2];
    const float* kw = (const float*)d_in[3];
    const float* kb = (const float*)d_in[4];
    const float* vw = (const float*)d_in[5];
    const float* vb = (const float*)d_in[6];
    const float* ow = (const float*)d_in[7];
    const float* ob = (const float*)d_in[8];
    float* out = (float*)d_out;

    float *gq, *gk, *gv, *gep, *gm, *gao;
    cudaGetSymbolAddress((void**)&gq, g_q);
    cudaGetSymbolAddress((void**)&gk, g_k);
    cudaGetSymbolAddress((void**)&gv, g_v);
    cudaGetSymbolAddress((void**)&gep, g_epart);
    cudaGetSymbolAddress((void**)&gm, g_mask);
    cudaGetSymbolAddress((void**)&gao, g_ao);

    __nv_bfloat16 *xh, *xl, *x3, *qws, *kwh, *kwl, *vwh, *vwl, *owh, *owl, *aoh, *aol;
    __nv_bfloat16 *qsh, *qsl, *ksh, *ksl, *vth, *vtl;
    cudaGetSymbolAddress((void**)&xh, g_xh);   cudaGetSymbolAddress((void**)&xl, g_xl);
    cudaGetSymbolAddress((void**)&x3, g_x3);   cudaGetSymbolAddress((void**)&qws, g_qws);
    cudaGetSymbolAddress((void**)&kwh, g_kwh); cudaGetSymbolAddress((void**)&kwl, g_kwl);
    cudaGetSymbolAddress((void**)&vwh, g_vwh); cudaGetSymbolAddress((void**)&vwl, g_vwl);
    cudaGetSymbolAddress((void**)&owh, g_owh); cudaGetSymbolAddress((void**)&owl, g_owl);
    cudaGetSymbolAddress((void**)&aoh, g_aoh); cudaGetSymbolAddress((void**)&aol, g_aol);
    cudaGetSymbolAddress((void**)&qsh, g_qsh); cudaGetSymbolAddress((void**)&qsl, g_qsl);
    cudaGetSymbolAddress((void**)&ksh, g_ksh); cudaGetSymbolAddress((void**)&ksl, g_ksl);
    cudaGetSymbolAddress((void**)&vth, g_vth); cudaGetSymbolAddress((void**)&vtl, g_vtl);

    cudaFuncSetAttribute((const void*)gemm_mma,
                         cudaFuncAttributeMaxDynamicSharedMemorySize, 2 * STAGE_B);
    cudaFuncSetAttribute((const void*)qgemm_mma,
                         cudaFuncAttributeMaxDynamicSharedMemorySize, 2 * QSTAGE_B);
    cudaFuncSetAttribute((const void*)attn_mma,
                         cudaFuncAttributeMaxDynamicSharedMemorySize, ATT_SMEM);

    // splits
    split3x<<<M_ * C_ / 1024, 256>>>((const float4*)x, (ushort4*)xh, (ushort4*)xl, (ushort4*)x3);
    signw_bf16<<<C_ * C_ / 1024, 256>>>((const float4*)qw, (ushort4*)qws);
    split2k<<<C_ * C_ / 1024, 256>>>((const float4*)kw, (ushort4*)kwh, (ushort4*)kwl);
    split2k<<<C_ * C_ / 1024, 256>>>((const float4*)vw, (ushort4*)vwh, (ushort4*)vwl);
    split2k<<<C_ * C_ / 1024, 256>>>((const float4*)ow, (ushort4*)owh, (ushort4*)owl);

    // projections
    qgemm_mma<<<dim3(C_ / 128, M_ / 64), 256, 2 * QSTAGE_B>>>(xh, xl, x3, qws, qb, gq);
    dim3 tGrid(C_ / 128, M_ / 128);
    gemm_mma<<<tGrid, 256, 2 * STAGE_B>>>(xh, xl, kwh, kwl, kb, gk, 1, nullptr);
    gemm_mma<<<tGrid, 256, 2 * STAGE_B>>>(xh, xl, vwh, vwl, vb, gv, 1, nullptr);

    qpost<<<BH_ * T_ / 4, 256>>>(gq, qsh, qsl);
    knorm<<<BH_ * T_ / 4, 256>>>(gk, ksh, ksl);
    vsplitT<<<dim3(16, BH_), 256>>>(gv, vth, vtl);

    attn_mma<<<dim3(16, BH_), 128, ATT_SMEM>>>(qsh, qsl, ksh, ksl, vth, vtl, gao, gep);
    headmask<<<1, 64>>>(gep, gm);

    split_ao<<<M_ * C_ / 1024, 256>>>((const float4*)gao, gm, (ushort4*)aoh, (ushort4*)aol);
    // O projection: skip K-chunks of masked heads (bitwise identical)
    gemm_mma<<<tGrid, 256, 2 * STAGE_B>>>(aoh, aol, owh, owl, ob, out, 0, gm);
}

// round 9
// speedup vs baseline: 2.6078x; 1.0256x over previous
#include <cuda_runtime.h>
#include <cuda_bf16.h>
#include <math.h>
#include <stdint.h>

#define B_  4
#define T_  1024
#define C_  1024
#define H_  16
#define DH_ 64
#define BH_ 64            // B_*H_
#define M_  4096          // B_*T_

// ---------------- scratch (device globals: allocation-free) ----------------
__device__ float g_q[BH_ * T_ * DH_];       // fp32 q after projection
__device__ float g_epart[BH_ * 16];
__device__ float g_mask[BH_];

// bf16 split buffers
__device__ __nv_bfloat16 g_xh[M_ * C_],  g_xl[M_ * C_], g_x3[M_ * C_];
__device__ __nv_bfloat16 g_qws[C_ * C_];
__device__ __nv_bfloat16 g_kwh[C_ * C_], g_kwl[C_ * C_];
__device__ __nv_bfloat16 g_vwh[C_ * C_], g_vwl[C_ * C_];
__device__ __nv_bfloat16 g_owh[C_ * C_], g_owl[C_ * C_];
__device__ __nv_bfloat16 g_aoh[M_ * C_], g_aol[M_ * C_];
// attention operand splits
__device__ __nv_bfloat16 g_qsh[BH_ * T_ * DH_], g_qsl[BH_ * T_ * DH_];   // (bh,t,d)
__device__ __nv_bfloat16 g_ksh[BH_ * T_ * DH_], g_ksl[BH_ * T_ * DH_];   // (bh,t,d)
__device__ __nv_bfloat16 g_vth[BH_ * T_ * DH_], g_vtl[BH_ * T_ * DH_];   // (bh,d,t)

__constant__ int KEEPC[16] = {22,21,20,19,18,18,17,16,15,14,13,13,12,11,10,9};

// ---------------- helpers ----------------
__device__ __forceinline__ void twosum(float& s, float& c, float v) {
    float t  = __fadd_rn(s, v);
    float bo = __fsub_rn(t, s);
    float e1 = __fsub_rn(s, __fsub_rn(t, bo));
    float e2 = __fsub_rn(v, bo);
    c = __fadd_rn(c, __fadd_rn(e1, e2));
    s = t;
}

// fast exp (no MUFU): d <= 0, rel err ~2.4e-8
__device__ __forceinline__ float fast_exp(float d) {
    d = fmaxf(d, -80.f);
    float t = d * 1.4426950408889634f;
    float n = rintf(t);
    float f = fmaf(n, -0.693147182464599609375f, d);
    f = fmaf(n, 1.9046542999577680452e-9f, f);
    float p = 1.3888888888888889e-3f;
    p = fmaf(p, f, 8.3333333333333332e-3f);
    p = fmaf(p, f, 4.1666666666666664e-2f);
    p = fmaf(p, f, 1.6666666666666666e-1f);
    p = fmaf(p, f, 0.5f);
    p = fmaf(p, f, 1.0f);
    p = fmaf(p, f, 1.0f);
    int j = (int)n;
    return p * __uint_as_float((unsigned)(127 + j) << 23);
}

__device__ __forceinline__ uint32_t pack_bf16x2(float lo, float hi) {
    uint32_t r;
    asm("cvt.rn.bf16x2.f32 %0, %1, %2;" : "=r"(r) : "f"(hi), "f"(lo));
    return r;
}

__device__ __forceinline__ void mma16816(float* d,
    uint32_t a0, uint32_t a1, uint32_t a2, uint32_t a3,
    uint32_t b0, uint32_t b1)
{
    asm volatile(
        "mma.sync.aligned.m16n8k16.row.col.f32.bf16.bf16.f32 "
        "{%0,%1,%2,%3}, {%4,%5,%6,%7}, {%8,%9}, {%0,%1,%2,%3};"
        : "+f"(d[0]), "+f"(d[1]), "+f"(d[2]), "+f"(d[3])
        : "r"(a0), "r"(a1), "r"(a2), "r"(a3), "r"(b0), "r"(b1));
}

__device__ __forceinline__ void bf16split(float x, unsigned short& h, unsigned short& l) {
    __nv_bfloat16 hh = __float2bfloat16(x);
    h = __bfloat16_as_ushort(hh);
    l = __bfloat16_as_ushort(__float2bfloat16(x - __bfloat162float(hh)));
}

// ---------------- split kernels ----------------
__global__ void split3x(const float4* __restrict__ src, ushort4* __restrict__ o1,
                        ushort4* __restrict__ o2, ushort4* __restrict__ o3)
{
    int i = blockIdx.x * 256 + threadIdx.x;
    float4 v = src[i];
    float a[4] = {v.x, v.y, v.z, v.w};
    ushort4 H, L, T3;
    unsigned short* hp = &H.x; unsigned short* lp = &L.x; unsigned short* tp = &T3.x;
#pragma unroll
    for (int j = 0; j < 4; j++) {
        __nv_bfloat16 h = __float2bfloat16(a[j]);
        float r1 = a[j] - __bfloat162float(h);
        __nv_bfloat16 l = __float2bfloat16(r1);
        float r2 = r1 - __bfloat162float(l);
        tp[j] = __bfloat16_as_ushort(__float2bfloat16(r2));
        hp[j] = __bfloat16_as_ushort(h);
        lp[j] = __bfloat16_as_ushort(l);
    }
    o1[i] = H; o2[i] = L; o3[i] = T3;
}

// all 4 weight preps in one launch: y=0 kw, y=1 vw, y=2 ow (2-term split), y=3 sign(qw)
__global__ void wsplit4(const float4* __restrict__ kw, const float4* __restrict__ vw,
                        const float4* __restrict__ ow, const float4* __restrict__ qw,
                        ushort4* __restrict__ kwh, ushort4* __restrict__ kwl,
                        ushort4* __restrict__ vwh, ushort4* __restrict__ vwl,
                        ushort4* __restrict__ owh, ushort4* __restrict__ owl,
                        ushort4* __restrict__ qws)
{
    int i = blockIdx.x * 256 + threadIdx.x;
    int which = blockIdx.y;
    if (which == 3) {
        float4 v = qw[i];
        ushort4 o;
        o.x = (v.x > 0.f) ? 0x3F80 : ((v.x < 0.f) ? 0xBF80 : 0);
        o.y = (v.y > 0.f) ? 0x3F80 : ((v.y < 0.f) ? 0xBF80 : 0);
        o.z = (v.z > 0.f) ? 0x3F80 : ((v.z < 0.f) ? 0xBF80 : 0);
        o.w = (v.w > 0.f) ? 0x3F80 : ((v.w < 0.f) ? 0xBF80 : 0);
        qws[i] = o;
        return;
    }
    const float4* src = (which == 0) ? kw : (which == 1) ? vw : ow;
    ushort4* hi = (which == 0) ? kwh : (which == 1) ? vwh : owh;
    ushort4* lo = (which == 0) ? kwl : (which == 1) ? vwl : owl;
    float4 v = src[i];
    float a[4] = {v.x, v.y, v.z, v.w};
    ushort4 H, L;
    unsigned short* hp = &H.x; unsigned short* lp = &L.x;
#pragma unroll
    for (int j = 0; j < 4; j++) bf16split(a[j], hp[j], lp[j]);
    hi[i] = H; lo[i] = L;
}

// ---------------- shared GEMM mainloop pieces ----------------
#define TILE_B   10240
#define STAGE_B  40960
#define NCHUNK   32

__device__ __forceinline__ void load_chunk_async(
    uint32_t sbase,
    const __nv_bfloat16* __restrict__ Ahi, const __nv_bfloat16* __restrict__ Alo,
    const __nv_bfloat16* __restrict__ Bhi, const __nv_bfloat16* __restrict__ Blo,
    int m0, int n0, int k0, int tid)
{
#pragma unroll
    for (int i = 0; i < 8; i++) {
        int u = tid + i * 256;
        int tile = u >> 9;
        int idx = u & 511;
        int row = idx >> 2;
        int jj = idx & 3;
        const __nv_bfloat16* g;
        if (tile == 0)      g = Ahi + (size_t)(m0 + row) * C_ + k0 + jj * 8;
        else if (tile == 1) g = Alo + (size_t)(m0 + row) * C_ + k0 + jj * 8;
        else if (tile == 2) g = Bhi + (size_t)(n0 + row) * C_ + k0 + jj * 8;
        else                g = Blo + (size_t)(n0 + row) * C_ + k0 + jj * 8;
        uint32_t dst = sbase + tile * TILE_B + row * 80 + jj * 16;
        asm volatile("cp.async.cg.shared.global [%0], [%1], 16;" :: "r"(dst), "l"(g));
    }
}

// mainloop macro: accumulates into acc[4][4][4], chunk list given by (start..count with act)
#define GEMM_MAINLOOP(ACT_EXPR, NA)                                                   \
    load_chunk_async(sbase, Ahi, Alo, Bhi, Blo, m0, n0, (ACT_EXPR(0)) * 32, tid);     \
    asm volatile("cp.async.commit_group;" ::: "memory");                              \
    asm volatile("cp.async.wait_group 0;" ::: "memory");                              \
    __syncthreads();                                                                  \
    for (int c = 0; c < (NA); c++) {                                                  \
        if (c + 1 < (NA)) {                                                           \
            load_chunk_async(sbase + ((c + 1) & 1) * STAGE_B,                         \
                             Ahi, Alo, Bhi, Blo, m0, n0, (ACT_EXPR(c + 1)) * 32, tid);\
            asm volatile("cp.async.commit_group;" ::: "memory");                      \
        }                                                                             \
        const char* st = smc + (c & 1) * STAGE_B;                                     \
        _Pragma("unroll")                                                             \
        for (int ks = 0; ks < 2; ks++) {                                              \
            const int acol = ks * 32 + tg * 4;                                        \
            uint32_t ah[4][4], al[4][4], bhf[4][2], blf[4][2];                        \
            _Pragma("unroll")                                                         \
            for (int nt = 0; nt < 4; nt++) {                                          \
                int ro = (wn * 32 + nt * 8 + gID) * 80 + acol;                        \
                bhf[nt][0] = *(const uint32_t*)(st + 2 * TILE_B + ro);                \
                bhf[nt][1] = *(const uint32_t*)(st + 2 * TILE_B + ro + 16);           \
                blf[nt][0] = *(const uint32_t*)(st + 3 * TILE_B + ro);                \
                blf[nt][1] = *(const uint32_t*)(st + 3 * TILE_B + ro + 16);           \
            }                                                                         \
            _Pragma("unroll")                                                         \
            for (int mt = 0; mt < 4; mt++) {                                          \
                int ro = (wm * 64 + mt * 16 + gID) * 80 + acol;                       \
                ah[mt][0] = *(const uint32_t*)(st + ro);                              \
                ah[mt][1] = *(const uint32_t*)(st + ro + 640);                        \
                ah[mt][2] = *(const uint32_t*)(st + ro + 16);                         \
                ah[mt][3] = *(const uint32_t*)(st + ro + 656);                        \
                al[mt][0] = *(const uint32_t*)(st + TILE_B + ro);                     \
                al[mt][1] = *(const uint32_t*)(st + TILE_B + ro + 640);               \
                al[mt][2] = *(const uint32_t*)(st + TILE_B + ro + 16);                \
                al[mt][3] = *(const uint32_t*)(st + TILE_B + ro + 656);               \
            }                                                                         \
            _Pragma("unroll")                                                         \
            for (int mt = 0; mt < 4; mt++)                                            \
                _Pragma("unroll")                                                     \
                for (int nt = 0; nt < 4; nt++) {                                      \
                    mma16816(acc[mt][nt], ah[mt][0], ah[mt][1], ah[mt][2], ah[mt][3], \
                             bhf[nt][0], bhf[nt][1]);                                 \
                    mma16816(acc[mt][nt], al[mt][0], al[mt][1], al[mt][2], al[mt][3], \
                             bhf[nt][0], bhf[nt][1]);                                 \
                    mma16816(acc[mt][nt], ah[mt][0], ah[mt][1], ah[mt][2], ah[mt][3], \
                             blf[nt][0], blf[nt][1]);                                 \
                }                                                                     \
        }                                                                             \
        if (c + 1 < (NA))                                                             \
            asm volatile("cp.async.wait_group 0;" ::: "memory");                      \
        __syncthreads();                                                              \
    }

#define ACT_ID(c) (c)
#define ACT_LUT(c) (act[c])

// ---------------- K GEMM fused with RMS norm + bf16 split ----------------
__global__ __launch_bounds__(256) void gemm_k(
    const __nv_bfloat16* __restrict__ Ahi, const __nv_bfloat16* __restrict__ Alo,
    const __nv_bfloat16* __restrict__ Bhi, const __nv_bfloat16* __restrict__ Blo,
    const float* __restrict__ bias,
    __nv_bfloat16* __restrict__ kh, __nv_bfloat16* __restrict__ kl)
{
    extern __shared__ char smc[];
    const int tid = threadIdx.x;
    const int lane = tid & 31, wid = tid >> 5;
    const int wm = wid >> 2, wn = wid & 3;
    const int gID = lane >> 2, tg = lane & 3;
    const int m0 = blockIdx.y * 128, n0 = blockIdx.x * 128;
    uint32_t sbase = (uint32_t)__cvta_generic_to_shared(smc);

    float acc[4][4][4];
#pragma unroll
    for (int mt = 0; mt < 4; mt++)
#pragma unroll
        for (int nt = 0; nt < 4; nt++)
#pragma unroll
            for (int r = 0; r < 4; r++) acc[mt][nt][r] = 0.f;

    GEMM_MAINLOOP(ACT_ID, NCHUNK)

    // epilogue: store (m,n) tile to smem, per-row RMS over each head, split-write
    float* tb = (float*)smc;     // [128][132]
#pragma unroll
    for (int mt = 0; mt < 4; mt++) {
        int ml = wm * 64 + mt * 16 + gID;
#pragma unroll
        for (int nt = 0; nt < 4; nt++) {
            int nl = wn * 32 + nt * 8 + tg * 2;
            float b0v = bias[n0 + nl], b1v = bias[n0 + nl + 1];
            tb[ml * 132 + nl]           = acc[mt][nt][0] + b0v;
            tb[ml * 132 + nl + 1]       = acc[mt][nt][1] + b1v;
            tb[(ml + 8) * 132 + nl]     = acc[mt][nt][2] + b0v;
            tb[(ml + 8) * 132 + nl + 1] = acc[mt][nt][3] + b1v;
        }
    }
    __syncthreads();

    {
        int ml = tid >> 1, h2 = tid & 1;
        const float* row = &tb[ml * 132 + h2 * 64];
        float ss = 0.f;
#pragma unroll
        for (int j4 = 0; j4 < 16; j4++) {
            float4 v = *(const float4*)&row[j4 * 4];
            ss += v.x * v.x + v.y * v.y + v.z * v.z + v.w * v.w;
        }
        float inv = 1.f / (sqrtf(ss * (1.f / 64.f)) + 1e-6f);
        int m = m0 + ml;
        int bb = m >> 10, t = m & 1023;
        int h = (n0 >> 6) + h2;
        __nv_bfloat16* oh = kh + (((size_t)(bb * H_ + h)) * T_ + t) * DH_;
        __nv_bfloat16* ol = kl + (((size_t)(bb * H_ + h)) * T_ + t) * DH_;
#pragma unroll
        for (int j4 = 0; j4 < 16; j4++) {
            float4 v = *(const float4*)&row[j4 * 4];
            ushort4 Hv, Lv;
            bf16split(v.x * inv, Hv.x, Lv.x);
            bf16split(v.y * inv, Hv.y, Lv.y);
            bf16split(v.z * inv, Hv.z, Lv.z);
            bf16split(v.w * inv, Hv.w, Lv.w);
            *(ushort4*)&oh[j4 * 4] = Hv;
            *(ushort4*)&ol[j4 * 4] = Lv;
        }
    }
}

// ---------------- V GEMM fused with transpose + bf16 split ----------------
__global__ __launch_bounds__(256) void gemm_v(
    const __nv_bfloat16* __restrict__ Ahi, const __nv_bfloat16* __restrict__ Alo,
    const __nv_bfloat16* __restrict__ Bhi, const __nv_bfloat16* __restrict__ Blo,
    const float* __restrict__ bias,
    __nv_bfloat16* __restrict__ vth, __nv_bfloat16* __restrict__ vtl)
{
    extern __shared__ char smc[];
    const int tid = threadIdx.x;
    const int lane = tid & 31, wid = tid >> 5;
    const int wm = wid >> 2, wn = wid & 3;
    const int gID = lane >> 2, tg = lane & 3;
    const int m0 = blockIdx.y * 128, n0 = blockIdx.x * 128;
    uint32_t sbase = (uint32_t)__cvta_generic_to_shared(smc);

    float acc[4][4][4];
#pragma unroll
    for (int mt = 0; mt < 4; mt++)
#pragma unroll
        for (int nt = 0; nt < 4; nt++)
#pragma unroll
            for (int r = 0; r < 4; r++) acc[mt][nt][r] = 0.f;

    GEMM_MAINLOOP(ACT_ID, NCHUNK)

    // epilogue: store TRANSPOSED tile tb[n][m], then split-write (bh,d,t)
    float* tb = (float*)smc;     // [128][132]
#pragma unroll
    for (int mt = 0; mt < 4; mt++) {
        int ml = wm * 64 + mt * 16 + gID;
#pragma unroll
        for (int nt = 0; nt < 4; nt++) {
            int nl = wn * 32 + nt * 8 + tg * 2;
            float b0v = bias[n0 + nl], b1v = bias[n0 + nl + 1];
            tb[nl * 132 + ml]           = acc[mt][nt][0] + b0v;
            tb[(nl + 1) * 132 + ml]     = acc[mt][nt][1] + b1v;
            tb[nl * 132 + ml + 8]       = acc[mt][nt][2] + b0v;
            tb[(nl + 1) * 132 + ml + 8] = acc[mt][nt][3] + b1v;
        }
    }
    __syncthreads();

    {
        int nl = tid >> 1, mhalf = (tid & 1) * 64;
        const float* row = &tb[nl * 132 + mhalf];
        int h = (n0 >> 6) + (nl >> 6);
        int d = nl & 63;
        int bb = m0 >> 10;
        int t0 = (m0 & 1023) + mhalf;
        __nv_bfloat16* oh = vth + (((size_t)(bb * H_ + h)) * DH_ + d) * T_ + t0;
        __nv_bfloat16* ol = vtl + (((size_t)(bb * H_ + h)) * DH_ + d) * T_ + t0;
#pragma unroll
        for (int j4 = 0; j4 < 16; j4++) {
            float4 v = *(const float4*)&row[j4 * 4];
            ushort4 Hv, Lv;
            bf16split(v.x, Hv.x, Lv.x);
            bf16split(v.y, Hv.y, Lv.y);
            bf16split(v.z, Hv.z, Lv.z);
            bf16split(v.w, Hv.w, Lv.w);
            *(ushort4*)&oh[j4 * 4] = Hv;
            *(ushort4*)&ol[j4 * 4] = Lv;
        }
    }
}

// ---------------- O GEMM with head-mask chunk skip ----------------
__global__ __launch_bounds__(256) void gemm_o(
    const __nv_bfloat16* __restrict__ Ahi, const __nv_bfloat16* __restrict__ Alo,
    const __nv_bfloat16* __restrict__ Bhi, const __nv_bfloat16* __restrict__ Blo,
    const float* __restrict__ bias, float* __restrict__ Cout,
    const float* __restrict__ maskp)
{
    extern __shared__ char smc[];
    const int tid = threadIdx.x;
    const int lane = tid & 31, wid = tid >> 5;
    const int wm = wid >> 2, wn = wid & 3;
    const int gID = lane >> 2, tg = lane & 3;
    const int m0 = blockIdx.y * 128, n0 = blockIdx.x * 128;
    uint32_t sbase = (uint32_t)__cvta_generic_to_shared(smc);

    __shared__ int act[NCHUNK];
    __shared__ int s_na;
    if (tid == 0) {
        int n = 0;
        int b16 = (m0 >> 10) << 4;
        for (int ch = 0; ch < NCHUNK; ch++)
            if (maskp[b16 + (ch >> 1)] != 0.f) act[n++] = ch;
        s_na = n;
    }
    __syncthreads();
    const int na = s_na;

    float acc[4][4][4];
#pragma unroll
    for (int mt = 0; mt < 4; mt++)
#pragma unroll
        for (int nt = 0; nt < 4; nt++)
#pragma unroll
            for (int r = 0; r < 4; r++) acc[mt][nt][r] = 0.f;

    GEMM_MAINLOOP(ACT_LUT, na)

#pragma unroll
    for (int mt = 0; mt < 4; mt++) {
        int m1 = m0 + wm * 64 + mt * 16 + gID;
#pragma unroll
        for (int nt = 0; nt < 4; nt++) {
            int n = n0 + wn * 32 + nt * 8 + tg * 2;
            float b0v = bias[n], b1v = bias[n + 1];
            float* a = acc[mt][nt];
            *(float2*)&Cout[(size_t)m1 * C_ + n] = make_float2(a[0] + b0v, a[1] + b1v);
            *(float2*)&Cout[(size_t)(m1 + 8) * C_ + n] = make_float2(a[2] + b0v, a[3] + b1v);
        }
    }
}

// ---------------- q GEMM (exact 3-term split + chunked TwoSum): 64x128 ----------------
#define QTILE_B  5120
#define QSTAGE_B 25600
#define QNCH     32

__device__ __forceinline__ void qload_chunk_async(
    uint32_t sbase,
    const __nv_bfloat16* __restrict__ X1, const __nv_bfloat16* __restrict__ X2,
    const __nv_bfloat16* __restrict__ X3, const __nv_bfloat16* __restrict__ Ws,
    int m0, int n0, int k0, int tid)
{
#pragma unroll
    for (int i = 0; i < 5; i++) {
        int u = tid + i * 256;
        const __nv_bfloat16* g;
        uint32_t dst;
        if (u < 768) {
            int term = u >> 8;
            int idx = u & 255;
            int row = idx >> 2, jj = idx & 3;
            const __nv_bfloat16* base = (term == 0) ? X1 : (term == 1) ? X2 : X3;
            g = base + (size_t)(m0 + row) * C_ + k0 + jj * 8;
            dst = sbase + term * QTILE_B + row * 80 + jj * 16;
        } else {
            int v = u - 768;
            int row = v >> 2, jj = v & 3;
            g = Ws + (size_t)(n0 + row) * C_ + k0 + jj * 8;
            dst = sbase + 3 * QTILE_B + row * 80 + jj * 16;
        }
        asm volatile("cp.async.cg.shared.global [%0], [%1], 16;" :: "r"(dst), "l"(g));
    }
}

__global__ __launch_bounds__(256) void qgemm_mma(
    const __nv_bfloat16* __restrict__ X1, const __nv_bfloat16* __restrict__ X2,
    const __nv_bfloat16* __restrict__ X3, const __nv_bfloat16* __restrict__ Ws,
    const float* __restrict__ bias, float* __restrict__ Q)
{
    extern __shared__ char smc[];
    const int tid = threadIdx.x;
    const int lane = tid & 31, wid = tid >> 5;
    const int wm = wid >> 2, wn = wid & 3;
    const int gID = lane >> 2, tg = lane & 3;
    const int m0 = blockIdx.y * 64, n0 = blockIdx.x * 128;
    uint32_t sbase = (uint32_t)__cvta_generic_to_shared(smc);

    float s_[2][4][4], c_[2][4][4];
#pragma unroll
    for (int mt = 0; mt < 2; mt++)
#pragma unroll
        for (int nt = 0; nt < 4; nt++)
#pragma unroll
            for (int r = 0; r < 4; r++) { s_[mt][nt][r] = 0.f; c_[mt][nt][r] = 0.f; }

    qload_chunk_async(sbase, X1, X2, X3, Ws, m0, n0, 0, tid);
    asm volatile("cp.async.commit_group;" ::: "memory");
    asm volatile("cp.async.wait_group 0;" ::: "memory");
    __syncthreads();

    for (int c = 0; c < QNCH; c++) {
        if (c + 1 < QNCH) {
            qload_chunk_async(sbase + ((c + 1) & 1) * QSTAGE_B,
                              X1, X2, X3, Ws, m0, n0, (c + 1) * 32, tid);
            asm volatile("cp.async.commit_group;" ::: "memory");
        }
        const char* st = smc + (c & 1) * QSTAGE_B;

        float tacc[2][4][4];
#pragma unroll
        for (int mt = 0; mt < 2; mt++)
#pragma unroll
            for (int nt = 0; nt < 4; nt++)
#pragma unroll
                for (int r = 0; r < 4; r++) tacc[mt][nt][r] = 0.f;

#pragma unroll
        for (int ks = 0; ks < 2; ks++) {
            const int acol = ks * 32 + tg * 4;
            uint32_t bw[4][2];
#pragma unroll
            for (int nt = 0; nt < 4; nt++) {
                int ro = (wn * 32 + nt * 8 + gID) * 80 + acol;
                bw[nt][0] = *(const uint32_t*)(st + 3 * QTILE_B + ro);
                bw[nt][1] = *(const uint32_t*)(st + 3 * QTILE_B + ro + 16);
            }
#pragma unroll
            for (int term = 0; term < 3; term++) {
                const char* at = st + term * QTILE_B;
                uint32_t ah[2][4];
#pragma unroll
                for (int mt = 0; mt < 2; mt++) {
                    int ro = (wm * 32 + mt * 16 + gID) * 80 + acol;
                    ah[mt][0] = *(const uint32_t*)(at + ro);
                    ah[mt][1] = *(const uint32_t*)(at + ro + 640);
                    ah[mt][2] = *(const uint32_t*)(at + ro + 16);
                    ah[mt][3] = *(const uint32_t*)(at + ro + 656);
                }
#pragma unroll
                for (int mt = 0; mt < 2; mt++)
#pragma unroll
                    for (int nt = 0; nt < 4; nt++)
                        mma16816(tacc[mt][nt], ah[mt][0], ah[mt][1], ah[mt][2], ah[mt][3],
                                 bw[nt][0], bw[nt][1]);
            }
        }
#pragma unroll
        for (int mt = 0; mt < 2; mt++)
#pragma unroll
            for (int nt = 0; nt < 4; nt++)
#pragma unroll
                for (int r = 0; r < 4; r++)
                    twosum(s_[mt][nt][r], c_[mt][nt][r], tacc[mt][nt][r]);

        if (c + 1 < QNCH)
            asm volatile("cp.async.wait_group 0;" ::: "memory");
        __syncthreads();
    }

#pragma unroll
    for (int mt = 0; mt < 2; mt++) {
        int m1 = m0 + wm * 32 + mt * 16 + gID;
#pragma unroll
        for (int nt = 0; nt < 4; nt++) {
            int n = n0 + wn * 32 + nt * 8 + tg * 2;
            int h = n >> 6, d = n & 63;
            float b0v = bias[n], b1v = bias[n + 1];
            float v0 = __fadd_rn(__fadd_rn(s_[mt][nt][0], c_[mt][nt][0]), b0v);
            float v1 = __fadd_rn(__fadd_rn(s_[mt][nt][1], c_[mt][nt][1]), b1v);
            float v2 = __fadd_rn(__fadd_rn(s_[mt][nt][2], c_[mt][nt][2]), b0v);
            float v3 = __fadd_rn(__fadd_rn(s_[mt][nt][3], c_[mt][nt][3]), b1v);
            int bb = m1 >> 10, t = m1 & 1023;
            *(float2*)&Q[(((size_t)(bb * H_ + h)) * T_ + t) * DH_ + d] = make_float2(v0, v1);
            int m2 = m1 + 8;
            int bb2 = m2 >> 10, t2 = m2 & 1023;
            *(float2*)&Q[(((size_t)(bb2 * H_ + h)) * T_ + t2) * DH_ + d] = make_float2(v2, v3);
        }
    }
}

// -------------- q post: RMS norm + exact top-k, emits bf16 split --------------
__global__ __launch_bounds__(256) void qpost(
    const float* __restrict__ q,
    __nv_bfloat16* __restrict__ qh, __nv_bfloat16* __restrict__ ql)
{
    int grp = threadIdx.x >> 6;
    int lane = threadIdx.x & 63;
    int row = blockIdx.x * 4 + grp;
    float v = q[(size_t)row * 64 + lane];
    float ss = v * v;
#pragma unroll
    for (int o = 16; o > 0; o >>= 1) ss += __shfl_xor_sync(0xffffffffu, ss, o);
    __shared__ float ws[8];
    if ((threadIdx.x & 31) == 0) ws[threadIdx.x >> 5] = ss;
    __syncthreads();
    float rms = sqrtf((ws[grp * 2] + ws[grp * 2 + 1]) * (1.f / 64.f)) + 1e-6f;
    float vn = v / rms;
    float a = fabsf(vn);
    __shared__ __align__(16) float sa[4][64];
    sa[grp][lane] = a;
    __syncthreads();
    int g = 0;
    const float4* sv = (const float4*)sa[grp];
#pragma unroll
    for (int j = 0; j < 16; j++) {
        float4 t = sv[j];
        g += (t.x > a) + (t.y > a) + (t.z > a) + (t.w > a);
    }
    int h = (row >> 10) & 15;
    int kc = KEEPC[h];
    float cand = (g <= kc - 1) ? a : INFINITY;
#pragma unroll
    for (int o = 16; o > 0; o >>= 1)
        cand = fminf(cand, __shfl_xor_sync(0xffffffffu, cand, o));
    __shared__ float wm_[8];
    if ((threadIdx.x & 31) == 0) wm_[threadIdx.x >> 5] = cand;
    __syncthreads();
    float th = fminf(wm_[grp * 2], wm_[grp * 2 + 1]);
    float vnm = (a >= th) ? vn : 0.f;
    __nv_bfloat16 hh = __float2bfloat16(vnm);
    qh[(size_t)row * 64 + lane] = hh;
    ql[(size_t)row * 64 + lane] = __float2bfloat16(vnm - __bfloat162float(hh));
}

// -------------- MMA flash attention --------------
#define APAD_B 144
#define ATS 9216
#define ATT_SMEM (2 * ATS + 2 * 4 * ATS)   // 92160

__device__ __forceinline__ void att_kvload(
    uint32_t sb, int s, int kt, size_t hoff, int tid,
    const __nv_bfloat16* __restrict__ kh_g, const __nv_bfloat16* __restrict__ kl_g,
    const __nv_bfloat16* __restrict__ vth_g, const __nv_bfloat16* __restrict__ vtl_g)
{
    uint32_t st = sb + 2 * ATS + s * 4 * ATS;
#pragma unroll
    for (int i = 0; i < 16; i++) {
        int u = tid + i * 128;
        int t = u >> 9, row = (u >> 3) & 63, c = u & 7;
        const __nv_bfloat16* src;
        if (t == 0)      src = kh_g + hoff + (size_t)(kt * 64 + row) * 64 + c * 8;
        else if (t == 1) src = kl_g + hoff + (size_t)(kt * 64 + row) * 64 + c * 8;
        else if (t == 2) src = vth_g + hoff + (size_t)row * T_ + kt * 64 + c * 8;
        else             src = vtl_g + hoff + (size_t)row * T_ + kt * 64 + c * 8;
        uint32_t dst = st + t * ATS + row * APAD_B + c * 16;
        asm volatile("cp.async.cg.shared.global [%0], [%1], 16;" :: "r"(dst), "l"(src));
    }
}

__global__ __launch_bounds__(128) void attn_mma(
    const __nv_bfloat16* __restrict__ qh_g, const __nv_bfloat16* __restrict__ ql_g,
    const __nv_bfloat16* __restrict__ kh_g, const __nv_bfloat16* __restrict__ kl_g,
    const __nv_bfloat16* __restrict__ vth_g, const __nv_bfloat16* __restrict__ vtl_g,
    __nv_bfloat16* __restrict__ aoh, __nv_bfloat16* __restrict__ aol,
    float* __restrict__ gepart)
{
    extern __shared__ char smr[];
    __shared__ float red[128];
    const int qt = (int)(gridDim.x - 1) - (int)blockIdx.x;   // heavy tiles first
    const int bh = blockIdx.y, q0 = qt * 64;
    const int tid = threadIdx.x, lane = tid & 31, w = tid >> 5;
    const int gID = lane >> 2, tg = lane & 3;
    uint32_t sb = (uint32_t)__cvta_generic_to_shared(smr);
    const size_t hoff = (size_t)bh * (T_ * 64);

#pragma unroll
    for (int i = 0; i < 8; i++) {
        int u = tid + i * 128;
        int t = u >> 9, row = (u >> 3) & 63, c = u & 7;
        const __nv_bfloat16* src = (t ? ql_g : qh_g) + hoff + (size_t)(q0 + row) * 64 + c * 8;
        uint32_t dst = sb + t * ATS + row * APAD_B + c * 16;
        asm volatile("cp.async.cg.shared.global [%0], [%1], 16;" :: "r"(dst), "l"(src));
    }
    att_kvload(sb, 0, 0, hoff, tid, kh_g, kl_g, vth_g, vtl_g);
    asm volatile("cp.async.commit_group;" ::: "memory");
    asm volatile("cp.async.wait_group 0;" ::: "memory");
    __syncthreads();

    float oacc[8][4];
#pragma unroll
    for (int nt = 0; nt < 8; nt++)
#pragma unroll
        for (int r = 0; r < 4; r++) oacc[nt][r] = 0.f;
    float mrow[2] = {-1e30f, -1e30f}, lrow[2] = {0.f, 0.f}, erow[2] = {0.f, 0.f};

    for (int kt = 0; kt <= qt; kt++) {
        if (kt < qt) {
            att_kvload(sb, (kt + 1) & 1, kt + 1, hoff, tid, kh_g, kl_g, vth_g, vtl_g);
            asm volatile("cp.async.commit_group;" ::: "memory");
        }
        uint32_t st = sb + 2 * ATS + (kt & 1) * 4 * ATS;

        float sacc[8][4];
#pragma unroll
        for (int nt = 0; nt < 8; nt++)
#pragma unroll
            for (int r = 0; r < 4; r++) sacc[nt][r] = 0.f;

#pragma unroll
        for (int ks = 0; ks < 4; ks++) {
            uint32_t aoff = sb + (w * 16 + gID) * APAD_B + (ks * 16 + tg * 2) * 2;
            uint32_t qh0 = *(const uint32_t*)(smr + (aoff - sb));
            uint32_t qh2 = *(const uint32_t*)(smr + (aoff - sb) + 16);
            uint32_t qh1 = *(const uint32_t*)(smr + (aoff - sb) + 8 * APAD_B);
            uint32_t qh3 = *(const uint32_t*)(smr + (aoff - sb) + 8 * APAD_B + 16);
            uint32_t ql0 = *(const uint32_t*)(smr + (aoff - sb) + ATS);
            uint32_t ql2 = *(const uint32_t*)(smr + (aoff - sb) + ATS + 16);
            uint32_t ql1 = *(const uint32_t*)(smr + (aoff - sb) + ATS + 8 * APAD_B);
            uint32_t ql3 = *(const uint32_t*)(smr + (aoff - sb) + ATS + 8 * APAD_B + 16);
#pragma unroll
            for (int nt = 0; nt < 8; nt++) {
                uint32_t bo = (st - sb) + (nt * 8 + gID) * APAD_B + (ks * 16 + tg * 2) * 2;
                uint32_t kb0 = *(const uint32_t*)(smr + bo);
                uint32_t kb1 = *(const uint32_t*)(smr + bo + 16);
                uint32_t kl0 = *(const uint32_t*)(smr + bo + ATS);
                uint32_t kl1 = *(const uint32_t*)(smr + bo + ATS + 16);
                mma16816(sacc[nt], qh0, qh1, qh2, qh3, kb0, kb1);
                mma16816(sacc[nt], ql0, ql1, ql2, ql3, kb0, kb1);
                mma16816(sacc[nt], qh0, qh1, qh2, qh3, kl0, kl1);
            }
        }

        if (kt == qt) {
            int r0 = w * 16 + gID, r1 = r0 + 8;
#pragma unroll
            for (int nt = 0; nt < 8; nt++) {
                int c0 = nt * 8 + tg * 2, c1 = c0 + 1;
                if (c0 > r0) sacc[nt][0] = -1e30f;
                if (c1 > r0) sacc[nt][1] = -1e30f;
                if (c0 > r1) sacc[nt][2] = -1e30f;
                if (c1 > r1) sacc[nt][3] = -1e30f;
            }
        }

#pragma unroll
        for (int r = 0; r < 2; r++) {
            float tm = -1e30f;
#pragma unroll
            for (int nt = 0; nt < 8; nt++)
                tm = fmaxf(tm, fmaxf(sacc[nt][2 * r], sacc[nt][2 * r + 1]));
            tm = fmaxf(tm, __shfl_xor_sync(0xffffffffu, tm, 1));
            tm = fmaxf(tm, __shfl_xor_sync(0xffffffffu, tm, 2));
            float mn = fmaxf(mrow[r], tm);
            float sc = fast_exp(mrow[r] - mn);
            mrow[r] = mn;
            float se = 0.f, s2 = 0.f;
#pragma unroll
            for (int nt = 0; nt < 8; nt++) {
                float p0 = fast_exp(sacc[nt][2 * r] - mn);
                float p1 = fast_exp(sacc[nt][2 * r + 1] - mn);
                sacc[nt][2 * r] = p0; sacc[nt][2 * r + 1] = p1;
                se += p0 + p1;
                s2 += p0 * p0 + p1 * p1;
            }
            se += __shfl_xor_sync(0xffffffffu, se, 1);
            se += __shfl_xor_sync(0xffffffffu, se, 2);
            s2 += __shfl_xor_sync(0xffffffffu, s2, 1);
            s2 += __shfl_xor_sync(0xffffffffu, s2, 2);
            lrow[r] = lrow[r] * sc + se;
            erow[r] = erow[r] * sc * sc + s2;
#pragma unroll
            for (int nt = 0; nt < 8; nt++) {
                oacc[nt][2 * r] *= sc;
                oacc[nt][2 * r + 1] *= sc;
            }
        }

        // PV
#pragma unroll
        for (int ks = 0; ks < 4; ks++) {
            float* pa = sacc[2 * ks];
            float* pb = sacc[2 * ks + 1];
            uint32_t ph[4], pl[4];
            float hx, hy;
            ph[0] = pack_bf16x2(pa[0], pa[1]);
            hx = __bfloat162float(__float2bfloat16(pa[0]));
            hy = __bfloat162float(__float2bfloat16(pa[1]));
            pl[0] = pack_bf16x2(pa[0] - hx, pa[1] - hy);
            ph[1] = pack_bf16x2(pa[2], pa[3]);
            hx = __bfloat162float(__float2bfloat16(pa[2]));
            hy = __bfloat162float(__float2bfloat16(pa[3]));
            pl[1] = pack_bf16x2(pa[2] - hx, pa[3] - hy);
            ph[2] = pack_bf16x2(pb[0], pb[1]);
            hx = __bfloat162float(__float2bfloat16(pb[0]));
            hy = __bfloat162float(__float2bfloat16(pb[1]));
            pl[2] = pack_bf16x2(pb[0] - hx, pb[1] - hy);
            ph[3] = pack_bf16x2(pb[2], pb[3]);
            hx = __bfloat162float(__float2bfloat16(pb[2]));
            hy = __bfloat162float(__float2bfloat16(pb[3]));
            pl[3] = pack_bf16x2(pb[2] - hx, pb[3] - hy);
#pragma unroll
            for (int nt = 0; nt < 8; nt++) {
                uint32_t bo = (st - sb) + 2 * ATS + (nt * 8 + gID) * APAD_B + (ks * 16 + tg * 2) * 2;
                uint32_t vh0 = *(const uint32_t*)(smr + bo);
                uint32_t vh1 = *(const uint32_t*)(smr + bo + 16);
                uint32_t vl0 = *(const uint32_t*)(smr + bo + ATS);
                uint32_t vl1 = *(const uint32_t*)(smr + bo + ATS + 16);
                mma16816(oacc[nt], ph[0], ph[1], ph[2], ph[3], vh0, vh1);
                mma16816(oacc[nt], pl[0], pl[1], pl[2], pl[3], vh0, vh1);
                mma16816(oacc[nt], ph[0], ph[1], ph[2], ph[3], vl0, vl1);
            }
        }

        asm volatile("cp.async.wait_group 0;" ::: "memory");
        __syncthreads();
    }

    // epilogue: write bf16 hi/lo of out (unmasked; mask handled by O-GEMM chunk skip)
    float linv0 = 1.f / lrow[0], linv1 = 1.f / lrow[1];
    int r0 = w * 16 + gID, r1 = r0 + 8;
    int b = bh >> 4, h = bh & 15;
    size_t base0 = (size_t)(b * T_ + q0 + r0) * C_ + h * DH_;
    size_t base1 = (size_t)(b * T_ + q0 + r1) * C_ + h * DH_;
#pragma unroll
    for (int nt = 0; nt < 8; nt++) {
        int col = nt * 8 + tg * 2;
        float v0 = oacc[nt][0] * linv0, v1 = oacc[nt][1] * linv0;
        float v2 = oacc[nt][2] * linv1, v3 = oacc[nt][3] * linv1;
        ushort2 H0, L0, H1, L1;
        bf16split(v0, H0.x, L0.x); bf16split(v1, H0.y, L0.y);
        bf16split(v2, H1.x, L1.x); bf16split(v3, H1.y, L1.y);
        *(ushort2*)&aoh[base0 + col] = H0;
        *(ushort2*)&aol[base0 + col] = L0;
        *(ushort2*)&aoh[base1 + col] = H1;
        *(ushort2*)&aol[base1 + col] = L1;
    }

    red[tid] = (tg == 0) ? (erow[0] * linv0 * linv0 + erow[1] * linv1 * linv1) : 0.f;
    __syncthreads();
    for (int o = 64; o > 0; o >>= 1) {
        if (tid < o) red[tid] += red[tid + o];
        __syncthreads();
    }
    if (tid == 0) gepart[bh * 16 + qt] = red[0];
}

// -------------- head energy -> entropy -> adaptive head mask --------------
__global__ void headmask(const float* __restrict__ epart, float* __restrict__ maskout)
{
    __shared__ double e[64];
    __shared__ double cand[64];
    int t = threadIdx.x;
    double s = 0.0;
    for (int i = 0; i < 16; i++) s += (double)epart[t * 16 + i];
    e[t] = s / 1048576.0;
    __syncthreads();
    int b = t >> 4;
    double m = -1e300;
    for (int j = 0; j < 16; j++) m = fmax(m, e[b * 16 + j]);
    double Z = 0.0;
    for (int j = 0; j < 16; j++) Z += exp(e[b * 16 + j] - m);
    double ent = 0.0;
    for (int j = 0; j < 16; j++) {
        double p = exp(e[b * 16 + j] - m) / Z;
        ent -= p * log(p + 1e-9);
    }
    double entn = fmin(fmax(ent / log(16.0), 0.0), 1.0);
    int keep = (int)rint(2.0 + entn * 4.0);
    double eh = e[t];
    int g = 0;
    for (int j = 0; j < 16; j++) g += (e[b * 16 + j] > eh);
    cand[t] = (g <= keep - 1) ? eh : 1e300;
    __syncthreads();
    double th = 1e300;
    for (int j = 0; j < 16; j++) th = fmin(th, cand[b * 16 + j]);
    maskout[t] = (eh >= th) ? 1.f : 0.f;
}

// ---------------- launch ----------------
extern "C" void kernel_launch(void* const* d_in, const int* in_sizes, int n_in,
                              void* d_out, int out_size)
{
    const float* x  = (const float*)d_in[0];
    const float* qw = (const float*)d_in[1];
    const float* qb = (const float*)d_in[2];
    const float* kw = (const float*)d_in[3];
    const float* kb = (const float*)d_in[4];
    const float* vw = (const float*)d_in[5];
    const float* vb = (const float*)d_in[6];
    const float* ow = (const float*)d_in[7];
    const float* ob = (const float*)d_in[8];
    float* out = (float*)d_out;

    float *gq, *gep, *gm;
    cudaGetSymbolAddress((void**)&gq, g_q);
    cudaGetSymbolAddress((void**)&gep, g_epart);
    cudaGetSymbolAddress((void**)&gm, g_mask);

    __nv_bfloat16 *xh, *xl, *x3, *qws, *kwh, *kwl, *vwh, *vwl, *owh, *owl, *aoh, *aol;
    __nv_bfloat16 *qsh, *qsl, *ksh, *ksl, *vth, *vtl;
    cudaGetSymbolAddress((void**)&xh, g_xh);   cudaGetSymbolAddress((void**)&xl, g_xl);
    cudaGetSymbolAddress((void**)&x3, g_x3);   cudaGetSymbolAddress((void**)&qws, g_qws);
    cudaGetSymbolAddress((void**)&kwh, g_kwh); cudaGetSymbolAddress((void**)&kwl, g_kwl);
    cudaGetSymbolAddress((void**)&vwh, g_vwh); cudaGetSymbolAddress((void**)&vwl, g_vwl);
    cudaGetSymbolAddress((void**)&owh, g_owh); cudaGetSymbolAddress((void**)&owl, g_owl);
    cudaGetSymbolAddress((void**)&aoh, g_aoh); cudaGetSymbolAddress((void**)&aol, g_aol);
    cudaGetSymbolAddress((void**)&qsh, g_qsh); cudaGetSymbolAddress((void**)&qsl, g_qsl);
    cudaGetSymbolAddress((void**)&ksh, g_ksh); cudaGetSymbolAddress((void**)&ksl, g_ksl);
    cudaGetSymbolAddress((void**)&vth, g_vth); cudaGetSymbolAddress((void**)&vtl, g_vtl);

    cudaFuncSetAttribute((const void*)gemm_k,
                         cudaFuncAttributeMaxDynamicSharedMemorySize, 2 * STAGE_B);
    cudaFuncSetAttribute((const void*)gemm_v,
                         cudaFuncAttributeMaxDynamicSharedMemorySize, 2 * STAGE_B);
    cudaFuncSetAttribute((const void*)gemm_o,
                         cudaFuncAttributeMaxDynamicSharedMemorySize, 2 * STAGE_B);
    cudaFuncSetAttribute((const void*)qgemm_mma,
                         cudaFuncAttributeMaxDynamicSharedMemorySize, 2 * QSTAGE_B);
    cudaFuncSetAttribute((const void*)attn_mma,
                         cudaFuncAttributeMaxDynamicSharedMemorySize, ATT_SMEM);

    // splits
    split3x<<<M_ * C_ / 1024, 256>>>((const float4*)x, (ushort4*)xh, (ushort4*)xl, (ushort4*)x3);
    wsplit4<<<dim3(C_ * C_ / 1024, 4), 256>>>(
        (const float4*)kw, (const float4*)vw, (const float4*)ow, (const float4*)qw,
        (ushort4*)kwh, (ushort4*)kwl, (ushort4*)vwh, (ushort4*)vwl,
        (ushort4*)owh, (ushort4*)owl, (ushort4*)qws);

    // projections (K and V fuse norm/split/transpose epilogues)
    qgemm_mma<<<dim3(C_ / 128, M_ / 64), 256, 2 * QSTAGE_B>>>(xh, xl, x3, qws, qb, gq);
    dim3 tGrid(C_ / 128, M_ / 128);
    gemm_k<<<tGrid, 256, 2 * STAGE_B>>>(xh, xl, kwh, kwl, kb, ksh, ksl);
    gemm_v<<<tGrid, 256, 2 * STAGE_B>>>(xh, xl, vwh, vwl, vb, vth, vtl);

    qpost<<<BH_ * T_ / 4, 256>>>(gq, qsh, qsl);

    attn_mma<<<dim3(16, BH_), 128, ATT_SMEM>>>(qsh, qsl, ksh, ksl, vth, vtl, aoh, aol, gep);
    headmask<<<1, 64>>>(gep, gm);

    // O projection: reads attn's bf16 splits directly, skips masked-head chunks
    gemm_o<<<tGrid, 256, 2 * STAGE_B>>>(aoh, aol, owh, owl, ob, out, gm);
}

// round 10
// speedup vs baseline: 2.7303x; 1.0470x over previous
#include <cuda_runtime.h>
#include <cuda_bf16.h>
#include <math.h>
#include <stdint.h>

#define B_  4
#define T_  1024
#define C_  1024
#define H_  16
#define DH_ 64
#define BH_ 64            // B_*H_
#define M_  4096          // B_*T_

// ---------------- scratch (device globals: allocation-free) ----------------
__device__ float g_q[BH_ * T_ * DH_];       // fp32 q after projection
__device__ float g_epart[BH_ * 16];
__device__ float g_mask[BH_];

// bf16 split buffers
__device__ __nv_bfloat16 g_xh[M_ * C_],  g_xl[M_ * C_], g_x3[M_ * C_];
__device__ __nv_bfloat16 g_qws[C_ * C_];
__device__ __nv_bfloat16 g_kwh[C_ * C_], g_kwl[C_ * C_];
__device__ __nv_bfloat16 g_vwh[C_ * C_], g_vwl[C_ * C_];
__device__ __nv_bfloat16 g_owh[C_ * C_], g_owl[C_ * C_];
__device__ __nv_bfloat16 g_aoh[M_ * C_], g_aol[M_ * C_];
// attention operand splits
__device__ __nv_bfloat16 g_qsh[BH_ * T_ * DH_], g_qsl[BH_ * T_ * DH_];   // (bh,t,d)
__device__ __nv_bfloat16 g_ksh[BH_ * T_ * DH_], g_ksl[BH_ * T_ * DH_];   // (bh,t,d)
__device__ __nv_bfloat16 g_vth[BH_ * T_ * DH_], g_vtl[BH_ * T_ * DH_];   // (bh,d,t)

__constant__ int KEEPC[16] = {22,21,20,19,18,18,17,16,15,14,13,13,12,11,10,9};

// ---------------- helpers ----------------
__device__ __forceinline__ void twosum(float& s, float& c, float v) {
    float t  = __fadd_rn(s, v);
    float bo = __fsub_rn(t, s);
    float e1 = __fsub_rn(s, __fsub_rn(t, bo));
    float e2 = __fsub_rn(v, bo);
    c = __fadd_rn(c, __fadd_rn(e1, e2));
    s = t;
}

// fast exp (no MUFU): d <= 0, rel err ~2.4e-8
__device__ __forceinline__ float fast_exp(float d) {
    d = fmaxf(d, -80.f);
    float t = d * 1.4426950408889634f;
    float n = rintf(t);
    float f = fmaf(n, -0.693147182464599609375f, d);
    f = fmaf(n, 1.9046542999577680452e-9f, f);
    float p = 1.3888888888888889e-3f;
    p = fmaf(p, f, 8.3333333333333332e-3f);
    p = fmaf(p, f, 4.1666666666666664e-2f);
    p = fmaf(p, f, 1.6666666666666666e-1f);
    p = fmaf(p, f, 0.5f);
    p = fmaf(p, f, 1.0f);
    p = fmaf(p, f, 1.0f);
    int j = (int)n;
    return p * __uint_as_float((unsigned)(127 + j) << 23);
}

__device__ __forceinline__ uint32_t pack_bf16x2(float lo, float hi) {
    uint32_t r;
    asm("cvt.rn.bf16x2.f32 %0, %1, %2;" : "=r"(r) : "f"(hi), "f"(lo));
    return r;
}

__device__ __forceinline__ void mma16816(float* d,
    uint32_t a0, uint32_t a1, uint32_t a2, uint32_t a3,
    uint32_t b0, uint32_t b1)
{
    asm volatile(
        "mma.sync.aligned.m16n8k16.row.col.f32.bf16.bf16.f32 "
        "{%0,%1,%2,%3}, {%4,%5,%6,%7}, {%8,%9}, {%0,%1,%2,%3};"
        : "+f"(d[0]), "+f"(d[1]), "+f"(d[2]), "+f"(d[3])
        : "r"(a0), "r"(a1), "r"(a2), "r"(a3), "r"(b0), "r"(b1));
}

__device__ __forceinline__ void ldsm4(uint32_t addr,
    uint32_t& r0, uint32_t& r1, uint32_t& r2, uint32_t& r3)
{
    asm volatile("ldmatrix.sync.aligned.m8n8.x4.shared.b16 {%0,%1,%2,%3}, [%4];"
                 : "=r"(r0), "=r"(r1), "=r"(r2), "=r"(r3) : "r"(addr));
}

__device__ __forceinline__ void bf16split(float x, unsigned short& h, unsigned short& l) {
    __nv_bfloat16 hh = __float2bfloat16(x);
    h = __bfloat16_as_ushort(hh);
    l = __bfloat16_as_ushort(__float2bfloat16(x - __bfloat162float(hh)));
}

// ---------------- split kernels ----------------
__global__ void split3x(const float4* __restrict__ src, ushort4* __restrict__ o1,
                        ushort4* __restrict__ o2, ushort4* __restrict__ o3)
{
    int i = blockIdx.x * 256 + threadIdx.x;
    float4 v = src[i];
    float a[4] = {v.x, v.y, v.z, v.w};
    ushort4 H, L, T3;
    unsigned short* hp = &H.x; unsigned short* lp = &L.x; unsigned short* tp = &T3.x;
#pragma unroll
    for (int j = 0; j < 4; j++) {
        __nv_bfloat16 h = __float2bfloat16(a[j]);
        float r1 = a[j] - __bfloat162float(h);
        __nv_bfloat16 l = __float2bfloat16(r1);
        float r2 = r1 - __bfloat162float(l);
        tp[j] = __bfloat16_as_ushort(__float2bfloat16(r2));
        hp[j] = __bfloat16_as_ushort(h);
        lp[j] = __bfloat16_as_ushort(l);
    }
    o1[i] = H; o2[i] = L; o3[i] = T3;
}

// all 4 weight preps in one launch: y=0 kw, y=1 vw, y=2 ow (2-term split), y=3 sign(qw)
__global__ void wsplit4(const float4* __restrict__ kw, const float4* __restrict__ vw,
                        const float4* __restrict__ ow, const float4* __restrict__ qw,
                        ushort4* __restrict__ kwh, ushort4* __restrict__ kwl,
                        ushort4* __restrict__ vwh, ushort4* __restrict__ vwl,
                        ushort4* __restrict__ owh, ushort4* __restrict__ owl,
                        ushort4* __restrict__ qws)
{
    int i = blockIdx.x * 256 + threadIdx.x;
    int which = blockIdx.y;
    if (which == 3) {
        float4 v = qw[i];
        ushort4 o;
        o.x = (v.x > 0.f) ? 0x3F80 : ((v.x < 0.f) ? 0xBF80 : 0);
        o.y = (v.y > 0.f) ? 0x3F80 : ((v.y < 0.f) ? 0xBF80 : 0);
        o.z = (v.z > 0.f) ? 0x3F80 : ((v.z < 0.f) ? 0xBF80 : 0);
        o.w = (v.w > 0.f) ? 0x3F80 : ((v.w < 0.f) ? 0xBF80 : 0);
        qws[i] = o;
        return;
    }
    const float4* src = (which == 0) ? kw : (which == 1) ? vw : ow;
    ushort4* hi = (which == 0) ? kwh : (which == 1) ? vwh : owh;
    ushort4* lo = (which == 0) ? kwl : (which == 1) ? vwl : owl;
    float4 v = src[i];
    float a[4] = {v.x, v.y, v.z, v.w};
    ushort4 H, L;
    unsigned short* hp = &H.x; unsigned short* lp = &L.x;
#pragma unroll
    for (int j = 0; j < 4; j++) bf16split(a[j], hp[j], lp[j]);
    hi[i] = H; lo[i] = L;
}

// ---------------- shared GEMM mainloop pieces ----------------
#define TILE_B   10240
#define STAGE_B  40960
#define NCHUNK   32

__device__ __forceinline__ void load_chunk_async(
    uint32_t sbase,
    const __nv_bfloat16* __restrict__ Ahi, const __nv_bfloat16* __restrict__ Alo,
    const __nv_bfloat16* __restrict__ Bhi, const __nv_bfloat16* __restrict__ Blo,
    int m0, int n0, int k0, int tid)
{
#pragma unroll
    for (int i = 0; i < 8; i++) {
        int u = tid + i * 256;
        int tile = u >> 9;
        int idx = u & 511;
        int row = idx >> 2;
        int jj = idx & 3;
        const __nv_bfloat16* g;
        if (tile == 0)      g = Ahi + (size_t)(m0 + row) * C_ + k0 + jj * 8;
        else if (tile == 1) g = Alo + (size_t)(m0 + row) * C_ + k0 + jj * 8;
        else if (tile == 2) g = Bhi + (size_t)(n0 + row) * C_ + k0 + jj * 8;
        else                g = Blo + (size_t)(n0 + row) * C_ + k0 + jj * 8;
        uint32_t dst = sbase + tile * TILE_B + row * 80 + jj * 16;
        asm volatile("cp.async.cg.shared.global [%0], [%1], 16;" :: "r"(dst), "l"(g));
    }
}

// ldmatrix fragment bases (lane-dependent):
// A x4 tiles: t0 rows 0-7@k0 (lanes0-7), t1 rows 8-15@k0, t2 rows 0-7@k8, t3 rows 8-15@k8
//   -> rowAdd = (l&7) + ((l>>3)&1)*8, kAdd = ((l>>4)&1)*16 bytes
// B x4 tiles: t0 n0-7@k0, t1 n0-7@k8, t2 n8-15@k0, t3 n8-15@k8
//   -> rowAdd = (l&7) + ((l>>4)&1)*8, kAdd = ((l>>3)&1)*16 bytes
#define GEMM_MAINLOOP(ACT_EXPR, NA)                                                   \
    const uint32_t aBase = (uint32_t)((wm * 64 + (lane & 7) + ((lane >> 3) & 1) * 8) * 80 \
                                      + ((lane >> 4) & 1) * 16);                      \
    const uint32_t bBase = (uint32_t)((wn * 32 + (lane & 7) + ((lane >> 4) & 1) * 8) * 80 \
                                      + ((lane >> 3) & 1) * 16);                      \
    load_chunk_async(sbase, Ahi, Alo, Bhi, Blo, m0, n0, (ACT_EXPR(0)) * 32, tid);     \
    asm volatile("cp.async.commit_group;" ::: "memory");                              \
    asm volatile("cp.async.wait_group 0;" ::: "memory");                              \
    __syncthreads();                                                                  \
    for (int c = 0; c < (NA); c++) {                                                  \
        if (c + 1 < (NA)) {                                                           \
            load_chunk_async(sbase + ((c + 1) & 1) * STAGE_B,                         \
                             Ahi, Alo, Bhi, Blo, m0, n0, (ACT_EXPR(c + 1)) * 32, tid);\
            asm volatile("cp.async.commit_group;" ::: "memory");                      \
        }                                                                             \
        const uint32_t stw = sbase + (c & 1) * STAGE_B;                               \
        _Pragma("unroll")                                                             \
        for (int ks = 0; ks < 2; ks++) {                                              \
            const uint32_t kb = ks * 32;                                              \
            uint32_t ah[4][4], al[4][4], bhf[4][2], blf[4][2];                        \
            ldsm4(stw + 2 * TILE_B + bBase + kb,                                      \
                  bhf[0][0], bhf[0][1], bhf[1][0], bhf[1][1]);                        \
            ldsm4(stw + 2 * TILE_B + 1280 + bBase + kb,                               \
                  bhf[2][0], bhf[2][1], bhf[3][0], bhf[3][1]);                        \
            ldsm4(stw + 3 * TILE_B + bBase + kb,                                      \
                  blf[0][0], blf[0][1], blf[1][0], blf[1][1]);                        \
            ldsm4(stw + 3 * TILE_B + 1280 + bBase + kb,                               \
                  blf[2][0], blf[2][1], blf[3][0], blf[3][1]);                        \
            _Pragma("unroll")                                                         \
            for (int mt = 0; mt < 4; mt++) {                                          \
                ldsm4(stw + aBase + mt * 1280 + kb,                                   \
                      ah[mt][0], ah[mt][1], ah[mt][2], ah[mt][3]);                    \
                ldsm4(stw + TILE_B + aBase + mt * 1280 + kb,                          \
                      al[mt][0], al[mt][1], al[mt][2], al[mt][3]);                    \
            }                                                                         \
            _Pragma("unroll")                                                         \
            for (int mt = 0; mt < 4; mt++)                                            \
                _Pragma("unroll")                                                     \
                for (int nt = 0; nt < 4; nt++) {                                      \
                    mma16816(acc[mt][nt], ah[mt][0], ah[mt][1], ah[mt][2], ah[mt][3], \
                             bhf[nt][0], bhf[nt][1]);                                 \
                    mma16816(acc[mt][nt], al[mt][0], al[mt][1], al[mt][2], al[mt][3], \
                             bhf[nt][0], bhf[nt][1]);                                 \
                    mma16816(acc[mt][nt], ah[mt][0], ah[mt][1], ah[mt][2], ah[mt][3], \
                             blf[nt][0], blf[nt][1]);                                 \
                }                                                                     \
        }                                                                             \
        if (c + 1 < (NA))                                                             \
            asm volatile("cp.async.wait_group 0;" ::: "memory");                      \
        __syncthreads();                                                              \
    }

#define ACT_ID(c) (c)
#define ACT_LUT(c) (act[c])

// ---------------- K GEMM fused with RMS norm + bf16 split ----------------
__global__ __launch_bounds__(256) void gemm_k(
    const __nv_bfloat16* __restrict__ Ahi, const __nv_bfloat16* __restrict__ Alo,
    const __nv_bfloat16* __restrict__ Bhi, const __nv_bfloat16* __restrict__ Blo,
    const float* __restrict__ bias,
    __nv_bfloat16* __restrict__ kh, __nv_bfloat16* __restrict__ kl)
{
    extern __shared__ char smc[];
    const int tid = threadIdx.x;
    const int lane = tid & 31, wid = tid >> 5;
    const int wm = wid >> 2, wn = wid & 3;
    const int gID = lane >> 2, tg = lane & 3;
    const int m0 = blockIdx.y * 128, n0 = blockIdx.x * 128;
    uint32_t sbase = (uint32_t)__cvta_generic_to_shared(smc);

    float acc[4][4][4];
#pragma unroll
    for (int mt = 0; mt < 4; mt++)
#pragma unroll
        for (int nt = 0; nt < 4; nt++)
#pragma unroll
            for (int r = 0; r < 4; r++) acc[mt][nt][r] = 0.f;

    GEMM_MAINLOOP(ACT_ID, NCHUNK)

    // epilogue: store (m,n) tile to smem, per-row RMS over each head, split-write
    float* tb = (float*)smc;     // [128][132]
#pragma unroll
    for (int mt = 0; mt < 4; mt++) {
        int ml = wm * 64 + mt * 16 + gID;
#pragma unroll
        for (int nt = 0; nt < 4; nt++) {
            int nl = wn * 32 + nt * 8 + tg * 2;
            float b0v = bias[n0 + nl], b1v = bias[n0 + nl + 1];
            tb[ml * 132 + nl]           = acc[mt][nt][0] + b0v;
            tb[ml * 132 + nl + 1]       = acc[mt][nt][1] + b1v;
            tb[(ml + 8) * 132 + nl]     = acc[mt][nt][2] + b0v;
            tb[(ml + 8) * 132 + nl + 1] = acc[mt][nt][3] + b1v;
        }
    }
    __syncthreads();

    {
        int ml = tid >> 1, h2 = tid & 1;
        const float* row = &tb[ml * 132 + h2 * 64];
        float ss = 0.f;
#pragma unroll
        for (int j4 = 0; j4 < 16; j4++) {
            float4 v = *(const float4*)&row[j4 * 4];
            ss += v.x * v.x + v.y * v.y + v.z * v.z + v.w * v.w;
        }
        float inv = 1.f / (sqrtf(ss * (1.f / 64.f)) + 1e-6f);
        int m = m0 + ml;
        int bb = m >> 10, t = m & 1023;
        int h = (n0 >> 6) + h2;
        __nv_bfloat16* oh = kh + (((size_t)(bb * H_ + h)) * T_ + t) * DH_;
        __nv_bfloat16* ol = kl + (((size_t)(bb * H_ + h)) * T_ + t) * DH_;
#pragma unroll
        for (int j4 = 0; j4 < 16; j4++) {
            float4 v = *(const float4*)&row[j4 * 4];
            ushort4 Hv, Lv;
            bf16split(v.x * inv, Hv.x, Lv.x);
            bf16split(v.y * inv, Hv.y, Lv.y);
            bf16split(v.z * inv, Hv.z, Lv.z);
            bf16split(v.w * inv, Hv.w, Lv.w);
            *(ushort4*)&oh[j4 * 4] = Hv;
            *(ushort4*)&ol[j4 * 4] = Lv;
        }
    }
}

// ---------------- V GEMM fused with transpose + bf16 split ----------------
__global__ __launch_bounds__(256) void gemm_v(
    const __nv_bfloat16* __restrict__ Ahi, const __nv_bfloat16* __restrict__ Alo,
    const __nv_bfloat16* __restrict__ Bhi, const __nv_bfloat16* __restrict__ Blo,
    const float* __restrict__ bias,
    __nv_bfloat16* __restrict__ vth, __nv_bfloat16* __restrict__ vtl)
{
    extern __shared__ char smc[];
    const int tid = threadIdx.x;
    const int lane = tid & 31, wid = tid >> 5;
    const int wm = wid >> 2, wn = wid & 3;
    const int gID = lane >> 2, tg = lane & 3;
    const int m0 = blockIdx.y * 128, n0 = blockIdx.x * 128;
    uint32_t sbase = (uint32_t)__cvta_generic_to_shared(smc);

    float acc[4][4][4];
#pragma unroll
    for (int mt = 0; mt < 4; mt++)
#pragma unroll
        for (int nt = 0; nt < 4; nt++)
#pragma unroll
            for (int r = 0; r < 4; r++) acc[mt][nt][r] = 0.f;

    GEMM_MAINLOOP(ACT_ID, NCHUNK)

    // epilogue: store TRANSPOSED tile tb[n][m], then split-write (bh,d,t)
    float* tb = (float*)smc;     // [128][132]
#pragma unroll
    for (int mt = 0; mt < 4; mt++) {
        int ml = wm * 64 + mt * 16 + gID;
#pragma unroll
        for (int nt = 0; nt < 4; nt++) {
            int nl = wn * 32 + nt * 8 + tg * 2;
            float b0v = bias[n0 + nl], b1v = bias[n0 + nl + 1];
            tb[nl * 132 + ml]           = acc[mt][nt][0] + b0v;
            tb[(nl + 1) * 132 + ml]     = acc[mt][nt][1] + b1v;
            tb[nl * 132 + ml + 8]       = acc[mt][nt][2] + b0v;
            tb[(nl + 1) * 132 + ml + 8] = acc[mt][nt][3] + b1v;
        }
    }
    __syncthreads();

    {
        int nl = tid >> 1, mhalf = (tid & 1) * 64;
        const float* row = &tb[nl * 132 + mhalf];
        int h = (n0 >> 6) + (nl >> 6);
        int d = nl & 63;
        int bb = m0 >> 10;
        int t0 = (m0 & 1023) + mhalf;
        __nv_bfloat16* oh = vth + (((size_t)(bb * H_ + h)) * DH_ + d) * T_ + t0;
        __nv_bfloat16* ol = vtl + (((size_t)(bb * H_ + h)) * DH_ + d) * T_ + t0;
#pragma unroll
        for (int j4 = 0; j4 < 16; j4++) {
            float4 v = *(const float4*)&row[j4 * 4];
            ushort4 Hv, Lv;
            bf16split(v.x, Hv.x, Lv.x);
            bf16split(v.y, Hv.y, Lv.y);
            bf16split(v.z, Hv.z, Lv.z);
            bf16split(v.w, Hv.w, Lv.w);
            *(ushort4*)&oh[j4 * 4] = Hv;
            *(ushort4*)&ol[j4 * 4] = Lv;
        }
    }
}

// ---------------- O GEMM with head-mask chunk skip ----------------
__global__ __launch_bounds__(256) void gemm_o(
    const __nv_bfloat16* __restrict__ Ahi, const __nv_bfloat16* __restrict__ Alo,
    const __nv_bfloat16* __restrict__ Bhi, const __nv_bfloat16* __restrict__ Blo,
    const float* __restrict__ bias, float* __restrict__ Cout,
    const float* __restrict__ maskp)
{
    extern __shared__ char smc[];
    const int tid = threadIdx.x;
    const int lane = tid & 31, wid = tid >> 5;
    const int wm = wid >> 2, wn = wid & 3;
    const int gID = lane >> 2, tg = lane & 3;
    const int m0 = blockIdx.y * 128, n0 = blockIdx.x * 128;
    uint32_t sbase = (uint32_t)__cvta_generic_to_shared(smc);

    __shared__ int act[NCHUNK];
    __shared__ int s_na;
    if (tid == 0) {
        int n = 0;
        int b16 = (m0 >> 10) << 4;
        for (int ch = 0; ch < NCHUNK; ch++)
            if (maskp[b16 + (ch >> 1)] != 0.f) act[n++] = ch;
        s_na = n;
    }
    __syncthreads();
    const int na = s_na;

    float acc[4][4][4];
#pragma unroll
    for (int mt = 0; mt < 4; mt++)
#pragma unroll
        for (int nt = 0; nt < 4; nt++)
#pragma unroll
            for (int r = 0; r < 4; r++) acc[mt][nt][r] = 0.f;

    GEMM_MAINLOOP(ACT_LUT, na)

#pragma unroll
    for (int mt = 0; mt < 4; mt++) {
        int m1 = m0 + wm * 64 + mt * 16 + gID;
#pragma unroll
        for (int nt = 0; nt < 4; nt++) {
            int n = n0 + wn * 32 + nt * 8 + tg * 2;
            float b0v = bias[n], b1v = bias[n + 1];
            float* a = acc[mt][nt];
            *(float2*)&Cout[(size_t)m1 * C_ + n] = make_float2(a[0] + b0v, a[1] + b1v);
            *(float2*)&Cout[(size_t)(m1 + 8) * C_ + n] = make_float2(a[2] + b0v, a[3] + b1v);
        }
    }
}

// ---------------- q GEMM (exact 3-term split + chunked TwoSum): 64x128 ----------------
#define QTILE_B  5120
#define QSTAGE_B 25600
#define QNCH     32

__device__ __forceinline__ void qload_chunk_async(
    uint32_t sbase,
    const __nv_bfloat16* __restrict__ X1, const __nv_bfloat16* __restrict__ X2,
    const __nv_bfloat16* __restrict__ X3, const __nv_bfloat16* __restrict__ Ws,
    int m0, int n0, int k0, int tid)
{
#pragma unroll
    for (int i = 0; i < 5; i++) {
        int u = tid + i * 256;
        const __nv_bfloat16* g;
        uint32_t dst;
        if (u < 768) {
            int term = u >> 8;
            int idx = u & 255;
            int row = idx >> 2, jj = idx & 3;
            const __nv_bfloat16* base = (term == 0) ? X1 : (term == 1) ? X2 : X3;
            g = base + (size_t)(m0 + row) * C_ + k0 + jj * 8;
            dst = sbase + term * QTILE_B + row * 80 + jj * 16;
        } else {
            int v = u - 768;
            int row = v >> 2, jj = v & 3;
            g = Ws + (size_t)(n0 + row) * C_ + k0 + jj * 8;
            dst = sbase + 3 * QTILE_B + row * 80 + jj * 16;
        }
        asm volatile("cp.async.cg.shared.global [%0], [%1], 16;" :: "r"(dst), "l"(g));
    }
}

__global__ __launch_bounds__(256) void qgemm_mma(
    const __nv_bfloat16* __restrict__ X1, const __nv_bfloat16* __restrict__ X2,
    const __nv_bfloat16* __restrict__ X3, const __nv_bfloat16* __restrict__ Ws,
    const float* __restrict__ bias, float* __restrict__ Q)
{
    extern __shared__ char smc[];
    const int tid = threadIdx.x;
    const int lane = tid & 31, wid = tid >> 5;
    const int wm = wid >> 2, wn = wid & 3;
    const int gID = lane >> 2, tg = lane & 3;
    const int m0 = blockIdx.y * 64, n0 = blockIdx.x * 128;
    uint32_t sbase = (uint32_t)__cvta_generic_to_shared(smc);

    const uint32_t aQBase = (uint32_t)((wm * 32 + (lane & 7) + ((lane >> 3) & 1) * 8) * 80
                                       + ((lane >> 4) & 1) * 16);
    const uint32_t bQBase = (uint32_t)((wn * 32 + (lane & 7) + ((lane >> 4) & 1) * 8) * 80
                                       + ((lane >> 3) & 1) * 16);

    float s_[2][4][4], c_[2][4][4];
#pragma unroll
    for (int mt = 0; mt < 2; mt++)
#pragma unroll
        for (int nt = 0; nt < 4; nt++)
#pragma unroll
            for (int r = 0; r < 4; r++) { s_[mt][nt][r] = 0.f; c_[mt][nt][r] = 0.f; }

    qload_chunk_async(sbase, X1, X2, X3, Ws, m0, n0, 0, tid);
    asm volatile("cp.async.commit_group;" ::: "memory");
    asm volatile("cp.async.wait_group 0;" ::: "memory");
    __syncthreads();

    for (int c = 0; c < QNCH; c++) {
        if (c + 1 < QNCH) {
            qload_chunk_async(sbase + ((c + 1) & 1) * QSTAGE_B,
                              X1, X2, X3, Ws, m0, n0, (c + 1) * 32, tid);
            asm volatile("cp.async.commit_group;" ::: "memory");
        }
        const uint32_t stq = sbase + (c & 1) * QSTAGE_B;

        float tacc[2][4][4];
#pragma unroll
        for (int mt = 0; mt < 2; mt++)
#pragma unroll
            for (int nt = 0; nt < 4; nt++)
#pragma unroll
                for (int r = 0; r < 4; r++) tacc[mt][nt][r] = 0.f;

#pragma unroll
        for (int ks = 0; ks < 2; ks++) {
            const uint32_t kb = ks * 32;
            uint32_t bw[4][2];
            ldsm4(stq + 3 * QTILE_B + bQBase + kb,
                  bw[0][0], bw[0][1], bw[1][0], bw[1][1]);
            ldsm4(stq + 3 * QTILE_B + 1280 + bQBase + kb,
                  bw[2][0], bw[2][1], bw[3][0], bw[3][1]);
#pragma unroll
            for (int term = 0; term < 3; term++) {
                uint32_t ah[2][4];
#pragma unroll
                for (int mt = 0; mt < 2; mt++)
                    ldsm4(stq + term * QTILE_B + aQBase + mt * 1280 + kb,
                          ah[mt][0], ah[mt][1], ah[mt][2], ah[mt][3]);
#pragma unroll
                for (int mt = 0; mt < 2; mt++)
#pragma unroll
                    for (int nt = 0; nt < 4; nt++)
                        mma16816(tacc[mt][nt], ah[mt][0], ah[mt][1], ah[mt][2], ah[mt][3],
                                 bw[nt][0], bw[nt][1]);
            }
        }
#pragma unroll
        for (int mt = 0; mt < 2; mt++)
#pragma unroll
            for (int nt = 0; nt < 4; nt++)
#pragma unroll
                for (int r = 0; r < 4; r++)
                    twosum(s_[mt][nt][r], c_[mt][nt][r], tacc[mt][nt][r]);

        if (c + 1 < QNCH)
            asm volatile("cp.async.wait_group 0;" ::: "memory");
        __syncthreads();
    }

#pragma unroll
    for (int mt = 0; mt < 2; mt++) {
        int m1 = m0 + wm * 32 + mt * 16 + gID;
#pragma unroll
        for (int nt = 0; nt < 4; nt++) {
            int n = n0 + wn * 32 + nt * 8 + tg * 2;
            int h = n >> 6, d = n & 63;
            float b0v = bias[n], b1v = bias[n + 1];
            float v0 = __fadd_rn(__fadd_rn(s_[mt][nt][0], c_[mt][nt][0]), b0v);
            float v1 = __fadd_rn(__fadd_rn(s_[mt][nt][1], c_[mt][nt][1]), b1v);
            float v2 = __fadd_rn(__fadd_rn(s_[mt][nt][2], c_[mt][nt][2]), b0v);
            float v3 = __fadd_rn(__fadd_rn(s_[mt][nt][3], c_[mt][nt][3]), b1v);
            int bb = m1 >> 10, t = m1 & 1023;
            *(float2*)&Q[(((size_t)(bb * H_ + h)) * T_ + t) * DH_ + d] = make_float2(v0, v1);
            int m2 = m1 + 8;
            int bb2 = m2 >> 10, t2 = m2 & 1023;
            *(float2*)&Q[(((size_t)(bb2 * H_ + h)) * T_ + t2) * DH_ + d] = make_float2(v2, v3);
        }
    }
}

// -------------- q post: RMS norm + exact top-k, emits bf16 split --------------
__global__ __launch_bounds__(256) void qpost(
    const float* __restrict__ q,
    __nv_bfloat16* __restrict__ qh, __nv_bfloat16* __restrict__ ql)
{
    int grp = threadIdx.x >> 6;
    int lane = threadIdx.x & 63;
    int row = blockIdx.x * 4 + grp;
    float v = q[(size_t)row * 64 + lane];
    float ss = v * v;
#pragma unroll
    for (int o = 16; o > 0; o >>= 1) ss += __shfl_xor_sync(0xffffffffu, ss, o);
    __shared__ float ws[8];
    if ((threadIdx.x & 31) == 0) ws[threadIdx.x >> 5] = ss;
    __syncthreads();
    float rms = sqrtf((ws[grp * 2] + ws[grp * 2 + 1]) * (1.f / 64.f)) + 1e-6f;
    float vn = v / rms;
    float a = fabsf(vn);
    __shared__ __align__(16) float sa[4][64];
    sa[grp][lane] = a;
    __syncthreads();
    int g = 0;
    const float4* sv = (const float4*)sa[grp];
#pragma unroll
    for (int j = 0; j < 16; j++) {
        float4 t = sv[j];
        g += (t.x > a) + (t.y > a) + (t.z > a) + (t.w > a);
    }
    int h = (row >> 10) & 15;
    int kc = KEEPC[h];
    float cand = (g <= kc - 1) ? a : INFINITY;
#pragma unroll
    for (int o = 16; o > 0; o >>= 1)
        cand = fminf(cand, __shfl_xor_sync(0xffffffffu, cand, o));
    __shared__ float wm_[8];
    if ((threadIdx.x & 31) == 0) wm_[threadIdx.x >> 5] = cand;
    __syncthreads();
    float th = fminf(wm_[grp * 2], wm_[grp * 2 + 1]);
    float vnm = (a >= th) ? vn : 0.f;
    __nv_bfloat16 hh = __float2bfloat16(vnm);
    qh[(size_t)row * 64 + lane] = hh;
    ql[(size_t)row * 64 + lane] = __float2bfloat16(vnm - __bfloat162float(hh));
}

// -------------- MMA flash attention --------------
#define APAD_B 144
#define ATS 9216
#define ATT_SMEM (2 * ATS + 2 * 4 * ATS)   // 92160

__device__ __forceinline__ void att_kvload(
    uint32_t sb, int s, int kt, size_t hoff, int tid,
    const __nv_bfloat16* __restrict__ kh_g, const __nv_bfloat16* __restrict__ kl_g,
    const __nv_bfloat16* __restrict__ vth_g, const __nv_bfloat16* __restrict__ vtl_g)
{
    uint32_t st = sb + 2 * ATS + s * 4 * ATS;
#pragma unroll
    for (int i = 0; i < 16; i++) {
        int u = tid + i * 128;
        int t = u >> 9, row = (u >> 3) & 63, c = u & 7;
        const __nv_bfloat16* src;
        if (t == 0)      src = kh_g + hoff + (size_t)(kt * 64 + row) * 64 + c * 8;
        else if (t == 1) src = kl_g + hoff + (size_t)(kt * 64 + row) * 64 + c * 8;
        else if (t == 2) src = vth_g + hoff + (size_t)row * T_ + kt * 64 + c * 8;
        else             src = vtl_g + hoff + (size_t)row * T_ + kt * 64 + c * 8;
        uint32_t dst = st + t * ATS + row * APAD_B + c * 16;
        asm volatile("cp.async.cg.shared.global [%0], [%1], 16;" :: "r"(dst), "l"(src));
    }
}

__global__ __launch_bounds__(128) void attn_mma(
    const __nv_bfloat16* __restrict__ qh_g, const __nv_bfloat16* __restrict__ ql_g,
    const __nv_bfloat16* __restrict__ kh_g, const __nv_bfloat16* __restrict__ kl_g,
    const __nv_bfloat16* __restrict__ vth_g, const __nv_bfloat16* __restrict__ vtl_g,
    __nv_bfloat16* __restrict__ aoh, __nv_bfloat16* __restrict__ aol,
    float* __restrict__ gepart)
{
    extern __shared__ char smr[];
    __shared__ float red[128];
    const int qt = (int)(gridDim.x - 1) - (int)blockIdx.x;   // heavy tiles first
    const int bh = blockIdx.y, q0 = qt * 64;
    const int tid = threadIdx.x, lane = tid & 31, w = tid >> 5;
    const int gID = lane >> 2, tg = lane & 3;
    uint32_t sb = (uint32_t)__cvta_generic_to_shared(smr);
    const size_t hoff = (size_t)bh * (T_ * 64);

#pragma unroll
    for (int i = 0; i < 8; i++) {
        int u = tid + i * 128;
        int t = u >> 9, row = (u >> 3) & 63, c = u & 7;
        const __nv_bfloat16* src = (t ? ql_g : qh_g) + hoff + (size_t)(q0 + row) * 64 + c * 8;
        uint32_t dst = sb + t * ATS + row * APAD_B + c * 16;
        asm volatile("cp.async.cg.shared.global [%0], [%1], 16;" :: "r"(dst), "l"(src));
    }
    att_kvload(sb, 0, 0, hoff, tid, kh_g, kl_g, vth_g, vtl_g);
    asm volatile("cp.async.commit_group;" ::: "memory");
    asm volatile("cp.async.wait_group 0;" ::: "memory");
    __syncthreads();

    float oacc[8][4];
#pragma unroll
    for (int nt = 0; nt < 8; nt++)
#pragma unroll
        for (int r = 0; r < 4; r++) oacc[nt][r] = 0.f;
    float mrow[2] = {-1e30f, -1e30f}, lrow[2] = {0.f, 0.f}, erow[2] = {0.f, 0.f};

    for (int kt = 0; kt <= qt; kt++) {
        if (kt < qt) {
            att_kvload(sb, (kt + 1) & 1, kt + 1, hoff, tid, kh_g, kl_g, vth_g, vtl_g);
            asm volatile("cp.async.commit_group;" ::: "memory");
        }
        uint32_t st = sb + 2 * ATS + (kt & 1) * 4 * ATS;

        float sacc[8][4];
#pragma unroll
        for (int nt = 0; nt < 8; nt++)
#pragma unroll
            for (int r = 0; r < 4; r++) sacc[nt][r] = 0.f;

#pragma unroll
        for (int ks = 0; ks < 4; ks++) {
            uint32_t aoff = sb + (w * 16 + gID) * APAD_B + (ks * 16 + tg * 2) * 2;
            uint32_t qh0 = *(const uint32_t*)(smr + (aoff - sb));
            uint32_t qh2 = *(const uint32_t*)(smr + (aoff - sb) + 16);
            uint32_t qh1 = *(const uint32_t*)(smr + (aoff - sb) + 8 * APAD_B);
            uint32_t qh3 = *(const uint32_t*)(smr + (aoff - sb) + 8 * APAD_B + 16);
            uint32_t ql0 = *(const uint32_t*)(smr + (aoff - sb) + ATS);
            uint32_t ql2 = *(const uint32_t*)(smr + (aoff - sb) + ATS + 16);
            uint32_t ql1 = *(const uint32_t*)(smr + (aoff - sb) + ATS + 8 * APAD_B);
            uint32_t ql3 = *(const uint32_t*)(smr + (aoff - sb) + ATS + 8 * APAD_B + 16);
#pragma unroll
            for (int nt = 0; nt < 8; nt++) {
                uint32_t bo = (st - sb) + (nt * 8 + gID) * APAD_B + (ks * 16 + tg * 2) * 2;
                uint32_t kb0 = *(const uint32_t*)(smr + bo);
                uint32_t kb1 = *(const uint32_t*)(smr + bo + 16);
                uint32_t kl0 = *(const uint32_t*)(smr + bo + ATS);
                uint32_t kl1 = *(const uint32_t*)(smr + bo + ATS + 16);
                mma16816(sacc[nt], qh0, qh1, qh2, qh3, kb0, kb1);
                mma16816(sacc[nt], ql0, ql1, ql2, ql3, kb0, kb1);
                mma16816(sacc[nt], qh0, qh1, qh2, qh3, kl0, kl1);
            }
        }

        if (kt == qt) {
            int r0 = w * 16 + gID, r1 = r0 + 8;
#pragma unroll
            for (int nt = 0; nt < 8; nt++) {
                int c0 = nt * 8 + tg * 2, c1 = c0 + 1;
                if (c0 > r0) sacc[nt][0] = -1e30f;
                if (c1 > r0) sacc[nt][1] = -1e30f;
                if (c0 > r1) sacc[nt][2] = -1e30f;
                if (c1 > r1) sacc[nt][3] = -1e30f;
            }
        }

#pragma unroll
        for (int r = 0; r < 2; r++) {
            float tm = -1e30f;
#pragma unroll
            for (int nt = 0; nt < 8; nt++)
                tm = fmaxf(tm, fmaxf(sacc[nt][2 * r], sacc[nt][2 * r + 1]));
            tm = fmaxf(tm, __shfl_xor_sync(0xffffffffu, tm, 1));
            tm = fmaxf(tm, __shfl_xor_sync(0xffffffffu, tm, 2));
            float mn = fmaxf(mrow[r], tm);
            float sc = fast_exp(mrow[r] - mn);
            mrow[r] = mn;
            float se = 0.f, s2 = 0.f;
#pragma unroll
            for (int nt = 0; nt < 8; nt++) {
                float p0 = fast_exp(sacc[nt][2 * r] - mn);
                float p1 = fast_exp(sacc[nt][2 * r + 1] - mn);
                sacc[nt][2 * r] = p0; sacc[nt][2 * r + 1] = p1;
                se += p0 + p1;
                s2 += p0 * p0 + p1 * p1;
            }
            se += __shfl_xor_sync(0xffffffffu, se, 1);
            se += __shfl_xor_sync(0xffffffffu, se, 2);
            s2 += __shfl_xor_sync(0xffffffffu, s2, 1);
            s2 += __shfl_xor_sync(0xffffffffu, s2, 2);
            lrow[r] = lrow[r] * sc + se;
            erow[r] = erow[r] * sc * sc + s2;
#pragma unroll
            for (int nt = 0; nt < 8; nt++) {
                oacc[nt][2 * r] *= sc;
                oacc[nt][2 * r + 1] *= sc;
            }
        }

        // PV
#pragma unroll
        for (int ks = 0; ks < 4; ks++) {
            float* pa = sacc[2 * ks];
            float* pb = sacc[2 * ks + 1];
            uint32_t ph[4], pl[4];
            float hx, hy;
            ph[0] = pack_bf16x2(pa[0], pa[1]);
            hx = __bfloat162float(__float2bfloat16(pa[0]));
            hy = __bfloat162float(__float2bfloat16(pa[1]));
            pl[0] = pack_bf16x2(pa[0] - hx, pa[1] - hy);
            ph[1] = pack_bf16x2(pa[2], pa[3]);
            hx = __bfloat162float(__float2bfloat16(pa[2]));
            hy = __bfloat162float(__float2bfloat16(pa[3]));
            pl[1] = pack_bf16x2(pa[2] - hx, pa[3] - hy);
            ph[2] = pack_bf16x2(pb[0], pb[1]);
            hx = __bfloat162float(__float2bfloat16(pb[0]));
            hy = __bfloat162float(__float2bfloat16(pb[1]));
            pl[2] = pack_bf16x2(pb[0] - hx, pb[1] - hy);
            ph[3] = pack_bf16x2(pb[2], pb[3]);
            hx = __bfloat162float(__float2bfloat16(pb[2]));
            hy = __bfloat162float(__float2bfloat16(pb[3]));
            pl[3] = pack_bf16x2(pb[2] - hx, pb[3] - hy);
#pragma unroll
            for (int nt = 0; nt < 8; nt++) {
                uint32_t bo = (st - sb) + 2 * ATS + (nt * 8 + gID) * APAD_B + (ks * 16 + tg * 2) * 2;
                uint32_t vh0 = *(const uint32_t*)(smr + bo);
                uint32_t vh1 = *(const uint32_t*)(smr + bo + 16);
                uint32_t vl0 = *(const uint32_t*)(smr + bo + ATS);
                uint32_t vl1 = *(const uint32_t*)(smr + bo + ATS + 16);
                mma16816(oacc[nt], ph[0], ph[1], ph[2], ph[3], vh0, vh1);
                mma16816(oacc[nt], pl[0], pl[1], pl[2], pl[3], vh0, vh1);
                mma16816(oacc[nt], ph[0], ph[1], ph[2], ph[3], vl0, vl1);
            }
        }

        asm volatile("cp.async.wait_group 0;" ::: "memory");
        __syncthreads();
    }

    // epilogue: write bf16 hi/lo of out (unmasked; mask handled by O-GEMM chunk skip)
    float linv0 = 1.f / lrow[0], linv1 = 1.f / lrow[1];
    int r0 = w * 16 + gID, r1 = r0 + 8;
    int b = bh >> 4, h = bh & 15;
    size_t base0 = (size_t)(b * T_ + q0 + r0) * C_ + h * DH_;
    size_t base1 = (size_t)(b * T_ + q0 + r1) * C_ + h * DH_;
#pragma unroll
    for (int nt = 0; nt < 8; nt++) {
        int col = nt * 8 + tg * 2;
        float v0 = oacc[nt][0] * linv0, v1 = oacc[nt][1] * linv0;
        float v2 = oacc[nt][2] * linv1, v3 = oacc[nt][3] * linv1;
        ushort2 H0, L0, H1, L1;
        bf16split(v0, H0.x, L0.x); bf16split(v1, H0.y, L0.y);
        bf16split(v2, H1.x, L1.x); bf16split(v3, H1.y, L1.y);
        *(ushort2*)&aoh[base0 + col] = H0;
        *(ushort2*)&aol[base0 + col] = L0;
        *(ushort2*)&aoh[base1 + col] = H1;
        *(ushort2*)&aol[base1 + col] = L1;
    }

    red[tid] = (tg == 0) ? (erow[0] * linv0 * linv0 + erow[1] * linv1 * linv1) : 0.f;
    __syncthreads();
    for (int o = 64; o > 0; o >>= 1) {
        if (tid < o) red[tid] += red[tid + o];
        __syncthreads();
    }
    if (tid == 0) gepart[bh * 16 + qt] = red[0];
}

// -------------- head energy -> entropy -> adaptive head mask --------------
__global__ void headmask(const float* __restrict__ epart, float* __restrict__ maskout)
{
    __shared__ double e[64];
    __shared__ double cand[64];
    int t = threadIdx.x;
    double s = 0.0;
    for (int i = 0; i < 16; i++) s += (double)epart[t * 16 + i];
    e[t] = s / 1048576.0;
    __syncthreads();
    int b = t >> 4;
    double m = -1e300;
    for (int j = 0; j < 16; j++) m = fmax(m, e[b * 16 + j]);
    double Z = 0.0;
    for (int j = 0; j < 16; j++) Z += exp(e[b * 16 + j] - m);
    double ent = 0.0;
    for (int j = 0; j < 16; j++) {
        double p = exp(e[b * 16 + j] - m) / Z;
        ent -= p * log(p + 1e-9);
    }
    double entn = fmin(fmax(ent / log(16.0), 0.0), 1.0);
    int keep = (int)rint(2.0 + entn * 4.0);
    double eh = e[t];
    int g = 0;
    for (int j = 0; j < 16; j++) g += (e[b * 16 + j] > eh);
    cand[t] = (g <= keep - 1) ? eh : 1e300;
    __syncthreads();
    double th = 1e300;
    for (int j = 0; j < 16; j++) th = fmin(th, cand[b * 16 + j]);
    maskout[t] = (eh >= th) ? 1.f : 0.f;
}

// ---------------- launch ----------------
extern "C" void kernel_launch(void* const* d_in, const int* in_sizes, int n_in,
                              void* d_out, int out_size)
{
    const float* x  = (const float*)d_in[0];
    const float* qw = (const float*)d_in[1];
    const float* qb = (const float*)d_in[2];
    const float* kw = (const float*)d_in[3];
    const float* kb = (const float*)d_in[4];
    const float* vw = (const float*)d_in[5];
    const float* vb = (const float*)d_in[6];
    const float* ow = (const float*)d_in[7];
    const float* ob = (const float*)d_in[8];
    float* out = (float*)d_out;

    float *gq, *gep, *gm;
    cudaGetSymbolAddress((void**)&gq, g_q);
    cudaGetSymbolAddress((void**)&gep, g_epart);
    cudaGetSymbolAddress((void**)&gm, g_mask);

    __nv_bfloat16 *xh, *xl, *x3, *qws, *kwh, *kwl, *vwh, *vwl, *owh, *owl, *aoh, *aol;
    __nv_bfloat16 *qsh, *qsl, *ksh, *ksl, *vth, *vtl;
    cudaGetSymbolAddress((void**)&xh, g_xh);   cudaGetSymbolAddress((void**)&xl, g_xl);
    cudaGetSymbolAddress((void**)&x3, g_x3);   cudaGetSymbolAddress((void**)&qws, g_qws);
    cudaGetSymbolAddress((void**)&kwh, g_kwh); cudaGetSymbolAddress((void**)&kwl, g_kwl);
    cudaGetSymbolAddress((void**)&vwh, g_vwh); cudaGetSymbolAddress((void**)&vwl, g_vwl);
    cudaGetSymbolAddress((void**)&owh, g_owh); cudaGetSymbolAddress((void**)&owl, g_owl);
    cudaGetSymbolAddress((void**)&aoh, g_aoh); cudaGetSymbolAddress((void**)&aol, g_aol);
    cudaGetSymbolAddress((void**)&qsh, g_qsh); cudaGetSymbolAddress((void**)&qsl, g_qsl);
    cudaGetSymbolAddress((void**)&ksh, g_ksh); cudaGetSymbolAddress((void**)&ksl, g_ksl);
    cudaGetSymbolAddress((void**)&vth, g_vth); cudaGetSymbolAddress((void**)&vtl, g_vtl);

    cudaFuncSetAttribute((const void*)gemm_k,
                         cudaFuncAttributeMaxDynamicSharedMemorySize, 2 * STAGE_B);
    cudaFuncSetAttribute((const void*)gemm_v,
                         cudaFuncAttributeMaxDynamicSharedMemorySize, 2 * STAGE_B);
    cudaFuncSetAttribute((const void*)gemm_o,
                         cudaFuncAttributeMaxDynamicSharedMemorySize, 2 * STAGE_B);
    cudaFuncSetAttribute((const void*)qgemm_mma,
                         cudaFuncAttributeMaxDynamicSharedMemorySize, 2 * QSTAGE_B);
    cudaFuncSetAttribute((const void*)attn_mma,
                         cudaFuncAttributeMaxDynamicSharedMemorySize, ATT_SMEM);

    // splits
    split3x<<<M_ * C_ / 1024, 256>>>((const float4*)x, (ushort4*)xh, (ushort4*)xl, (ushort4*)x3);
    wsplit4<<<dim3(C_ * C_ / 1024, 4), 256>>>(
        (const float4*)kw, (const float4*)vw, (const float4*)ow, (const float4*)qw,
        (ushort4*)kwh, (ushort4*)kwl, (ushort4*)vwh, (ushort4*)vwl,
        (ushort4*)owh, (ushort4*)owl, (ushort4*)qws);

    // projections (K and V fuse norm/split/transpose epilogues)
    qgemm_mma<<<dim3(C_ / 128, M_ / 64), 256, 2 * QSTAGE_B>>>(xh, xl, x3, qws, qb, gq);
    dim3 tGrid(C_ / 128, M_ / 128);
    gemm_k<<<tGrid, 256, 2 * STAGE_B>>>(xh, xl, kwh, kwl, kb, ksh, ksl);
    gemm_v<<<tGrid, 256, 2 * STAGE_B>>>(xh, xl, vwh, vwl, vb, vth, vtl);

    qpost<<<BH_ * T_ / 4, 256>>>(gq, qsh, qsl);

    attn_mma<<<dim3(16, BH_), 128, ATT_SMEM>>>(qsh, qsl, ksh, ksl, vth, vtl, aoh, aol, gep);
    headmask<<<1, 64>>>(gep, gm);

    // O projection: reads attn's bf16 splits directly, skips masked-head chunks
    gemm_o<<<tGrid, 256, 2 * STAGE_B>>>(aoh, aol, owh, owl, ob, out, gm);
}